// round 1
// baseline (speedup 1.0000x reference)
#include <cuda_runtime.h>
#include <math.h>

#define BB 8
#define CC 128
#define HH 96
#define WW 96
#define HW 9216            // 96*96
#define WC 144             // k*k*DIM/SP
#define PTOT (BB*HW)       // 73728

// ---------------- scratch (device globals; no allocation allowed) ----------------
__device__ float g_k   [BB*CC*HW];   // key_embed output (relu'd)
__device__ float g_v   [BB*CC*HW];   // value 1x1 conv
__device__ float g_wpre[BB*WC*HW];   // embed output pre-GN
__device__ float g_ypre[BB*CC*HW];   // local-conv output pre-BN
__device__ float g_y   [BB*CC*HW];   // post BN+swish
__device__ float g_w1T [256*64];     // e_w1 transposed (K-major)
__device__ float g_c1T [128*128];    // c1_w transposed
__device__ float g_w2T [64*144];     // e_w2 transposed
__device__ float g_gn  [128*2];      // per (b,group) mean, rstd
__device__ float g_bnS [128*768];    // BN partial sums  (per channel, per (b,row))
__device__ float g_bnQ [128*768];    // BN partial sumsq
__device__ float g_bn  [128*2];      // per channel mean, rstd
__device__ float g_gap [BB*CC];
__device__ float g_a   [BB*CC*2];    // radix-softmax weights

// ---------------- K0: transpose small weight matrices for coalesced GEMM A-loads ----------------
__global__ void k0_prep(const float* __restrict__ e_w1, const float* __restrict__ c1_w,
                        const float* __restrict__ e_w2) {
    int idx = blockIdx.x * 256 + threadIdx.x;   // 0..16383
    if (idx < 64*256)  { int m = idx / 256, k = idx % 256; g_w1T[k*64  + m] = e_w1[idx]; }
    if (idx < 128*128) { int m = idx / 128, k = idx % 128; g_c1T[k*128 + m] = c1_w[idx]; }
    if (idx < 144*64)  { int m = idx / 64,  k = idx % 64;  g_w2T[k*144 + m] = e_w2[idx]; }
}

// ---------------- K1: grouped 3x3 conv (groups=4) + ReLU -> g_k ----------------
// block = (row h, group g, batch b); 256 threads; smem holds 32 in-ch x 3 rows x 98 cols
__global__ void __launch_bounds__(256) k1_key(const float* __restrict__ x,
                                              const float* __restrict__ kw) {
    __shared__ float xs[32 * 294];  // [ci][r(3)][col(98)]
    int h = blockIdx.x, g = blockIdx.y, b = blockIdx.z;
    int tid = threadIdx.x;
    for (int idx = tid; idx < 32 * 294; idx += 256) {
        int ci = idx / 294, rem = idx % 294, r = rem / 98, col = rem % 98;
        int hh = h + r - 1, wc = col - 1;
        float v = 0.f;
        if ((unsigned)hh < 96u && (unsigned)wc < 96u)
            v = x[(b*128 + g*32 + ci) * HW + hh*96 + wc];
        xs[idx] = v;
    }
    __syncthreads();
    int co = tid >> 3, pg = tid & 7, w0 = pg * 12;
    float acc[12];
#pragma unroll
    for (int j = 0; j < 12; j++) acc[j] = 0.f;
    const float* wb = kw + (g*32 + co) * 32 * 9;
    for (int ci = 0; ci < 32; ci++) {
        float wv[9];
#pragma unroll
        for (int t = 0; t < 9; t++) wv[t] = __ldg(wb + ci*9 + t);
        const float* xr = xs + ci * 294;
#pragma unroll
        for (int r = 0; r < 3; r++)
#pragma unroll
            for (int c = 0; c < 3; c++) {
                float wgt = wv[r*3 + c];
#pragma unroll
                for (int j = 0; j < 12; j++)
                    acc[j] += wgt * xr[r*98 + w0 + j + c];
            }
    }
    float* ob = g_k + (b*128 + g*32 + co) * HW + h*96 + w0;
#pragma unroll
    for (int j = 0; j < 12; j++) ob[j] = fmaxf(acc[j], 0.f);
}

// ---------------- K2: fused embed GEMMs: hidden = relu(W1 @ [x;k]); wpre = W2 @ hidden + b2 ----------------
// block: 128-pixel tile; 256 threads as 16x16; stage1 4x8 reg tile, stage2 9x8 reg tile
__global__ void __launch_bounds__(256, 2) k2_embed(const float* __restrict__ x,
                                                   const float* __restrict__ e_b2) {
    __shared__ float hid[64 * 128];   // 32KB
    __shared__ float tile[3072];      // 12KB: stage1 As(1024)+Bs(2048); stage2 W2s(2304)
    float* As = tile;
    float* Bs = tile + 1024;
    int tid = threadIdx.x, tx = tid & 15, ty = tid >> 4;
    int pb = blockIdx.x * 128, b = pb / HW, hw0 = pb % HW;
    const float* xb = x   + (size_t)b*128*HW + hw0;
    const float* kb = g_k + (size_t)b*128*HW + hw0;

    float a1[4][8];
#pragma unroll
    for (int i = 0; i < 4; i++)
#pragma unroll
        for (int j = 0; j < 8; j++) a1[i][j] = 0.f;

    for (int kc = 0; kc < 256; kc += 16) {
#pragma unroll
        for (int q = 0; q < 4; q++) { int idx = tid + q*256; int k = idx >> 6, m = idx & 63;
            As[idx] = g_w1T[(kc + k)*64 + m]; }
#pragma unroll
        for (int q = 0; q < 8; q++) { int idx = tid + q*256; int k = idx >> 7, n = idx & 127;
            int c = kc + k;
            Bs[idx] = (c < 128) ? xb[c*HW + n] : kb[(c - 128)*HW + n]; }
        __syncthreads();
#pragma unroll
        for (int kk = 0; kk < 16; kk++) {
            float4 b0 = *(const float4*)&Bs[kk*128 + tx*4];
            float4 b1 = *(const float4*)&Bs[kk*128 + 64 + tx*4];
            float av[4];
#pragma unroll
            for (int i = 0; i < 4; i++) av[i] = As[kk*64 + ty*4 + i];
#pragma unroll
            for (int i = 0; i < 4; i++) {
                a1[i][0] += av[i]*b0.x; a1[i][1] += av[i]*b0.y;
                a1[i][2] += av[i]*b0.z; a1[i][3] += av[i]*b0.w;
                a1[i][4] += av[i]*b1.x; a1[i][5] += av[i]*b1.y;
                a1[i][6] += av[i]*b1.z; a1[i][7] += av[i]*b1.w;
            }
        }
        __syncthreads();
    }
    // store relu'd hidden
#pragma unroll
    for (int i = 0; i < 4; i++) {
        int m = ty*4 + i;
        float4 h0 = make_float4(fmaxf(a1[i][0],0.f), fmaxf(a1[i][1],0.f),
                                fmaxf(a1[i][2],0.f), fmaxf(a1[i][3],0.f));
        float4 h1 = make_float4(fmaxf(a1[i][4],0.f), fmaxf(a1[i][5],0.f),
                                fmaxf(a1[i][6],0.f), fmaxf(a1[i][7],0.f));
        *(float4*)&hid[m*128 + tx*4]      = h0;
        *(float4*)&hid[m*128 + 64 + tx*4] = h1;
    }
    __syncthreads();

    // stage2: M=144, K=64
    float cc[9][8];
#pragma unroll
    for (int i = 0; i < 9; i++)
#pragma unroll
        for (int j = 0; j < 8; j++) cc[i][j] = 0.f;
    float* W2s = tile;  // 2304 floats
    for (int kc = 0; kc < 64; kc += 16) {
        __syncthreads();
#pragma unroll
        for (int q = 0; q < 9; q++) { int idx = tid + q*256; int k = idx / 144, m = idx % 144;
            W2s[idx] = g_w2T[(kc + k)*144 + m]; }
        __syncthreads();
#pragma unroll
        for (int kk = 0; kk < 16; kk++) {
            int k = kc + kk;
            float4 b0 = *(const float4*)&hid[k*128 + tx*4];
            float4 b1 = *(const float4*)&hid[k*128 + 64 + tx*4];
#pragma unroll
            for (int i = 0; i < 9; i++) {
                float a = W2s[kk*144 + ty*9 + i];
                cc[i][0] += a*b0.x; cc[i][1] += a*b0.y; cc[i][2] += a*b0.z; cc[i][3] += a*b0.w;
                cc[i][4] += a*b1.x; cc[i][5] += a*b1.y; cc[i][6] += a*b1.z; cc[i][7] += a*b1.w;
            }
        }
    }
#pragma unroll
    for (int i = 0; i < 9; i++) {
        int m = ty*9 + i;
        float bias = __ldg(&e_b2[m]);
        float* op = g_wpre + (size_t)(b*144 + m)*HW + hw0;
        float4 o0 = make_float4(cc[i][0]+bias, cc[i][1]+bias, cc[i][2]+bias, cc[i][3]+bias);
        float4 o1 = make_float4(cc[i][4]+bias, cc[i][5]+bias, cc[i][6]+bias, cc[i][7]+bias);
        *(float4*)&op[tx*4]      = o0;
        *(float4*)&op[64 + tx*4] = o1;
    }
}

// ---------------- K3: value 1x1 conv (128x128 GEMM) -> g_v ----------------
__global__ void __launch_bounds__(256) k3_v(const float* __restrict__ x) {
    __shared__ float As[16 * 128];
    __shared__ float Bs[16 * 128];
    int tid = threadIdx.x, tx = tid & 15, ty = tid >> 4;
    int pb = blockIdx.x * 128, b = pb / HW, hw0 = pb % HW;
    const float* xb = x + (size_t)b*128*HW + hw0;
    float acc[8][8];
#pragma unroll
    for (int i = 0; i < 8; i++)
#pragma unroll
        for (int j = 0; j < 8; j++) acc[i][j] = 0.f;

    for (int kc = 0; kc < 128; kc += 16) {
#pragma unroll
        for (int q = 0; q < 8; q++) {
            int idx = tid + q*256; int k = idx >> 7, n = idx & 127;
            As[idx] = g_c1T[(kc + k)*128 + n];
            Bs[idx] = xb[(kc + k)*HW + n];
        }
        __syncthreads();
#pragma unroll
        for (int kk = 0; kk < 16; kk++) {
            float4 b0 = *(const float4*)&Bs[kk*128 + tx*4];
            float4 b1 = *(const float4*)&Bs[kk*128 + 64 + tx*4];
            float av[8];
#pragma unroll
            for (int i = 0; i < 8; i++) {
                int m = (i < 4) ? (ty*4 + i) : (64 + ty*4 + i - 4);
                av[i] = As[kk*128 + m];
            }
#pragma unroll
            for (int i = 0; i < 8; i++) {
                acc[i][0] += av[i]*b0.x; acc[i][1] += av[i]*b0.y;
                acc[i][2] += av[i]*b0.z; acc[i][3] += av[i]*b0.w;
                acc[i][4] += av[i]*b1.x; acc[i][5] += av[i]*b1.y;
                acc[i][6] += av[i]*b1.z; acc[i][7] += av[i]*b1.w;
            }
        }
        __syncthreads();
    }
#pragma unroll
    for (int i = 0; i < 8; i++) {
        int m = (i < 4) ? (ty*4 + i) : (64 + ty*4 + i - 4);
        float* op = g_v + (size_t)(b*128 + m)*HW + hw0;
        *(float4*)&op[tx*4]      = make_float4(acc[i][0], acc[i][1], acc[i][2], acc[i][3]);
        *(float4*)&op[64 + tx*4] = make_float4(acc[i][4], acc[i][5], acc[i][6], acc[i][7]);
    }
}

// ---------------- K4: GroupNorm stats per (b, group): 9 ch x 9216 px ----------------
__global__ void k4_gn() {
    __shared__ float rs[256], rq[256];
    int bg = blockIdx.x;            // b*16+g
    int b = bg >> 4, g = bg & 15;
    const float* base = g_wpre + (size_t)(b*144 + g*9) * HW;  // channels contiguous
    float s = 0.f, q = 0.f;
    for (int idx = threadIdx.x; idx < 9*HW; idx += 256) {
        float v = base[idx]; s += v; q += v*v;
    }
    rs[threadIdx.x] = s; rq[threadIdx.x] = q;
    __syncthreads();
    for (int o = 128; o > 0; o >>= 1) {
        if (threadIdx.x < o) { rs[threadIdx.x] += rs[threadIdx.x+o]; rq[threadIdx.x] += rq[threadIdx.x+o]; }
        __syncthreads();
    }
    if (threadIdx.x == 0) {
        float inv = 1.f / (9.f*HW);
        float mean = rs[0] * inv;
        float var  = rq[0] * inv - mean*mean;
        g_gn[bg*2]     = mean;
        g_gn[bg*2 + 1] = rsqrtf(var + 1e-5f);
    }
}

// ---------------- K5: local dynamic conv + BN partials ----------------
// block = (row h, group g(16), batch b); 96 threads (one per column)
__global__ void __launch_bounds__(96) k5_local(const float* __restrict__ gn_g,
                                               const float* __restrict__ gn_b) {
    __shared__ float wn[9 * 96];
    __shared__ float vs[8 * 294];   // [s][r(3)][col(98)]
    __shared__ float red[48];
    int h = blockIdx.x, g = blockIdx.y, b = blockIdx.z;
    int w = threadIdx.x;
    float mean = g_gn[(b*16 + g)*2], rstd = g_gn[(b*16 + g)*2 + 1];
#pragma unroll
    for (int t = 0; t < 9; t++) {
        int ch = g*9 + t;
        float raw = g_wpre[(size_t)(b*144 + ch)*HW + h*96 + w];
        wn[t*96 + w] = (raw - mean) * rstd * __ldg(&gn_g[ch]) + __ldg(&gn_b[ch]);
    }
    for (int idx = w; idx < 8*294; idx += 96) {
        int s = idx / 294, rem = idx % 294, r = rem / 98, col = rem % 98;
        int hh = h + r - 1, wc = col - 1;
        float v = 0.f;
        if ((unsigned)hh < 96u && (unsigned)wc < 96u)
            v = g_v[(size_t)(b*128 + g*8 + s)*HW + hh*96 + wc];
        vs[idx] = v;
    }
    __syncthreads();
    int lane = w & 31, warp = w >> 5;
#pragma unroll
    for (int s = 0; s < 8; s++) {
        float acc = 0.f;
        const float* vb = vs + s*294;
#pragma unroll
        for (int r = 0; r < 3; r++)
#pragma unroll
            for (int c = 0; c < 3; c++)
                acc += vb[r*98 + w + c] * wn[(r*3 + c)*96 + w];
        g_ypre[(size_t)(b*128 + g*8 + s)*HW + h*96 + w] = acc;
        float v1 = acc, v2 = acc*acc;
        for (int off = 16; off; off >>= 1) {
            v1 += __shfl_down_sync(0xffffffffu, v1, off);
            v2 += __shfl_down_sync(0xffffffffu, v2, off);
        }
        if (lane == 0) { red[warp*8 + s] = v1; red[24 + warp*8 + s] = v2; }
    }
    __syncthreads();
    if (w < 8) {
        float s1 = red[w] + red[8 + w] + red[16 + w];
        float s2 = red[24 + w] + red[32 + w] + red[40 + w];
        int c = g*8 + w;
        g_bnS[c*768 + b*96 + h] = s1;
        g_bnQ[c*768 + b*96 + h] = s2;
    }
}

// ---------------- K6: BN finalize per channel ----------------
__global__ void k6_bn() {
    __shared__ float rs[256], rq[256];
    int c = blockIdx.x;
    float s = 0.f, q = 0.f;
    for (int idx = threadIdx.x; idx < 768; idx += 256) {
        s += g_bnS[c*768 + idx]; q += g_bnQ[c*768 + idx];
    }
    rs[threadIdx.x] = s; rq[threadIdx.x] = q;
    __syncthreads();
    for (int o = 128; o > 0; o >>= 1) {
        if (threadIdx.x < o) { rs[threadIdx.x] += rs[threadIdx.x+o]; rq[threadIdx.x] += rq[threadIdx.x+o]; }
        __syncthreads();
    }
    if (threadIdx.x == 0) {
        float inv = 1.f / (float)PTOT;
        float mean = rs[0] * inv;
        float var  = rq[0] * inv - mean*mean;
        g_bn[c*2]     = mean;
        g_bn[c*2 + 1] = rsqrtf(var + 1e-5f);
    }
}

// ---------------- K7: BN apply + swish + GAP partials ----------------
__global__ void k7_swish(const float* __restrict__ bn_g, const float* __restrict__ bn_b) {
    __shared__ float rs[256];
    int c = blockIdx.x, b = blockIdx.y;
    float mean = g_bn[c*2], rstd = g_bn[c*2 + 1];
    float gg = __ldg(&bn_g[c]), bb = __ldg(&bn_b[c]);
    const float* yb = g_ypre + (size_t)(b*128 + c)*HW;
    const float* kb = g_k    + (size_t)(b*128 + c)*HW;
    float*       yo = g_y    + (size_t)(b*128 + c)*HW;
    float s = 0.f;
    for (int idx = threadIdx.x; idx < HW; idx += 256) {
        float t = (yb[idx] - mean) * rstd * gg + bb;
        float y = t / (1.f + expf(-t));
        yo[idx] = y;
        s += y + kb[idx];
    }
    rs[threadIdx.x] = s;
    __syncthreads();
    for (int o = 128; o > 0; o >>= 1) {
        if (threadIdx.x < o) rs[threadIdx.x] += rs[threadIdx.x + o];
        __syncthreads();
    }
    if (threadIdx.x == 0) g_gap[b*128 + c] = rs[0] * (1.f / (float)HW);
}

// ---------------- K8: SE MLP + radix softmax ----------------
__global__ void k8_se(const float* __restrict__ w1, const float* __restrict__ b1,
                      const float* __restrict__ w2, const float* __restrict__ b2) {
    __shared__ float gaps[128], a1s[64], a2s[256];
    int b = blockIdx.x, tid = threadIdx.x;
    if (tid < 128) gaps[tid] = g_gap[b*128 + tid];
    __syncthreads();
    if (tid < 64) {
        float s = __ldg(&b1[tid]);
        for (int c = 0; c < 128; c++) s += __ldg(&w1[tid*128 + c]) * gaps[c];
        a1s[tid] = fmaxf(s, 0.f);
    }
    __syncthreads();
    {
        float s = __ldg(&b2[tid]);
        for (int j = 0; j < 64; j++) s += __ldg(&w2[tid*64 + j]) * a1s[j];
        a2s[tid] = s;
    }
    __syncthreads();
    if (tid < 128) {
        float e0 = a2s[tid*2], e1 = a2s[tid*2 + 1];
        float m = fmaxf(e0, e1);
        float p0 = expf(e0 - m), p1 = expf(e1 - m);
        float d = p0 + p1;
        g_a[(b*128 + tid)*2]     = p0 / d;
        g_a[(b*128 + tid)*2 + 1] = p1 / d;
    }
}

// ---------------- K9: final mix ----------------
__global__ void k9_out(float* __restrict__ out) {
    int idx = blockIdx.x * 256 + threadIdx.x;   // float4 index, total 2359296
    const float4 y = ((const float4*)g_y)[idx];
    const float4 k = ((const float4*)g_k)[idx];
    int bc = idx / 2304;                        // 9216/4 floats per (b,c)
    float a0 = g_a[bc*2], a1 = g_a[bc*2 + 1];
    ((float4*)out)[idx] = make_float4(y.x*a0 + k.x*a1, y.y*a0 + k.y*a1,
                                      y.z*a0 + k.z*a1, y.w*a0 + k.w*a1);
}

// ---------------- launch ----------------
extern "C" void kernel_launch(void* const* d_in, const int* in_sizes, int n_in,
                              void* d_out, int out_size) {
    const float* x     = (const float*)d_in[0];
    const float* key_w = (const float*)d_in[1];
    const float* e_w1  = (const float*)d_in[2];
    const float* e_w2  = (const float*)d_in[3];
    const float* e_b2  = (const float*)d_in[4];
    const float* gn_g  = (const float*)d_in[5];
    const float* gn_b  = (const float*)d_in[6];
    const float* c1_w  = (const float*)d_in[7];
    const float* bn_g  = (const float*)d_in[8];
    const float* bn_b  = (const float*)d_in[9];
    const float* se_w1 = (const float*)d_in[10];
    const float* se_b1 = (const float*)d_in[11];
    const float* se_w2 = (const float*)d_in[12];
    const float* se_b2 = (const float*)d_in[13];
    float* out = (float*)d_out;

    k0_prep <<<64, 256>>>(e_w1, c1_w, e_w2);
    k1_key  <<<dim3(96, 4, 8), 256>>>(x, key_w);
    k2_embed<<<PTOT/128, 256>>>(x, e_b2);
    k3_v    <<<PTOT/128, 256>>>(x);
    k4_gn   <<<128, 256>>>();
    k5_local<<<dim3(96, 16, 8), 96>>>(gn_g, gn_b);
    k6_bn   <<<128, 256>>>();
    k7_swish<<<dim3(128, 8), 256>>>(bn_g, bn_b);
    k8_se   <<<8, 256>>>(se_w1, se_b1, se_w2, se_b2);
    k9_out  <<<PTOT*128/(256*4), 256>>>(out);
}

// round 2
// speedup vs baseline: 1.1302x; 1.1302x over previous
#include <cuda_runtime.h>
#include <math.h>

#define BB 8
#define CC 128
#define HH 96
#define WW 96
#define HW 9216            // 96*96
#define WC 144             // k*k*DIM/SP
#define PTOT (BB*HW)       // 73728

typedef unsigned long long u64;

// ---- packed f32x2 helpers (sm_100+: one instruction, two fp32 FMAs, exact IEEE rounding) ----
__device__ __forceinline__ u64 pack2(float lo, float hi) {
    u64 r; asm("mov.b64 %0, {%1,%2};" : "=l"(r) : "f"(lo), "f"(hi)); return r;
}
__device__ __forceinline__ void unpack2(u64 v, float& lo, float& hi) {
    asm("mov.b64 {%0,%1}, %2;" : "=f"(lo), "=f"(hi) : "l"(v));
}
__device__ __forceinline__ void fma2(u64& d, u64 a, u64 b) {
    asm("fma.rn.f32x2 %0, %1, %2, %0;" : "+l"(d) : "l"(a), "l"(b));
}

// ---------------- scratch (device globals; no allocation allowed) ----------------
__device__ float g_k   [BB*CC*HW];   // key_embed output (relu'd)
__device__ float g_v   [BB*CC*HW];   // value 1x1 conv
__device__ float g_wpre[BB*WC*HW];   // embed output pre-GN
__device__ float g_ypre[BB*CC*HW];   // local-conv output pre-BN
__device__ float g_y   [BB*CC*HW];   // post BN+swish
__device__ float g_w1T [256*64];     // e_w1 transposed (K-major)
__device__ float g_c1T [128*128];    // c1_w transposed
__device__ float g_w2T [64*144];     // e_w2 transposed
__device__ float g_gn  [128*2];      // per (b,group) mean, rstd
__device__ float g_bnS [128*768];    // BN partial sums  (per channel, per (b,row))
__device__ float g_bnQ [128*768];    // BN partial sumsq
__device__ float g_bn  [128*2];      // per channel mean, rstd
__device__ float g_gap [BB*CC];
__device__ float g_a   [BB*CC*2];    // radix-softmax weights

// ---------------- K0: transpose small weight matrices ----------------
__global__ void k0_prep(const float* __restrict__ e_w1, const float* __restrict__ c1_w,
                        const float* __restrict__ e_w2) {
    int idx = blockIdx.x * 256 + threadIdx.x;   // 0..16383
    if (idx < 64*256)  { int m = idx / 256, k = idx % 256; g_w1T[k*64  + m] = e_w1[idx]; }
    if (idx < 128*128) { int m = idx / 128, k = idx % 128; g_c1T[k*128 + m] = c1_w[idx]; }
    if (idx < 144*64)  { int m = idx / 64,  k = idx % 64;  g_w2T[k*144 + m] = e_w2[idx]; }
}

// ---------------- K1: grouped 3x3 conv (groups=4) + ReLU -> g_k, FFMA2 version ----------------
// block = (row h, group g, batch b); 128 threads.
// Each thread: one output-channel PAIR (packed f32x2) x 12 w positions.
__global__ void __launch_bounds__(128) k1_key(const float* __restrict__ x,
                                              const float* __restrict__ kw) {
    __shared__ float xs[32 * 294];          // [ci][r(3)][col(98)]
    __shared__ u64   wp[32 * 9 * 16];       // [(ci*9+t)*16 + cp] = {w[co0], w[co1]}
    int h = blockIdx.x, g = blockIdx.y, b = blockIdx.z;
    int tid = threadIdx.x;
    for (int idx = tid; idx < 32 * 294; idx += 128) {
        int ci = idx / 294, rem = idx % 294, r = rem / 98, col = rem % 98;
        int hh = h + r - 1, wc = col - 1;
        float v = 0.f;
        if ((unsigned)hh < 96u && (unsigned)wc < 96u)
            v = x[(b*128 + g*32 + ci) * HW + hh*96 + wc];
        xs[idx] = v;
    }
    for (int idx = tid; idx < 32*9*16; idx += 128) {
        int cpv = idx & 15, rest = idx >> 4, t = rest % 9, ci = rest / 9;
        int co0 = g*32 + cpv*2;
        float w0v = __ldg(&kw[(size_t)co0      * 32*9 + ci*9 + t]);
        float w1v = __ldg(&kw[(size_t)(co0+1)  * 32*9 + ci*9 + t]);
        wp[idx] = pack2(w0v, w1v);
    }
    __syncthreads();
    int cp = tid >> 3, pg = tid & 7, w0 = pg * 12;
    u64 acc[12];
#pragma unroll
    for (int j = 0; j < 12; j++) acc[j] = 0ull;
    for (int ci = 0; ci < 32; ci++) {
        u64 wv[9];
#pragma unroll
        for (int t = 0; t < 9; t++) wv[t] = wp[(ci*9 + t)*16 + cp];
        const float* xr = xs + ci * 294;
#pragma unroll
        for (int r = 0; r < 3; r++) {
            u64 xb[14];
#pragma unroll
            for (int j = 0; j < 14; j++) {
                float xv = xr[r*98 + w0 + j];
                xb[j] = pack2(xv, xv);
            }
#pragma unroll
            for (int c = 0; c < 3; c++) {
                u64 wgt = wv[r*3 + c];
#pragma unroll
                for (int j = 0; j < 12; j++)
                    fma2(acc[j], wgt, xb[j + c]);
            }
        }
    }
    int co0 = g*32 + cp*2;
    float* o0 = g_k + (size_t)(b*128 + co0) * HW + h*96 + w0;
    float* o1 = o0 + HW;
#pragma unroll
    for (int jj = 0; jj < 12; jj += 4) {
        float a0,b0,a1,b1,a2,b2,a3,b3;
        unpack2(acc[jj+0], a0, b0); unpack2(acc[jj+1], a1, b1);
        unpack2(acc[jj+2], a2, b2); unpack2(acc[jj+3], a3, b3);
        *(float4*)&o0[jj] = make_float4(fmaxf(a0,0.f), fmaxf(a1,0.f), fmaxf(a2,0.f), fmaxf(a3,0.f));
        *(float4*)&o1[jj] = make_float4(fmaxf(b0,0.f), fmaxf(b1,0.f), fmaxf(b2,0.f), fmaxf(b3,0.f));
    }
}

// ---------------- K2: fused embed GEMMs (FFMA2) ----------------
__global__ void __launch_bounds__(256, 2) k2_embed(const float* __restrict__ x,
                                                   const float* __restrict__ e_b2) {
    __shared__ float hid[64 * 128];   // 32KB
    __shared__ float tile[3072];      // 12KB
    float* As = tile;
    float* Bs = tile + 1024;
    int tid = threadIdx.x, tx = tid & 15, ty = tid >> 4;
    int pb = blockIdx.x * 128, b = pb / HW, hw0 = pb % HW;
    const float* xb = x   + (size_t)b*128*HW + hw0;
    const float* kb = g_k + (size_t)b*128*HW + hw0;

    u64 a1[4][4];
#pragma unroll
    for (int i = 0; i < 4; i++)
#pragma unroll
        for (int j = 0; j < 4; j++) a1[i][j] = 0ull;

    for (int kc = 0; kc < 256; kc += 16) {
#pragma unroll
        for (int q = 0; q < 4; q++) { int idx = tid + q*256; int k = idx >> 6, m = idx & 63;
            As[idx] = g_w1T[(kc + k)*64 + m]; }
#pragma unroll
        for (int q = 0; q < 8; q++) { int idx = tid + q*256; int k = idx >> 7, n = idx & 127;
            int c = kc + k;
            Bs[idx] = (c < 128) ? xb[c*HW + n] : kb[(c - 128)*HW + n]; }
        __syncthreads();
#pragma unroll
        for (int kk = 0; kk < 16; kk++) {
            ulonglong2 b0 = *(const ulonglong2*)&Bs[kk*128 + tx*4];
            ulonglong2 b1 = *(const ulonglong2*)&Bs[kk*128 + 64 + tx*4];
            float4 av = *(const float4*)&As[kk*64 + ty*4];
            u64 ap0 = pack2(av.x, av.x), ap1 = pack2(av.y, av.y);
            u64 ap2 = pack2(av.z, av.z), ap3 = pack2(av.w, av.w);
            fma2(a1[0][0], ap0, b0.x); fma2(a1[0][1], ap0, b0.y);
            fma2(a1[0][2], ap0, b1.x); fma2(a1[0][3], ap0, b1.y);
            fma2(a1[1][0], ap1, b0.x); fma2(a1[1][1], ap1, b0.y);
            fma2(a1[1][2], ap1, b1.x); fma2(a1[1][3], ap1, b1.y);
            fma2(a1[2][0], ap2, b0.x); fma2(a1[2][1], ap2, b0.y);
            fma2(a1[2][2], ap2, b1.x); fma2(a1[2][3], ap2, b1.y);
            fma2(a1[3][0], ap3, b0.x); fma2(a1[3][1], ap3, b0.y);
            fma2(a1[3][2], ap3, b1.x); fma2(a1[3][3], ap3, b1.y);
        }
        __syncthreads();
    }
    // store relu'd hidden
#pragma unroll
    for (int i = 0; i < 4; i++) {
        int m = ty*4 + i;
        float v0,v1,v2,v3,v4,v5,v6,v7;
        unpack2(a1[i][0], v0, v1); unpack2(a1[i][1], v2, v3);
        unpack2(a1[i][2], v4, v5); unpack2(a1[i][3], v6, v7);
        *(float4*)&hid[m*128 + tx*4] =
            make_float4(fmaxf(v0,0.f), fmaxf(v1,0.f), fmaxf(v2,0.f), fmaxf(v3,0.f));
        *(float4*)&hid[m*128 + 64 + tx*4] =
            make_float4(fmaxf(v4,0.f), fmaxf(v5,0.f), fmaxf(v6,0.f), fmaxf(v7,0.f));
    }
    __syncthreads();

    // stage2: M=144, K=64
    u64 cc[9][4];
#pragma unroll
    for (int i = 0; i < 9; i++)
#pragma unroll
        for (int j = 0; j < 4; j++) cc[i][j] = 0ull;
    float* W2s = tile;  // 2304 floats
    for (int kc = 0; kc < 64; kc += 16) {
        __syncthreads();
#pragma unroll
        for (int q = 0; q < 9; q++) { int idx = tid + q*256; int k = idx / 144, m = idx % 144;
            W2s[idx] = g_w2T[(kc + k)*144 + m]; }
        __syncthreads();
#pragma unroll
        for (int kk = 0; kk < 16; kk++) {
            int k = kc + kk;
            ulonglong2 b0 = *(const ulonglong2*)&hid[k*128 + tx*4];
            ulonglong2 b1 = *(const ulonglong2*)&hid[k*128 + 64 + tx*4];
#pragma unroll
            for (int i = 0; i < 9; i++) {
                float a = W2s[kk*144 + ty*9 + i];
                u64 ap = pack2(a, a);
                fma2(cc[i][0], ap, b0.x); fma2(cc[i][1], ap, b0.y);
                fma2(cc[i][2], ap, b1.x); fma2(cc[i][3], ap, b1.y);
            }
        }
    }
#pragma unroll
    for (int i = 0; i < 9; i++) {
        int m = ty*9 + i;
        float bias = __ldg(&e_b2[m]);
        float v0,v1,v2,v3,v4,v5,v6,v7;
        unpack2(cc[i][0], v0, v1); unpack2(cc[i][1], v2, v3);
        unpack2(cc[i][2], v4, v5); unpack2(cc[i][3], v6, v7);
        float* op = g_wpre + (size_t)(b*144 + m)*HW + hw0;
        *(float4*)&op[tx*4]      = make_float4(v0+bias, v1+bias, v2+bias, v3+bias);
        *(float4*)&op[64 + tx*4] = make_float4(v4+bias, v5+bias, v6+bias, v7+bias);
    }
}

// ---------------- K3: value 1x1 conv (128x128 GEMM, FFMA2) -> g_v ----------------
__global__ void __launch_bounds__(256) k3_v(const float* __restrict__ x) {
    __shared__ float As[16 * 128];
    __shared__ float Bs[16 * 128];
    int tid = threadIdx.x, tx = tid & 15, ty = tid >> 4;
    int pb = blockIdx.x * 128, b = pb / HW, hw0 = pb % HW;
    const float* xb = x + (size_t)b*128*HW + hw0;
    u64 acc[8][4];
#pragma unroll
    for (int i = 0; i < 8; i++)
#pragma unroll
        for (int j = 0; j < 4; j++) acc[i][j] = 0ull;

    for (int kc = 0; kc < 128; kc += 16) {
#pragma unroll
        for (int q = 0; q < 8; q++) {
            int idx = tid + q*256; int k = idx >> 7, n = idx & 127;
            As[idx] = g_c1T[(kc + k)*128 + n];
            Bs[idx] = xb[(kc + k)*HW + n];
        }
        __syncthreads();
#pragma unroll
        for (int kk = 0; kk < 16; kk++) {
            ulonglong2 b0 = *(const ulonglong2*)&Bs[kk*128 + tx*4];
            ulonglong2 b1 = *(const ulonglong2*)&Bs[kk*128 + 64 + tx*4];
            float4 av0 = *(const float4*)&As[kk*128 + ty*4];
            float4 av1 = *(const float4*)&As[kk*128 + 64 + ty*4];
            u64 ap;
            ap = pack2(av0.x, av0.x);
            fma2(acc[0][0], ap, b0.x); fma2(acc[0][1], ap, b0.y);
            fma2(acc[0][2], ap, b1.x); fma2(acc[0][3], ap, b1.y);
            ap = pack2(av0.y, av0.y);
            fma2(acc[1][0], ap, b0.x); fma2(acc[1][1], ap, b0.y);
            fma2(acc[1][2], ap, b1.x); fma2(acc[1][3], ap, b1.y);
            ap = pack2(av0.z, av0.z);
            fma2(acc[2][0], ap, b0.x); fma2(acc[2][1], ap, b0.y);
            fma2(acc[2][2], ap, b1.x); fma2(acc[2][3], ap, b1.y);
            ap = pack2(av0.w, av0.w);
            fma2(acc[3][0], ap, b0.x); fma2(acc[3][1], ap, b0.y);
            fma2(acc[3][2], ap, b1.x); fma2(acc[3][3], ap, b1.y);
            ap = pack2(av1.x, av1.x);
            fma2(acc[4][0], ap, b0.x); fma2(acc[4][1], ap, b0.y);
            fma2(acc[4][2], ap, b1.x); fma2(acc[4][3], ap, b1.y);
            ap = pack2(av1.y, av1.y);
            fma2(acc[5][0], ap, b0.x); fma2(acc[5][1], ap, b0.y);
            fma2(acc[5][2], ap, b1.x); fma2(acc[5][3], ap, b1.y);
            ap = pack2(av1.z, av1.z);
            fma2(acc[6][0], ap, b0.x); fma2(acc[6][1], ap, b0.y);
            fma2(acc[6][2], ap, b1.x); fma2(acc[6][3], ap, b1.y);
            ap = pack2(av1.w, av1.w);
            fma2(acc[7][0], ap, b0.x); fma2(acc[7][1], ap, b0.y);
            fma2(acc[7][2], ap, b1.x); fma2(acc[7][3], ap, b1.y);
        }
        __syncthreads();
    }
#pragma unroll
    for (int i = 0; i < 8; i++) {
        int m = (i < 4) ? (ty*4 + i) : (64 + ty*4 + i - 4);
        float v0,v1,v2,v3,v4,v5,v6,v7;
        unpack2(acc[i][0], v0, v1); unpack2(acc[i][1], v2, v3);
        unpack2(acc[i][2], v4, v5); unpack2(acc[i][3], v6, v7);
        float* op = g_v + (size_t)(b*128 + m)*HW + hw0;
        *(float4*)&op[tx*4]      = make_float4(v0, v1, v2, v3);
        *(float4*)&op[64 + tx*4] = make_float4(v4, v5, v6, v7);
    }
}

// ---------------- K4: GroupNorm stats per (b, group) ----------------
__global__ void k4_gn() {
    __shared__ float rs[256], rq[256];
    int bg = blockIdx.x;
    int b = bg >> 4, g = bg & 15;
    const float* base = g_wpre + (size_t)(b*144 + g*9) * HW;
    float s = 0.f, q = 0.f;
    for (int idx = threadIdx.x; idx < 9*HW; idx += 256) {
        float v = base[idx]; s += v; q += v*v;
    }
    rs[threadIdx.x] = s; rq[threadIdx.x] = q;
    __syncthreads();
    for (int o = 128; o > 0; o >>= 1) {
        if (threadIdx.x < o) { rs[threadIdx.x] += rs[threadIdx.x+o]; rq[threadIdx.x] += rq[threadIdx.x+o]; }
        __syncthreads();
    }
    if (threadIdx.x == 0) {
        float inv = 1.f / (9.f*HW);
        float mean = rs[0] * inv;
        float var  = rq[0] * inv - mean*mean;
        g_gn[bg*2]     = mean;
        g_gn[bg*2 + 1] = rsqrtf(var + 1e-5f);
    }
}

// ---------------- K5: local dynamic conv + BN partials ----------------
__global__ void __launch_bounds__(96) k5_local(const float* __restrict__ gn_g,
                                               const float* __restrict__ gn_b) {
    __shared__ float wn[9 * 96];
    __shared__ float vs[8 * 294];
    __shared__ float red[48];
    int h = blockIdx.x, g = blockIdx.y, b = blockIdx.z;
    int w = threadIdx.x;
    float mean = g_gn[(b*16 + g)*2], rstd = g_gn[(b*16 + g)*2 + 1];
#pragma unroll
    for (int t = 0; t < 9; t++) {
        int ch = g*9 + t;
        float raw = g_wpre[(size_t)(b*144 + ch)*HW + h*96 + w];
        wn[t*96 + w] = (raw - mean) * rstd * __ldg(&gn_g[ch]) + __ldg(&gn_b[ch]);
    }
    for (int idx = w; idx < 8*294; idx += 96) {
        int s = idx / 294, rem = idx % 294, r = rem / 98, col = rem % 98;
        int hh = h + r - 1, wc = col - 1;
        float v = 0.f;
        if ((unsigned)hh < 96u && (unsigned)wc < 96u)
            v = g_v[(size_t)(b*128 + g*8 + s)*HW + hh*96 + wc];
        vs[idx] = v;
    }
    __syncthreads();
    int lane = w & 31, warp = w >> 5;
#pragma unroll
    for (int s = 0; s < 8; s++) {
        float acc = 0.f;
        const float* vb = vs + s*294;
#pragma unroll
        for (int r = 0; r < 3; r++)
#pragma unroll
            for (int c = 0; c < 3; c++)
                acc += vb[r*98 + w + c] * wn[(r*3 + c)*96 + w];
        g_ypre[(size_t)(b*128 + g*8 + s)*HW + h*96 + w] = acc;
        float v1 = acc, v2 = acc*acc;
        for (int off = 16; off; off >>= 1) {
            v1 += __shfl_down_sync(0xffffffffu, v1, off);
            v2 += __shfl_down_sync(0xffffffffu, v2, off);
        }
        if (lane == 0) { red[warp*8 + s] = v1; red[24 + warp*8 + s] = v2; }
    }
    __syncthreads();
    if (w < 8) {
        float s1 = red[w] + red[8 + w] + red[16 + w];
        float s2 = red[24 + w] + red[32 + w] + red[40 + w];
        int c = g*8 + w;
        g_bnS[c*768 + b*96 + h] = s1;
        g_bnQ[c*768 + b*96 + h] = s2;
    }
}

// ---------------- K6: BN finalize per channel ----------------
__global__ void k6_bn() {
    __shared__ float rs[256], rq[256];
    int c = blockIdx.x;
    float s = 0.f, q = 0.f;
    for (int idx = threadIdx.x; idx < 768; idx += 256) {
        s += g_bnS[c*768 + idx]; q += g_bnQ[c*768 + idx];
    }
    rs[threadIdx.x] = s; rq[threadIdx.x] = q;
    __syncthreads();
    for (int o = 128; o > 0; o >>= 1) {
        if (threadIdx.x < o) { rs[threadIdx.x] += rs[threadIdx.x+o]; rq[threadIdx.x] += rq[threadIdx.x+o]; }
        __syncthreads();
    }
    if (threadIdx.x == 0) {
        float inv = 1.f / (float)PTOT;
        float mean = rs[0] * inv;
        float var  = rq[0] * inv - mean*mean;
        g_bn[c*2]     = mean;
        g_bn[c*2 + 1] = rsqrtf(var + 1e-5f);
    }
}

// ---------------- K7: BN apply + swish + GAP partials ----------------
__global__ void k7_swish(const float* __restrict__ bn_g, const float* __restrict__ bn_b) {
    __shared__ float rs[256];
    int c = blockIdx.x, b = blockIdx.y;
    float mean = g_bn[c*2], rstd = g_bn[c*2 + 1];
    float gg = __ldg(&bn_g[c]), bb = __ldg(&bn_b[c]);
    const float* yb = g_ypre + (size_t)(b*128 + c)*HW;
    const float* kb = g_k    + (size_t)(b*128 + c)*HW;
    float*       yo = g_y    + (size_t)(b*128 + c)*HW;
    float s = 0.f;
    for (int idx = threadIdx.x; idx < HW; idx += 256) {
        float t = (yb[idx] - mean) * rstd * gg + bb;
        float y = t * __frcp_rn(1.f + __expf(-t));
        yo[idx] = y;
        s += y + kb[idx];
    }
    rs[threadIdx.x] = s;
    __syncthreads();
    for (int o = 128; o > 0; o >>= 1) {
        if (threadIdx.x < o) rs[threadIdx.x] += rs[threadIdx.x + o];
        __syncthreads();
    }
    if (threadIdx.x == 0) g_gap[b*128 + c] = rs[0] * (1.f / (float)HW);
}

// ---------------- K8: SE MLP + radix softmax ----------------
__global__ void k8_se(const float* __restrict__ w1, const float* __restrict__ b1,
                      const float* __restrict__ w2, const float* __restrict__ b2) {
    __shared__ float gaps[128], a1s[64], a2s[256];
    int b = blockIdx.x, tid = threadIdx.x;
    if (tid < 128) gaps[tid] = g_gap[b*128 + tid];
    __syncthreads();
    if (tid < 64) {
        float s = __ldg(&b1[tid]);
        for (int c = 0; c < 128; c++) s += __ldg(&w1[tid*128 + c]) * gaps[c];
        a1s[tid] = fmaxf(s, 0.f);
    }
    __syncthreads();
    {
        float s = __ldg(&b2[tid]);
        for (int j = 0; j < 64; j++) s += __ldg(&w2[tid*64 + j]) * a1s[j];
        a2s[tid] = s;
    }
    __syncthreads();
    if (tid < 128) {
        float e0 = a2s[tid*2], e1 = a2s[tid*2 + 1];
        float m = fmaxf(e0, e1);
        float p0 = expf(e0 - m), p1 = expf(e1 - m);
        float d = p0 + p1;
        g_a[(b*128 + tid)*2]     = p0 / d;
        g_a[(b*128 + tid)*2 + 1] = p1 / d;
    }
}

// ---------------- K9: final mix ----------------
__global__ void k9_out(float* __restrict__ out) {
    int idx = blockIdx.x * 256 + threadIdx.x;
    const float4 y = ((const float4*)g_y)[idx];
    const float4 k = ((const float4*)g_k)[idx];
    int bc = idx / 2304;
    float a0 = g_a[bc*2], a1 = g_a[bc*2 + 1];
    ((float4*)out)[idx] = make_float4(y.x*a0 + k.x*a1, y.y*a0 + k.y*a1,
                                      y.z*a0 + k.z*a1, y.w*a0 + k.w*a1);
}

// ---------------- launch ----------------
extern "C" void kernel_launch(void* const* d_in, const int* in_sizes, int n_in,
                              void* d_out, int out_size) {
    const float* x     = (const float*)d_in[0];
    const float* key_w = (const float*)d_in[1];
    const float* e_w1  = (const float*)d_in[2];
    const float* e_w2  = (const float*)d_in[3];
    const float* e_b2  = (const float*)d_in[4];
    const float* gn_g  = (const float*)d_in[5];
    const float* gn_b  = (const float*)d_in[6];
    const float* c1_w  = (const float*)d_in[7];
    const float* bn_g  = (const float*)d_in[8];
    const float* bn_b  = (const float*)d_in[9];
    const float* se_w1 = (const float*)d_in[10];
    const float* se_b1 = (const float*)d_in[11];
    const float* se_w2 = (const float*)d_in[12];
    const float* se_b2 = (const float*)d_in[13];
    float* out = (float*)d_out;

    k0_prep <<<64, 256>>>(e_w1, c1_w, e_w2);
    k1_key  <<<dim3(96, 4, 8), 128>>>(x, key_w);
    k2_embed<<<PTOT/128, 256>>>(x, e_b2);
    k3_v    <<<PTOT/128, 256>>>(x);
    k4_gn   <<<128, 256>>>();
    k5_local<<<dim3(96, 16, 8), 96>>>(gn_g, gn_b);
    k6_bn   <<<128, 256>>>();
    k7_swish<<<dim3(128, 8), 256>>>(bn_g, bn_b);
    k8_se   <<<8, 256>>>(se_w1, se_b1, se_w2, se_b2);
    k9_out  <<<PTOT*128/(256*4), 256>>>(out);
}

// round 5
// speedup vs baseline: 1.1623x; 1.0284x over previous
#include <cuda_runtime.h>
#include <cuda_bf16.h>
#include <math.h>
#include <stdint.h>

#define BB 8
#define CC 128
#define HH 96
#define WW 96
#define HW 9216            // 96*96
#define WC 144             // k*k*DIM/SP
#define PTOT (BB*HW)       // 73728

typedef unsigned long long u64;
typedef unsigned int u32;

// ---- packed f32x2 helpers ----
__device__ __forceinline__ u64 pack2(float lo, float hi) {
    u64 r; asm("mov.b64 %0, {%1,%2};" : "=l"(r) : "f"(lo), "f"(hi)); return r;
}
__device__ __forceinline__ void unpack2(u64 v, float& lo, float& hi) {
    asm("mov.b64 {%0,%1}, %2;" : "=f"(lo), "=f"(hi) : "l"(v));
}
__device__ __forceinline__ void fma2(u64& d, u64 a, u64 b) {
    asm("fma.rn.f32x2 %0, %1, %2, %0;" : "+l"(d) : "l"(a), "l"(b));
}

__device__ __forceinline__ unsigned short f2bf(float f) {
    return __bfloat16_as_ushort(__float2bfloat16(f));
}
__device__ __forceinline__ float bf2f(unsigned short u) {
    return __bfloat162float(__ushort_as_bfloat16(u));
}
__device__ __forceinline__ u32 packbf(float a, float b) {
    return (u32)f2bf(a) | ((u32)f2bf(b) << 16);
}

// m16n8k16 bf16 MMA, fp32 accumulate (HMMA path — valid on compute_103 base target)
__device__ __forceinline__ void mma_bf16(float* c, u32 a0, u32 a1, u32 a2, u32 a3,
                                         u32 b0, u32 b1) {
    asm volatile(
        "mma.sync.aligned.m16n8k16.row.col.f32.bf16.bf16.f32 "
        "{%0,%1,%2,%3}, {%4,%5,%6,%7}, {%8,%9}, {%0,%1,%2,%3};"
        : "+f"(c[0]), "+f"(c[1]), "+f"(c[2]), "+f"(c[3])
        : "r"(a0), "r"(a1), "r"(a2), "r"(a3), "r"(b0), "r"(b1));
}

// ---------------- scratch ----------------
__device__ float g_k   [BB*CC*HW];
__device__ float g_v   [BB*CC*HW];
__device__ float g_wpre[BB*WC*HW];
__device__ float g_ypre[BB*CC*HW];
__device__ float g_y   [BB*CC*HW];
__device__ float g_w1T [256*64];
__device__ float g_w2T [64*144];
// A-fragment images for k3 (c1_w): [mtile 8][kstep 8][lane 32][reg 4] u32, bf16 hi/lo
__device__ __align__(16) u32 g_Afh[8192];
__device__ __align__(16) u32 g_Afl[8192];
__device__ float g_gn  [128*2];
__device__ float g_bnS [128*768];
__device__ float g_bnQ [128*768];
__device__ float g_bn  [128*2];
__device__ float g_gap [BB*CC];
__device__ float g_a   [BB*CC*2];

// ---------------- K0: weight prep ----------------
__global__ void k0_prep(const float* __restrict__ e_w1, const float* __restrict__ c1_w,
                        const float* __restrict__ e_w2) {
    int idx = blockIdx.x * 256 + threadIdx.x;   // 0..16383
    if (idx < 64*256)  { int m = idx / 256, k = idx % 256; g_w1T[k*64  + m] = e_w1[idx]; }
    if (idx < 144*64)  { int m = idx / 64,  k = idx % 64;  g_w2T[k*144 + m] = e_w2[idx]; }
    if (idx < 8192) {
        // A fragment slot for m16n8k16: reg r, lane, kstep, mtile
        int r = idx & 3, lane = (idx >> 2) & 31, ks = (idx >> 7) & 7, mt = idx >> 10;
        int gid = lane >> 2, tig = lane & 3;
        int row = mt*16 + gid + (r & 1) * 8;
        int col = ks*16 + tig*2 + (r & 2) * 4;   // (r>>1)*8
        float w0 = c1_w[row*128 + col];
        float w1 = c1_w[row*128 + col + 1];
        unsigned short h0 = f2bf(w0), h1 = f2bf(w1);
        g_Afh[idx] = (u32)h0 | ((u32)h1 << 16);
        g_Afl[idx] = packbf(w0 - bf2f(h0), w1 - bf2f(h1));
    }
}

// ---------------- K1: grouped 3x3 conv + ReLU (FFMA2) ----------------
__global__ void __launch_bounds__(128) k1_key(const float* __restrict__ x,
                                              const float* __restrict__ kw) {
    __shared__ float xs[32 * 294];
    __shared__ u64   wp[32 * 9 * 16];
    int h = blockIdx.x, g = blockIdx.y, b = blockIdx.z;
    int tid = threadIdx.x;
    for (int idx = tid; idx < 32 * 294; idx += 128) {
        int ci = idx / 294, rem = idx % 294, r = rem / 98, col = rem % 98;
        int hh = h + r - 1, wc = col - 1;
        float v = 0.f;
        if ((unsigned)hh < 96u && (unsigned)wc < 96u)
            v = x[(b*128 + g*32 + ci) * HW + hh*96 + wc];
        xs[idx] = v;
    }
    for (int idx = tid; idx < 32*9*16; idx += 128) {
        int cpv = idx & 15, rest = idx >> 4, t = rest % 9, ci = rest / 9;
        int co0 = g*32 + cpv*2;
        float w0v = __ldg(&kw[(size_t)co0      * 32*9 + ci*9 + t]);
        float w1v = __ldg(&kw[(size_t)(co0+1)  * 32*9 + ci*9 + t]);
        wp[idx] = pack2(w0v, w1v);
    }
    __syncthreads();
    int cp = tid >> 3, pg = tid & 7, w0 = pg * 12;
    u64 acc[12];
#pragma unroll
    for (int j = 0; j < 12; j++) acc[j] = 0ull;
    for (int ci = 0; ci < 32; ci++) {
        u64 wv[9];
#pragma unroll
        for (int t = 0; t < 9; t++) wv[t] = wp[(ci*9 + t)*16 + cp];
        const float* xr = xs + ci * 294;
#pragma unroll
        for (int r = 0; r < 3; r++) {
            u64 xb[14];
#pragma unroll
            for (int j = 0; j < 14; j++) {
                float xv = xr[r*98 + w0 + j];
                xb[j] = pack2(xv, xv);
            }
#pragma unroll
            for (int c = 0; c < 3; c++) {
                u64 wgt = wv[r*3 + c];
#pragma unroll
                for (int j = 0; j < 12; j++)
                    fma2(acc[j], wgt, xb[j + c]);
            }
        }
    }
    int co0 = g*32 + cp*2;
    float* o0 = g_k + (size_t)(b*128 + co0) * HW + h*96 + w0;
    float* o1 = o0 + HW;
#pragma unroll
    for (int jj = 0; jj < 12; jj += 4) {
        float a0,b0,a1,b1,a2,b2,a3,b3;
        unpack2(acc[jj+0], a0, b0); unpack2(acc[jj+1], a1, b1);
        unpack2(acc[jj+2], a2, b2); unpack2(acc[jj+3], a3, b3);
        *(float4*)&o0[jj] = make_float4(fmaxf(a0,0.f), fmaxf(a1,0.f), fmaxf(a2,0.f), fmaxf(a3,0.f));
        *(float4*)&o1[jj] = make_float4(fmaxf(b0,0.f), fmaxf(b1,0.f), fmaxf(b2,0.f), fmaxf(b3,0.f));
    }
}

// ---------------- K2: fused embed GEMMs (FFMA2) ----------------
__global__ void __launch_bounds__(256, 2) k2_embed(const float* __restrict__ x,
                                                   const float* __restrict__ e_b2) {
    __shared__ float hid[64 * 128];
    __shared__ float tile[3072];
    float* As = tile;
    float* Bs = tile + 1024;
    int tid = threadIdx.x, tx = tid & 15, ty = tid >> 4;
    int pb = blockIdx.x * 128, b = pb / HW, hw0 = pb % HW;
    const float* xb = x   + (size_t)b*128*HW + hw0;
    const float* kb = g_k + (size_t)b*128*HW + hw0;

    u64 a1[4][4];
#pragma unroll
    for (int i = 0; i < 4; i++)
#pragma unroll
        for (int j = 0; j < 4; j++) a1[i][j] = 0ull;

    for (int kc = 0; kc < 256; kc += 16) {
#pragma unroll
        for (int q = 0; q < 4; q++) { int idx = tid + q*256; int k = idx >> 6, m = idx & 63;
            As[idx] = g_w1T[(kc + k)*64 + m]; }
#pragma unroll
        for (int q = 0; q < 8; q++) { int idx = tid + q*256; int k = idx >> 7, n = idx & 127;
            int c = kc + k;
            Bs[idx] = (c < 128) ? xb[c*HW + n] : kb[(c - 128)*HW + n]; }
        __syncthreads();
#pragma unroll
        for (int kk = 0; kk < 16; kk++) {
            ulonglong2 b0 = *(const ulonglong2*)&Bs[kk*128 + tx*4];
            ulonglong2 b1 = *(const ulonglong2*)&Bs[kk*128 + 64 + tx*4];
            float4 av = *(const float4*)&As[kk*64 + ty*4];
            u64 ap0 = pack2(av.x, av.x), ap1 = pack2(av.y, av.y);
            u64 ap2 = pack2(av.z, av.z), ap3 = pack2(av.w, av.w);
            fma2(a1[0][0], ap0, b0.x); fma2(a1[0][1], ap0, b0.y);
            fma2(a1[0][2], ap0, b1.x); fma2(a1[0][3], ap0, b1.y);
            fma2(a1[1][0], ap1, b0.x); fma2(a1[1][1], ap1, b0.y);
            fma2(a1[1][2], ap1, b1.x); fma2(a1[1][3], ap1, b1.y);
            fma2(a1[2][0], ap2, b0.x); fma2(a1[2][1], ap2, b0.y);
            fma2(a1[2][2], ap2, b1.x); fma2(a1[2][3], ap2, b1.y);
            fma2(a1[3][0], ap3, b0.x); fma2(a1[3][1], ap3, b0.y);
            fma2(a1[3][2], ap3, b1.x); fma2(a1[3][3], ap3, b1.y);
        }
        __syncthreads();
    }
#pragma unroll
    for (int i = 0; i < 4; i++) {
        int m = ty*4 + i;
        float v0,v1,v2,v3,v4,v5,v6,v7;
        unpack2(a1[i][0], v0, v1); unpack2(a1[i][1], v2, v3);
        unpack2(a1[i][2], v4, v5); unpack2(a1[i][3], v6, v7);
        *(float4*)&hid[m*128 + tx*4] =
            make_float4(fmaxf(v0,0.f), fmaxf(v1,0.f), fmaxf(v2,0.f), fmaxf(v3,0.f));
        *(float4*)&hid[m*128 + 64 + tx*4] =
            make_float4(fmaxf(v4,0.f), fmaxf(v5,0.f), fmaxf(v6,0.f), fmaxf(v7,0.f));
    }
    __syncthreads();

    u64 cc[9][4];
#pragma unroll
    for (int i = 0; i < 9; i++)
#pragma unroll
        for (int j = 0; j < 4; j++) cc[i][j] = 0ull;
    float* W2s = tile;
    for (int kc = 0; kc < 64; kc += 16) {
        __syncthreads();
#pragma unroll
        for (int q = 0; q < 9; q++) { int idx = tid + q*256; int k = idx / 144, m = idx % 144;
            W2s[idx] = g_w2T[(kc + k)*144 + m]; }
        __syncthreads();
#pragma unroll
        for (int kk = 0; kk < 16; kk++) {
            int k = kc + kk;
            ulonglong2 b0 = *(const ulonglong2*)&hid[k*128 + tx*4];
            ulonglong2 b1 = *(const ulonglong2*)&hid[k*128 + 64 + tx*4];
#pragma unroll
            for (int i = 0; i < 9; i++) {
                float a = W2s[kk*144 + ty*9 + i];
                u64 ap = pack2(a, a);
                fma2(cc[i][0], ap, b0.x); fma2(cc[i][1], ap, b0.y);
                fma2(cc[i][2], ap, b1.x); fma2(cc[i][3], ap, b1.y);
            }
        }
    }
#pragma unroll
    for (int i = 0; i < 9; i++) {
        int m = ty*9 + i;
        float bias = __ldg(&e_b2[m]);
        float v0,v1,v2,v3,v4,v5,v6,v7;
        unpack2(cc[i][0], v0, v1); unpack2(cc[i][1], v2, v3);
        unpack2(cc[i][2], v4, v5); unpack2(cc[i][3], v6, v7);
        float* op = g_wpre + (size_t)(b*144 + m)*HW + hw0;
        *(float4*)&op[tx*4]      = make_float4(v0+bias, v1+bias, v2+bias, v3+bias);
        *(float4*)&op[64 + tx*4] = make_float4(v4+bias, v5+bias, v6+bias, v7+bias);
    }
}

// ---------------- K3: value 1x1 conv via warp MMA (bf16 hi/lo split, 3 MMAs) ----------------
// D[128 out-ch, 64 px] = W[128,128] @ X[128 ch, 64 px], fp32 accum.
// smem: xs[128][65] fp32 stage + B-fragment buffers (hi/lo) in exact mma lane order.
#define K3_SMEM (33280 + 32768)
__global__ void __launch_bounds__(256) k3_mma(const float* __restrict__ x) {
    extern __shared__ float sm[];
    float* xs = sm;                       // [128][65]
    u32* bhf = (u32*)(sm + 8320);         // [kstep8][ntile8][lane32][2]
    u32* blf = bhf + 4096;
    int tid = threadIdx.x, wid = tid >> 5, lane = tid & 31;
    int pb = blockIdx.x * 64, b = pb / HW, hw0 = pb % HW;
    const float* xb = x + (size_t)b*128*HW + hw0;

    // stage x tile (coalesced float2)
    for (int i = tid; i < 128*32; i += 256) {
        int k = i >> 5, n = (i & 31) * 2;
        float2 v = *(const float2*)(xb + (size_t)k*HW + n);
        xs[k*65 + n] = v.x; xs[k*65 + n + 1] = v.y;
    }
    __syncthreads();

    // build B fragments (hi/lo) in m16n8k16 b-lane order
    for (int i = tid; i < 2048; i += 256) {
        int l2 = i & 31, nt = (i >> 5) & 7, ks = i >> 8;
        int gid = l2 >> 2, tig = l2 & 3;
        int n = nt*8 + gid, k = ks*16 + tig*2;
        float f0 = xs[k*65 + n],     f1 = xs[(k+1)*65 + n];
        float f2 = xs[(k+8)*65 + n], f3 = xs[(k+9)*65 + n];
        unsigned short h0 = f2bf(f0), h1 = f2bf(f1), h2 = f2bf(f2), h3 = f2bf(f3);
        int base = i * 2;
        bhf[base]     = (u32)h0 | ((u32)h1 << 16);
        bhf[base + 1] = (u32)h2 | ((u32)h3 << 16);
        blf[base]     = packbf(f0 - bf2f(h0), f1 - bf2f(h1));
        blf[base + 1] = packbf(f2 - bf2f(h2), f3 - bf2f(h3));
    }
    __syncthreads();

    // compute: warp wid owns m-tile [wid*16, wid*16+16)
    float acc[8][4];
#pragma unroll
    for (int i = 0; i < 8; i++)
#pragma unroll
        for (int j = 0; j < 4; j++) acc[i][j] = 0.f;

#pragma unroll
    for (int ks = 0; ks < 8; ks++) {
        uint4 ah = ((const uint4*)g_Afh)[(wid*8 + ks)*32 + lane];
        uint4 al = ((const uint4*)g_Afl)[(wid*8 + ks)*32 + lane];
#pragma unroll
        for (int nt = 0; nt < 8; nt++) {
            int base = ((ks*8 + nt)*32 + lane) * 2;
            u32 bh0 = bhf[base], bh1 = bhf[base + 1];
            u32 bl0 = blf[base], bl1 = blf[base + 1];
            mma_bf16(acc[nt], ah.x, ah.y, ah.z, ah.w, bh0, bh1);
            mma_bf16(acc[nt], ah.x, ah.y, ah.z, ah.w, bl0, bl1);
            mma_bf16(acc[nt], al.x, al.y, al.z, al.w, bh0, bh1);
        }
    }

    // epilogue: C fragment mapping -> g_v
    int gid = lane >> 2, tig = lane & 3;
    int m0 = wid*16 + gid;
    float* vb = g_v + (size_t)(b*128 + m0)*HW + hw0 + tig*2;
#pragma unroll
    for (int nt = 0; nt < 8; nt++) {
        *(float2*)(vb + nt*8)          = make_float2(acc[nt][0], acc[nt][1]);
        *(float2*)(vb + nt*8 + 8*HW)   = make_float2(acc[nt][2], acc[nt][3]);
    }
}

// ---------------- K4: GroupNorm stats ----------------
__global__ void k4_gn() {
    __shared__ float rs[256], rq[256];
    int bg = blockIdx.x;
    int b = bg >> 4, g = bg & 15;
    const float* base = g_wpre + (size_t)(b*144 + g*9) * HW;
    float s = 0.f, q = 0.f;
    for (int idx = threadIdx.x; idx < 9*HW; idx += 256) {
        float v = base[idx]; s += v; q += v*v;
    }
    rs[threadIdx.x] = s; rq[threadIdx.x] = q;
    __syncthreads();
    for (int o = 128; o > 0; o >>= 1) {
        if (threadIdx.x < o) { rs[threadIdx.x] += rs[threadIdx.x+o]; rq[threadIdx.x] += rq[threadIdx.x+o]; }
        __syncthreads();
    }
    if (threadIdx.x == 0) {
        float inv = 1.f / (9.f*HW);
        float mean = rs[0] * inv;
        float var  = rq[0] * inv - mean*mean;
        g_gn[bg*2]     = mean;
        g_gn[bg*2 + 1] = rsqrtf(var + 1e-5f);
    }
}

// ---------------- K5: local dynamic conv + BN partials ----------------
__global__ void __launch_bounds__(96) k5_local(const float* __restrict__ gn_g,
                                               const float* __restrict__ gn_b) {
    __shared__ float wn[9 * 96];
    __shared__ float vs[8 * 294];
    __shared__ float red[48];
    int h = blockIdx.x, g = blockIdx.y, b = blockIdx.z;
    int w = threadIdx.x;
    float mean = g_gn[(b*16 + g)*2], rstd = g_gn[(b*16 + g)*2 + 1];
#pragma unroll
    for (int t = 0; t < 9; t++) {
        int ch = g*9 + t;
        float raw = g_wpre[(size_t)(b*144 + ch)*HW + h*96 + w];
        wn[t*96 + w] = (raw - mean) * rstd * __ldg(&gn_g[ch]) + __ldg(&gn_b[ch]);
    }
    for (int idx = w; idx < 8*294; idx += 96) {
        int s = idx / 294, rem = idx % 294, r = rem / 98, col = rem % 98;
        int hh = h + r - 1, wc = col - 1;
        float v = 0.f;
        if ((unsigned)hh < 96u && (unsigned)wc < 96u)
            v = g_v[(size_t)(b*128 + g*8 + s)*HW + hh*96 + wc];
        vs[idx] = v;
    }
    __syncthreads();
    int lane = w & 31, warp = w >> 5;
#pragma unroll
    for (int s = 0; s < 8; s++) {
        float acc = 0.f;
        const float* vb = vs + s*294;
#pragma unroll
        for (int r = 0; r < 3; r++)
#pragma unroll
            for (int c = 0; c < 3; c++)
                acc += vb[r*98 + w + c] * wn[(r*3 + c)*96 + w];
        g_ypre[(size_t)(b*128 + g*8 + s)*HW + h*96 + w] = acc;
        float v1 = acc, v2 = acc*acc;
        for (int off = 16; off; off >>= 1) {
            v1 += __shfl_down_sync(0xffffffffu, v1, off);
            v2 += __shfl_down_sync(0xffffffffu, v2, off);
        }
        if (lane == 0) { red[warp*8 + s] = v1; red[24 + warp*8 + s] = v2; }
    }
    __syncthreads();
    if (w < 8) {
        float s1 = red[w] + red[8 + w] + red[16 + w];
        float s2 = red[24 + w] + red[32 + w] + red[40 + w];
        int c = g*8 + w;
        g_bnS[c*768 + b*96 + h] = s1;
        g_bnQ[c*768 + b*96 + h] = s2;
    }
}

// ---------------- K6: BN finalize ----------------
__global__ void k6_bn() {
    __shared__ float rs[256], rq[256];
    int c = blockIdx.x;
    float s = 0.f, q = 0.f;
    for (int idx = threadIdx.x; idx < 768; idx += 256) {
        s += g_bnS[c*768 + idx]; q += g_bnQ[c*768 + idx];
    }
    rs[threadIdx.x] = s; rq[threadIdx.x] = q;
    __syncthreads();
    for (int o = 128; o > 0; o >>= 1) {
        if (threadIdx.x < o) { rs[threadIdx.x] += rs[threadIdx.x+o]; rq[threadIdx.x] += rq[threadIdx.x+o]; }
        __syncthreads();
    }
    if (threadIdx.x == 0) {
        float inv = 1.f / (float)PTOT;
        float mean = rs[0] * inv;
        float var  = rq[0] * inv - mean*mean;
        g_bn[c*2]     = mean;
        g_bn[c*2 + 1] = rsqrtf(var + 1e-5f);
    }
}

// ---------------- K7: BN apply + swish + GAP partials ----------------
__global__ void k7_swish(const float* __restrict__ bn_g, const float* __restrict__ bn_b) {
    __shared__ float rs[256];
    int c = blockIdx.x, b = blockIdx.y;
    float mean = g_bn[c*2], rstd = g_bn[c*2 + 1];
    float gg = __ldg(&bn_g[c]), bb = __ldg(&bn_b[c]);
    const float* yb = g_ypre + (size_t)(b*128 + c)*HW;
    const float* kb = g_k    + (size_t)(b*128 + c)*HW;
    float*       yo = g_y    + (size_t)(b*128 + c)*HW;
    float s = 0.f;
    for (int idx = threadIdx.x; idx < HW; idx += 256) {
        float t = (yb[idx] - mean) * rstd * gg + bb;
        float y = t * __frcp_rn(1.f + __expf(-t));
        yo[idx] = y;
        s += y + kb[idx];
    }
    rs[threadIdx.x] = s;
    __syncthreads();
    for (int o = 128; o > 0; o >>= 1) {
        if (threadIdx.x < o) rs[threadIdx.x] += rs[threadIdx.x + o];
        __syncthreads();
    }
    if (threadIdx.x == 0) g_gap[b*128 + c] = rs[0] * (1.f / (float)HW);
}

// ---------------- K8: SE MLP + radix softmax ----------------
__global__ void k8_se(const float* __restrict__ w1, const float* __restrict__ b1,
                      const float* __restrict__ w2, const float* __restrict__ b2) {
    __shared__ float gaps[128], a1s[64], a2s[256];
    int b = blockIdx.x, tid = threadIdx.x;
    if (tid < 128) gaps[tid] = g_gap[b*128 + tid];
    __syncthreads();
    if (tid < 64) {
        float s = __ldg(&b1[tid]);
        for (int c = 0; c < 128; c++) s += __ldg(&w1[tid*128 + c]) * gaps[c];
        a1s[tid] = fmaxf(s, 0.f);
    }
    __syncthreads();
    {
        float s = __ldg(&b2[tid]);
        for (int j = 0; j < 64; j++) s += __ldg(&w2[tid*64 + j]) * a1s[j];
        a2s[tid] = s;
    }
    __syncthreads();
    if (tid < 128) {
        float e0 = a2s[tid*2], e1 = a2s[tid*2 + 1];
        float m = fmaxf(e0, e1);
        float p0 = expf(e0 - m), p1 = expf(e1 - m);
        float d = p0 + p1;
        g_a[(b*128 + tid)*2]     = p0 / d;
        g_a[(b*128 + tid)*2 + 1] = p1 / d;
    }
}

// ---------------- K9: final mix ----------------
__global__ void k9_out(float* __restrict__ out) {
    int idx = blockIdx.x * 256 + threadIdx.x;
    const float4 y = ((const float4*)g_y)[idx];
    const float4 k = ((const float4*)g_k)[idx];
    int bc = idx / 2304;
    float a0 = g_a[bc*2], a1 = g_a[bc*2 + 1];
    ((float4*)out)[idx] = make_float4(y.x*a0 + k.x*a1, y.y*a0 + k.y*a1,
                                      y.z*a0 + k.z*a1, y.w*a0 + k.w*a1);
}

// ---------------- launch ----------------
extern "C" void kernel_launch(void* const* d_in, const int* in_sizes, int n_in,
                              void* d_out, int out_size) {
    const float* x     = (const float*)d_in[0];
    const float* key_w = (const float*)d_in[1];
    const float* e_w1  = (const float*)d_in[2];
    const float* e_w2  = (const float*)d_in[3];
    const float* e_b2  = (const float*)d_in[4];
    const float* gn_g  = (const float*)d_in[5];
    const float* gn_b  = (const float*)d_in[6];
    const float* c1_w  = (const float*)d_in[7];
    const float* bn_g  = (const float*)d_in[8];
    const float* bn_b  = (const float*)d_in[9];
    const float* se_w1 = (const float*)d_in[10];
    const float* se_b1 = (const float*)d_in[11];
    const float* se_w2 = (const float*)d_in[12];
    const float* se_b2 = (const float*)d_in[13];
    float* out = (float*)d_out;

    static int once = 0;
    if (!once) {
        cudaFuncSetAttribute(k3_mma, cudaFuncAttributeMaxDynamicSharedMemorySize, K3_SMEM);
        once = 1;
    }

    k0_prep <<<64, 256>>>(e_w1, c1_w, e_w2);
    k1_key  <<<dim3(96, 4, 8), 128>>>(x, key_w);
    k2_embed<<<PTOT/128, 256>>>(x, e_b2);
    k3_mma  <<<PTOT/64, 256, K3_SMEM>>>(x);
    k4_gn   <<<128, 256>>>();
    k5_local<<<dim3(96, 16, 8), 96>>>(gn_g, gn_b);
    k6_bn   <<<128, 256>>>();
    k7_swish<<<dim3(128, 8), 256>>>(bn_g, bn_b);
    k8_se   <<<8, 256>>>(se_w1, se_b1, se_w2, se_b2);
    k9_out  <<<PTOT*128/(256*4), 256>>>(out);
}

// round 6
// speedup vs baseline: 1.1835x; 1.0182x over previous
#include <cuda_runtime.h>
#include <cuda_bf16.h>
#include <math.h>
#include <stdint.h>

#define BB 8
#define CC 128
#define HH 96
#define WW 96
#define HW 9216            // 96*96
#define WC 144             // k*k*DIM/SP
#define PTOT (BB*HW)       // 73728

typedef unsigned long long u64;
typedef unsigned int u32;

// ---- packed f32x2 helpers ----
__device__ __forceinline__ u64 pack2(float lo, float hi) {
    u64 r; asm("mov.b64 %0, {%1,%2};" : "=l"(r) : "f"(lo), "f"(hi)); return r;
}
__device__ __forceinline__ void unpack2(u64 v, float& lo, float& hi) {
    asm("mov.b64 {%0,%1}, %2;" : "=f"(lo), "=f"(hi) : "l"(v));
}
__device__ __forceinline__ void fma2(u64& d, u64 a, u64 b) {
    asm("fma.rn.f32x2 %0, %1, %2, %0;" : "+l"(d) : "l"(a), "l"(b));
}

__device__ __forceinline__ unsigned short f2bf(float f) {
    return __bfloat16_as_ushort(__float2bfloat16(f));
}
__device__ __forceinline__ float bf2f(unsigned short u) {
    return __bfloat162float(__ushort_as_bfloat16(u));
}
__device__ __forceinline__ u32 packbf(float a, float b) {
    return (u32)f2bf(a) | ((u32)f2bf(b) << 16);
}

// m16n8k16 bf16 MMA, fp32 accumulate
__device__ __forceinline__ void mma_bf16(float* c, u32 a0, u32 a1, u32 a2, u32 a3,
                                         u32 b0, u32 b1) {
    asm volatile(
        "mma.sync.aligned.m16n8k16.row.col.f32.bf16.bf16.f32 "
        "{%0,%1,%2,%3}, {%4,%5,%6,%7}, {%8,%9}, {%0,%1,%2,%3};"
        : "+f"(c[0]), "+f"(c[1]), "+f"(c[2]), "+f"(c[3])
        : "r"(a0), "r"(a1), "r"(a2), "r"(a3), "r"(b0), "r"(b1));
}

// ---------------- scratch ----------------
__device__ float g_k   [BB*CC*HW];
__device__ float g_v   [BB*CC*HW];
__device__ float g_wpre[BB*WC*HW];
__device__ float g_ypre[BB*CC*HW];
__device__ float g_y   [BB*CC*HW];
// A-fragment images (bf16 hi/lo) — all static weights, built once in k0
__device__ __align__(16) u32 g_Afh [8192];   // c1_w:  [mt8][ks8][lane32][4]
__device__ __align__(16) u32 g_Afl [8192];
__device__ __align__(16) u32 g_W1fh[8192];   // e_w1:  [mt4][ks16][lane32][4]
__device__ __align__(16) u32 g_W1fl[8192];
__device__ __align__(16) u32 g_W2fh[4608];   // e_w2:  [mt9][ks4][lane32][4]
__device__ __align__(16) u32 g_W2fl[4608];
__device__ float g_gn  [128*2];
__device__ float g_bnS [128*768];
__device__ float g_bnQ [128*768];
__device__ float g_bn  [128*2];
__device__ float g_gap [BB*CC];
__device__ float g_a   [BB*CC*2];

// ---------------- K0: weight prep (A-fragment images) ----------------
__global__ void k0_prep(const float* __restrict__ e_w1, const float* __restrict__ c1_w,
                        const float* __restrict__ e_w2) {
    int idx = blockIdx.x * 256 + threadIdx.x;   // 0..8191
    int r = idx & 3, lane = (idx >> 2) & 31;
    int gid = lane >> 2, tig = lane & 3;
    int dr = (r & 1) * 8, dc = (r & 2) * 4;
    {   // c1_w [128,128]: mt8, ks8
        int ks = (idx >> 7) & 7, mt = idx >> 10;
        int row = mt*16 + gid + dr, col = ks*16 + tig*2 + dc;
        float w0 = c1_w[row*128 + col], w1 = c1_w[row*128 + col + 1];
        g_Afh[idx] = packbf(w0, w1);
        g_Afl[idx] = packbf(w0 - bf2f(f2bf(w0)), w1 - bf2f(f2bf(w1)));
    }
    {   // e_w1 [64,256]: mt4, ks16
        int ks = (idx >> 7) & 15, mt = idx >> 11;
        int row = mt*16 + gid + dr, col = ks*16 + tig*2 + dc;
        float w0 = e_w1[row*256 + col], w1 = e_w1[row*256 + col + 1];
        g_W1fh[idx] = packbf(w0, w1);
        g_W1fl[idx] = packbf(w0 - bf2f(f2bf(w0)), w1 - bf2f(f2bf(w1)));
    }
    if (idx < 4608) {   // e_w2 [144,64]: mt9, ks4
        int ks = (idx >> 7) & 3, mt = idx >> 9;
        int row = mt*16 + gid + dr, col = ks*16 + tig*2 + dc;
        float w0 = e_w2[row*64 + col], w1 = e_w2[row*64 + col + 1];
        g_W2fh[idx] = packbf(w0, w1);
        g_W2fl[idx] = packbf(w0 - bf2f(f2bf(w0)), w1 - bf2f(f2bf(w1)));
    }
}

// ---------------- K1: grouped 3x3 conv + ReLU (FFMA2) ----------------
__global__ void __launch_bounds__(128) k1_key(const float* __restrict__ x,
                                              const float* __restrict__ kw) {
    __shared__ float xs[32 * 294];
    __shared__ u64   wp[32 * 9 * 16];
    int h = blockIdx.x, g = blockIdx.y, b = blockIdx.z;
    int tid = threadIdx.x;
    for (int idx = tid; idx < 32 * 294; idx += 128) {
        int ci = idx / 294, rem = idx % 294, r = rem / 98, col = rem % 98;
        int hh = h + r - 1, wc = col - 1;
        float v = 0.f;
        if ((unsigned)hh < 96u && (unsigned)wc < 96u)
            v = x[(b*128 + g*32 + ci) * HW + hh*96 + wc];
        xs[idx] = v;
    }
    for (int idx = tid; idx < 32*9*16; idx += 128) {
        int cpv = idx & 15, rest = idx >> 4, t = rest % 9, ci = rest / 9;
        int co0 = g*32 + cpv*2;
        float w0v = __ldg(&kw[(size_t)co0      * 32*9 + ci*9 + t]);
        float w1v = __ldg(&kw[(size_t)(co0+1)  * 32*9 + ci*9 + t]);
        wp[idx] = pack2(w0v, w1v);
    }
    __syncthreads();
    int cp = tid >> 3, pg = tid & 7, w0 = pg * 12;
    u64 acc[12];
#pragma unroll
    for (int j = 0; j < 12; j++) acc[j] = 0ull;
    for (int ci = 0; ci < 32; ci++) {
        u64 wv[9];
#pragma unroll
        for (int t = 0; t < 9; t++) wv[t] = wp[(ci*9 + t)*16 + cp];
        const float* xr = xs + ci * 294;
#pragma unroll
        for (int r = 0; r < 3; r++) {
            u64 xb[14];
#pragma unroll
            for (int j = 0; j < 14; j++) {
                float xv = xr[r*98 + w0 + j];
                xb[j] = pack2(xv, xv);
            }
#pragma unroll
            for (int c = 0; c < 3; c++) {
                u64 wgt = wv[r*3 + c];
#pragma unroll
                for (int j = 0; j < 12; j++)
                    fma2(acc[j], wgt, xb[j + c]);
            }
        }
    }
    int co0 = g*32 + cp*2;
    float* o0 = g_k + (size_t)(b*128 + co0) * HW + h*96 + w0;
    float* o1 = o0 + HW;
#pragma unroll
    for (int jj = 0; jj < 12; jj += 4) {
        float a0,b0,a1,b1,a2,b2,a3,b3;
        unpack2(acc[jj+0], a0, b0); unpack2(acc[jj+1], a1, b1);
        unpack2(acc[jj+2], a2, b2); unpack2(acc[jj+3], a3, b3);
        *(float4*)&o0[jj] = make_float4(fmaxf(a0,0.f), fmaxf(a1,0.f), fmaxf(a2,0.f), fmaxf(a3,0.f));
        *(float4*)&o1[jj] = make_float4(fmaxf(b0,0.f), fmaxf(b1,0.f), fmaxf(b2,0.f), fmaxf(b3,0.f));
    }
}

// ---------------- K2: fused embed GEMMs via warp MMA (bf16 hi/lo, 3 MMAs) ----------------
// Stage1: hid[64,128px] = relu(W1[64,256] @ [x;k]); Stage2: wpre[144,128px] = W2 @ hid + b2
// smem: xs/hid[64][130] fp32 + fragment buffers bh/bl [4ks][16nt][32lane][2]
#define K2_SMEM (33280 + 32768)
__global__ void __launch_bounds__(256) k2_mma(const float* __restrict__ x,
                                              const float* __restrict__ e_b2) {
    extern __shared__ float sm[];
    float* xs = sm;                       // 64*130 = 8320 floats (also hid later)
    u32* bh = (u32*)(sm + 8320);          // 4096 u32
    u32* bl = bh + 4096;                  // 4096 u32
    int tid = threadIdx.x, wid = tid >> 5, lane = tid & 31;
    int gid = lane >> 2, tig = lane & 3;
    int pb = blockIdx.x * 128, b = pb / HW, hw0 = pb % HW;
    const float* xb = x   + (size_t)b*128*HW + hw0;
    const float* kb = g_k + (size_t)b*128*HW + hw0;

    // ---- stage 1 ----
    int mt1 = wid & 3;       // m-tile (rows mt1*16..+16 of hidden)
    int ng  = wid >> 2;      // n-tile group: ntiles ng*8 .. ng*8+7
    float acc[8][4];
#pragma unroll
    for (int i = 0; i < 8; i++)
#pragma unroll
        for (int j = 0; j < 4; j++) acc[i][j] = 0.f;

    for (int kc = 0; kc < 4; kc++) {
        const float* src = (kc < 2) ? (xb + (size_t)kc*64*HW) : (kb + (size_t)(kc-2)*64*HW);
        for (int i = tid; i < 64*64; i += 256) {   // 64 rows x 64 float2
            int k = i >> 6, n = (i & 63) * 2;
            float2 v = *(const float2*)(src + (size_t)k*HW + n);
            xs[k*130 + n] = v.x; xs[k*130 + n + 1] = v.y;
        }
        __syncthreads();
        for (int i = tid; i < 2048; i += 256) {    // 4ks x 16nt x 32ln
            int l2 = i & 31, nt = (i >> 5) & 15, ks = i >> 9;
            int g2 = l2 >> 2, t2 = l2 & 3;
            int n = nt*8 + g2, k = ks*16 + t2*2;
            float f0 = xs[k*130 + n],     f1 = xs[(k+1)*130 + n];
            float f2 = xs[(k+8)*130 + n], f3 = xs[(k+9)*130 + n];
            int base = i * 2;
            bh[base]     = packbf(f0, f1);
            bh[base + 1] = packbf(f2, f3);
            bl[base]     = packbf(f0 - bf2f(f2bf(f0)), f1 - bf2f(f2bf(f1)));
            bl[base + 1] = packbf(f2 - bf2f(f2bf(f2)), f3 - bf2f(f2bf(f3)));
        }
        __syncthreads();
#pragma unroll
        for (int ks = 0; ks < 4; ks++) {
            int gks = kc*4 + ks;
            uint4 ah = ((const uint4*)g_W1fh)[(mt1*16 + gks)*32 + lane];
            uint4 al = ((const uint4*)g_W1fl)[(mt1*16 + gks)*32 + lane];
#pragma unroll
            for (int nt2 = 0; nt2 < 8; nt2++) {
                int nt = ng*8 + nt2;
                int base = ((ks*16 + nt)*32 + lane) * 2;
                u32 bh0 = bh[base], bh1 = bh[base + 1];
                u32 bl0 = bl[base], bl1 = bl[base + 1];
                mma_bf16(acc[nt2], ah.x, ah.y, ah.z, ah.w, bh0, bh1);
                mma_bf16(acc[nt2], ah.x, ah.y, ah.z, ah.w, bl0, bl1);
                mma_bf16(acc[nt2], al.x, al.y, al.z, al.w, bh0, bh1);
            }
        }
        __syncthreads();
    }
    // write hidden (ReLU) into xs as fp32 hid[64][130]
#pragma unroll
    for (int nt2 = 0; nt2 < 8; nt2++) {
        int n0 = (ng*8 + nt2)*8 + tig*2;
        int r0 = mt1*16 + gid;
        xs[r0*130 + n0]       = fmaxf(acc[nt2][0], 0.f);
        xs[r0*130 + n0 + 1]   = fmaxf(acc[nt2][1], 0.f);
        xs[(r0+8)*130 + n0]   = fmaxf(acc[nt2][2], 0.f);
        xs[(r0+8)*130 + n0+1] = fmaxf(acc[nt2][3], 0.f);
    }
    __syncthreads();

    // ---- stage 2 fragments from hid ----
    for (int i = tid; i < 2048; i += 256) {
        int l2 = i & 31, nt = (i >> 5) & 15, ks = i >> 9;
        int g2 = l2 >> 2, t2 = l2 & 3;
        int n = nt*8 + g2, k = ks*16 + t2*2;
        float f0 = xs[k*130 + n],     f1 = xs[(k+1)*130 + n];
        float f2 = xs[(k+8)*130 + n], f3 = xs[(k+9)*130 + n];
        int base = i * 2;
        bh[base]     = packbf(f0, f1);
        bh[base + 1] = packbf(f2, f3);
        bl[base]     = packbf(f0 - bf2f(f2bf(f0)), f1 - bf2f(f2bf(f1)));
        bl[base + 1] = packbf(f2 - bf2f(f2bf(f2)), f3 - bf2f(f2bf(f3)));
    }
    __syncthreads();

    // ---- stage 2 MMAs: warp wid owns mtile wid (16 ntiles) + slice of mtile 8 ----
    float acc2[16][4];
    float acc3[2][4];
#pragma unroll
    for (int i = 0; i < 16; i++)
#pragma unroll
        for (int j = 0; j < 4; j++) acc2[i][j] = 0.f;
#pragma unroll
    for (int i = 0; i < 2; i++)
#pragma unroll
        for (int j = 0; j < 4; j++) acc3[i][j] = 0.f;

#pragma unroll
    for (int ks = 0; ks < 4; ks++) {
        uint4 ah  = ((const uint4*)g_W2fh)[(wid*4 + ks)*32 + lane];
        uint4 al  = ((const uint4*)g_W2fl)[(wid*4 + ks)*32 + lane];
        uint4 ah8 = ((const uint4*)g_W2fh)[(8*4 + ks)*32 + lane];
        uint4 al8 = ((const uint4*)g_W2fl)[(8*4 + ks)*32 + lane];
#pragma unroll
        for (int nt = 0; nt < 16; nt++) {
            int base = ((ks*16 + nt)*32 + lane) * 2;
            u32 bh0 = bh[base], bh1 = bh[base + 1];
            u32 bl0 = bl[base], bl1 = bl[base + 1];
            mma_bf16(acc2[nt], ah.x, ah.y, ah.z, ah.w, bh0, bh1);
            mma_bf16(acc2[nt], ah.x, ah.y, ah.z, ah.w, bl0, bl1);
            mma_bf16(acc2[nt], al.x, al.y, al.z, al.w, bh0, bh1);
        }
#pragma unroll
        for (int j = 0; j < 2; j++) {
            int nt = wid*2 + j;
            int base = ((ks*16 + nt)*32 + lane) * 2;
            u32 bh0 = bh[base], bh1 = bh[base + 1];
            u32 bl0 = bl[base], bl1 = bl[base + 1];
            mma_bf16(acc3[j], ah8.x, ah8.y, ah8.z, ah8.w, bh0, bh1);
            mma_bf16(acc3[j], ah8.x, ah8.y, ah8.z, ah8.w, bl0, bl1);
            mma_bf16(acc3[j], al8.x, al8.y, al8.z, al8.w, bh0, bh1);
        }
    }

    // ---- epilogue ----
    {
        int m0 = wid*16 + gid;
        float bias0 = __ldg(&e_b2[m0]), bias1 = __ldg(&e_b2[m0 + 8]);
        float* p0 = g_wpre + (size_t)(b*144 + m0)*HW + hw0 + tig*2;
        float* p1 = p0 + (size_t)8*HW;
#pragma unroll
        for (int nt = 0; nt < 16; nt++) {
            *(float2*)(p0 + nt*8) = make_float2(acc2[nt][0] + bias0, acc2[nt][1] + bias0);
            *(float2*)(p1 + nt*8) = make_float2(acc2[nt][2] + bias1, acc2[nt][3] + bias1);
        }
        int m8 = 128 + gid;
        float bias2 = __ldg(&e_b2[m8]), bias3 = __ldg(&e_b2[m8 + 8]);
        float* q0 = g_wpre + (size_t)(b*144 + m8)*HW + hw0 + tig*2;
        float* q1 = q0 + (size_t)8*HW;
#pragma unroll
        for (int j = 0; j < 2; j++) {
            int nt = wid*2 + j;
            *(float2*)(q0 + nt*8) = make_float2(acc3[j][0] + bias2, acc3[j][1] + bias2);
            *(float2*)(q1 + nt*8) = make_float2(acc3[j][2] + bias3, acc3[j][3] + bias3);
        }
    }
}

// ---------------- K3: value 1x1 conv via warp MMA ----------------
#define K3_SMEM (33280 + 32768)
__global__ void __launch_bounds__(256) k3_mma(const float* __restrict__ x) {
    extern __shared__ float sm[];
    float* xs = sm;                       // [128][65]
    u32* bhf = (u32*)(sm + 8320);
    u32* blf = bhf + 4096;
    int tid = threadIdx.x, wid = tid >> 5, lane = tid & 31;
    int pb = blockIdx.x * 64, b = pb / HW, hw0 = pb % HW;
    const float* xb = x + (size_t)b*128*HW + hw0;

    for (int i = tid; i < 128*32; i += 256) {
        int k = i >> 5, n = (i & 31) * 2;
        float2 v = *(const float2*)(xb + (size_t)k*HW + n);
        xs[k*65 + n] = v.x; xs[k*65 + n + 1] = v.y;
    }
    __syncthreads();

    for (int i = tid; i < 2048; i += 256) {
        int l2 = i & 31, nt = (i >> 5) & 7, ks = i >> 8;
        int g2 = l2 >> 2, t2 = l2 & 3;
        int n = nt*8 + g2, k = ks*16 + t2*2;
        float f0 = xs[k*65 + n],     f1 = xs[(k+1)*65 + n];
        float f2 = xs[(k+8)*65 + n], f3 = xs[(k+9)*65 + n];
        int base = i * 2;
        bhf[base]     = packbf(f0, f1);
        bhf[base + 1] = packbf(f2, f3);
        blf[base]     = packbf(f0 - bf2f(f2bf(f0)), f1 - bf2f(f2bf(f1)));
        blf[base + 1] = packbf(f2 - bf2f(f2bf(f2)), f3 - bf2f(f2bf(f3)));
    }
    __syncthreads();

    float acc[8][4];
#pragma unroll
    for (int i = 0; i < 8; i++)
#pragma unroll
        for (int j = 0; j < 4; j++) acc[i][j] = 0.f;

#pragma unroll
    for (int ks = 0; ks < 8; ks++) {
        uint4 ah = ((const uint4*)g_Afh)[(wid*8 + ks)*32 + lane];
        uint4 al = ((const uint4*)g_Afl)[(wid*8 + ks)*32 + lane];
#pragma unroll
        for (int nt = 0; nt < 8; nt++) {
            int base = ((ks*8 + nt)*32 + lane) * 2;
            u32 bh0 = bhf[base], bh1 = bhf[base + 1];
            u32 bl0 = blf[base], bl1 = blf[base + 1];
            mma_bf16(acc[nt], ah.x, ah.y, ah.z, ah.w, bh0, bh1);
            mma_bf16(acc[nt], ah.x, ah.y, ah.z, ah.w, bl0, bl1);
            mma_bf16(acc[nt], al.x, al.y, al.z, al.w, bh0, bh1);
        }
    }

    int gid = lane >> 2, tig = lane & 3;
    int m0 = wid*16 + gid;
    float* vb = g_v + (size_t)(b*128 + m0)*HW + hw0 + tig*2;
#pragma unroll
    for (int nt = 0; nt < 8; nt++) {
        *(float2*)(vb + nt*8)        = make_float2(acc[nt][0], acc[nt][1]);
        *(float2*)(vb + nt*8 + 8*HW) = make_float2(acc[nt][2], acc[nt][3]);
    }
}

// ---------------- K4: GroupNorm stats ----------------
__global__ void k4_gn() {
    __shared__ float rs[256], rq[256];
    int bg = blockIdx.x;
    int b = bg >> 4, g = bg & 15;
    const float* base = g_wpre + (size_t)(b*144 + g*9) * HW;
    float s = 0.f, q = 0.f;
    for (int idx = threadIdx.x; idx < 9*HW; idx += 256) {
        float v = base[idx]; s += v; q += v*v;
    }
    rs[threadIdx.x] = s; rq[threadIdx.x] = q;
    __syncthreads();
    for (int o = 128; o > 0; o >>= 1) {
        if (threadIdx.x < o) { rs[threadIdx.x] += rs[threadIdx.x+o]; rq[threadIdx.x] += rq[threadIdx.x+o]; }
        __syncthreads();
    }
    if (threadIdx.x == 0) {
        float inv = 1.f / (9.f*HW);
        float mean = rs[0] * inv;
        float var  = rq[0] * inv - mean*mean;
        g_gn[bg*2]     = mean;
        g_gn[bg*2 + 1] = rsqrtf(var + 1e-5f);
    }
}

// ---------------- K5: local dynamic conv + BN partials ----------------
__global__ void __launch_bounds__(96) k5_local(const float* __restrict__ gn_g,
                                               const float* __restrict__ gn_b) {
    __shared__ float wn[9 * 96];
    __shared__ float vs[8 * 294];
    __shared__ float red[48];
    int h = blockIdx.x, g = blockIdx.y, b = blockIdx.z;
    int w = threadIdx.x;
    float mean = g_gn[(b*16 + g)*2], rstd = g_gn[(b*16 + g)*2 + 1];
#pragma unroll
    for (int t = 0; t < 9; t++) {
        int ch = g*9 + t;
        float raw = g_wpre[(size_t)(b*144 + ch)*HW + h*96 + w];
        wn[t*96 + w] = (raw - mean) * rstd * __ldg(&gn_g[ch]) + __ldg(&gn_b[ch]);
    }
    for (int idx = w; idx < 8*294; idx += 96) {
        int s = idx / 294, rem = idx % 294, r = rem / 98, col = rem % 98;
        int hh = h + r - 1, wc = col - 1;
        float v = 0.f;
        if ((unsigned)hh < 96u && (unsigned)wc < 96u)
            v = g_v[(size_t)(b*128 + g*8 + s)*HW + hh*96 + wc];
        vs[idx] = v;
    }
    __syncthreads();
    int lane = w & 31, warp = w >> 5;
#pragma unroll
    for (int s = 0; s < 8; s++) {
        float acc = 0.f;
        const float* vb = vs + s*294;
#pragma unroll
        for (int r = 0; r < 3; r++)
#pragma unroll
            for (int c = 0; c < 3; c++)
                acc += vb[r*98 + w + c] * wn[(r*3 + c)*96 + w];
        g_ypre[(size_t)(b*128 + g*8 + s)*HW + h*96 + w] = acc;
        float v1 = acc, v2 = acc*acc;
        for (int off = 16; off; off >>= 1) {
            v1 += __shfl_down_sync(0xffffffffu, v1, off);
            v2 += __shfl_down_sync(0xffffffffu, v2, off);
        }
        if (lane == 0) { red[warp*8 + s] = v1; red[24 + warp*8 + s] = v2; }
    }
    __syncthreads();
    if (w < 8) {
        float s1 = red[w] + red[8 + w] + red[16 + w];
        float s2 = red[24 + w] + red[32 + w] + red[40 + w];
        int c = g*8 + w;
        g_bnS[c*768 + b*96 + h] = s1;
        g_bnQ[c*768 + b*96 + h] = s2;
    }
}

// ---------------- K6: BN finalize ----------------
__global__ void k6_bn() {
    __shared__ float rs[256], rq[256];
    int c = blockIdx.x;
    float s = 0.f, q = 0.f;
    for (int idx = threadIdx.x; idx < 768; idx += 256) {
        s += g_bnS[c*768 + idx]; q += g_bnQ[c*768 + idx];
    }
    rs[threadIdx.x] = s; rq[threadIdx.x] = q;
    __syncthreads();
    for (int o = 128; o > 0; o >>= 1) {
        if (threadIdx.x < o) { rs[threadIdx.x] += rs[threadIdx.x+o]; rq[threadIdx.x] += rq[threadIdx.x+o]; }
        __syncthreads();
    }
    if (threadIdx.x == 0) {
        float inv = 1.f / (float)PTOT;
        float mean = rs[0] * inv;
        float var  = rq[0] * inv - mean*mean;
        g_bn[c*2]     = mean;
        g_bn[c*2 + 1] = rsqrtf(var + 1e-5f);
    }
}

// ---------------- K7: BN apply + swish + GAP partials ----------------
__global__ void k7_swish(const float* __restrict__ bn_g, const float* __restrict__ bn_b) {
    __shared__ float rs[256];
    int c = blockIdx.x, b = blockIdx.y;
    float mean = g_bn[c*2], rstd = g_bn[c*2 + 1];
    float gg = __ldg(&bn_g[c]), bb = __ldg(&bn_b[c]);
    const float* yb = g_ypre + (size_t)(b*128 + c)*HW;
    const float* kb = g_k    + (size_t)(b*128 + c)*HW;
    float*       yo = g_y    + (size_t)(b*128 + c)*HW;
    float s = 0.f;
    for (int idx = threadIdx.x; idx < HW; idx += 256) {
        float t = (yb[idx] - mean) * rstd * gg + bb;
        float y = t * __frcp_rn(1.f + __expf(-t));
        yo[idx] = y;
        s += y + kb[idx];
    }
    rs[threadIdx.x] = s;
    __syncthreads();
    for (int o = 128; o > 0; o >>= 1) {
        if (threadIdx.x < o) rs[threadIdx.x] += rs[threadIdx.x + o];
        __syncthreads();
    }
    if (threadIdx.x == 0) g_gap[b*128 + c] = rs[0] * (1.f / (float)HW);
}

// ---------------- K8: SE MLP + radix softmax ----------------
__global__ void k8_se(const float* __restrict__ w1, const float* __restrict__ b1,
                      const float* __restrict__ w2, const float* __restrict__ b2) {
    __shared__ float gaps[128], a1s[64], a2s[256];
    int b = blockIdx.x, tid = threadIdx.x;
    if (tid < 128) gaps[tid] = g_gap[b*128 + tid];
    __syncthreads();
    if (tid < 64) {
        float s = __ldg(&b1[tid]);
        for (int c = 0; c < 128; c++) s += __ldg(&w1[tid*128 + c]) * gaps[c];
        a1s[tid] = fmaxf(s, 0.f);
    }
    __syncthreads();
    {
        float s = __ldg(&b2[tid]);
        for (int j = 0; j < 64; j++) s += __ldg(&w2[tid*64 + j]) * a1s[j];
        a2s[tid] = s;
    }
    __syncthreads();
    if (tid < 128) {
        float e0 = a2s[tid*2], e1 = a2s[tid*2 + 1];
        float m = fmaxf(e0, e1);
        float p0 = expf(e0 - m), p1 = expf(e1 - m);
        float d = p0 + p1;
        g_a[(b*128 + tid)*2]     = p0 / d;
        g_a[(b*128 + tid)*2 + 1] = p1 / d;
    }
}

// ---------------- K9: final mix ----------------
__global__ void k9_out(float* __restrict__ out) {
    int idx = blockIdx.x * 256 + threadIdx.x;
    const float4 y = ((const float4*)g_y)[idx];
    const float4 k = ((const float4*)g_k)[idx];
    int bc = idx / 2304;
    float a0 = g_a[bc*2], a1 = g_a[bc*2 + 1];
    ((float4*)out)[idx] = make_float4(y.x*a0 + k.x*a1, y.y*a0 + k.y*a1,
                                      y.z*a0 + k.z*a1, y.w*a0 + k.w*a1);
}

// ---------------- launch ----------------
extern "C" void kernel_launch(void* const* d_in, const int* in_sizes, int n_in,
                              void* d_out, int out_size) {
    const float* x     = (const float*)d_in[0];
    const float* key_w = (const float*)d_in[1];
    const float* e_w1  = (const float*)d_in[2];
    const float* e_w2  = (const float*)d_in[3];
    const float* e_b2  = (const float*)d_in[4];
    const float* gn_g  = (const float*)d_in[5];
    const float* gn_b  = (const float*)d_in[6];
    const float* c1_w  = (const float*)d_in[7];
    const float* bn_g  = (const float*)d_in[8];
    const float* bn_b  = (const float*)d_in[9];
    const float* se_w1 = (const float*)d_in[10];
    const float* se_b1 = (const float*)d_in[11];
    const float* se_w2 = (const float*)d_in[12];
    const float* se_b2 = (const float*)d_in[13];
    float* out = (float*)d_out;

    cudaFuncSetAttribute(k2_mma, cudaFuncAttributeMaxDynamicSharedMemorySize, K2_SMEM);
    cudaFuncSetAttribute(k3_mma, cudaFuncAttributeMaxDynamicSharedMemorySize, K3_SMEM);

    k0_prep <<<32, 256>>>(e_w1, c1_w, e_w2);
    k1_key  <<<dim3(96, 4, 8), 128>>>(x, key_w);
    k2_mma  <<<PTOT/128, 256, K2_SMEM>>>(x, e_b2);
    k3_mma  <<<PTOT/64, 256, K3_SMEM>>>(x);
    k4_gn   <<<128, 256>>>();
    k5_local<<<dim3(96, 16, 8), 96>>>(gn_g, gn_b);
    k6_bn   <<<128, 256>>>();
    k7_swish<<<dim3(128, 8), 256>>>(bn_g, bn_b);
    k8_se   <<<8, 256>>>(se_w1, se_b1, se_w2, se_b2);
    k9_out  <<<PTOT*128/(256*4), 256>>>(out);
}

// round 7
// speedup vs baseline: 1.5468x; 1.3070x over previous
#include <cuda_runtime.h>
#include <cuda_bf16.h>
#include <math.h>
#include <stdint.h>

#define BB 8
#define CC 128
#define HH 96
#define WW 96
#define HW 9216            // 96*96
#define WC 144             // k*k*DIM/SP
#define PTOT (BB*HW)       // 73728

typedef unsigned long long u64;
typedef unsigned int u32;

__device__ __forceinline__ unsigned short f2bf(float f) {
    return __bfloat16_as_ushort(__float2bfloat16(f));
}
__device__ __forceinline__ float bf2f(unsigned short u) {
    return __bfloat162float(__ushort_as_bfloat16(u));
}
__device__ __forceinline__ u32 packbf(float a, float b) {
    return (u32)f2bf(a) | ((u32)f2bf(b) << 16);
}

// m16n8k16 bf16 MMA, fp32 accumulate
__device__ __forceinline__ void mma_bf16(float* c, u32 a0, u32 a1, u32 a2, u32 a3,
                                         u32 b0, u32 b1) {
    asm volatile(
        "mma.sync.aligned.m16n8k16.row.col.f32.bf16.bf16.f32 "
        "{%0,%1,%2,%3}, {%4,%5,%6,%7}, {%8,%9}, {%0,%1,%2,%3};"
        : "+f"(c[0]), "+f"(c[1]), "+f"(c[2]), "+f"(c[3])
        : "r"(a0), "r"(a1), "r"(a2), "r"(a3), "r"(b0), "r"(b1));
}

// ---------------- scratch ----------------
__device__ float g_k   [BB*CC*HW];
__device__ float g_v   [BB*CC*HW];
__device__ float g_wpre[BB*WC*HW];
__device__ float g_ypre[BB*CC*HW];
__device__ float g_y   [BB*CC*HW];
// A-fragment images (bf16 hi/lo) — static weights, built once in k0
__device__ __align__(16) u32 g_Afh [8192];    // c1_w:  [mt8][ks8][lane32][4]
__device__ __align__(16) u32 g_Afl [8192];
__device__ __align__(16) u32 g_W1fh[8192];    // e_w1:  [mt4][ks16][lane32][4]
__device__ __align__(16) u32 g_W1fl[8192];
__device__ __align__(16) u32 g_W2fh[4608];    // e_w2:  [mt9][ks4][lane32][4]
__device__ __align__(16) u32 g_W2fl[4608];
__device__ __align__(16) u32 g_KWfh[18432];   // key_w: [g4][mt2][ks18][lane32][4], k = tap*32+ci
__device__ __align__(16) u32 g_KWfl[18432];
__device__ float g_gn  [128*2];
__device__ float g_bnS [128*768];
__device__ float g_bnQ [128*768];
__device__ float g_bn  [128*2];
__device__ float g_gap [BB*CC];
__device__ float g_a   [BB*CC*2];

// ---------------- K0: weight prep (A-fragment images) ----------------
__global__ void k0_prep(const float* __restrict__ e_w1, const float* __restrict__ c1_w,
                        const float* __restrict__ e_w2, const float* __restrict__ key_w) {
    int idx = blockIdx.x * 256 + threadIdx.x;   // 0..18431
    int r = idx & 3, lane = (idx >> 2) & 31;
    int gid = lane >> 2, tig = lane & 3;
    int dr = (r & 1) * 8, dc = (r & 2) * 4;
    if (idx < 8192) {   // c1_w [128,128]: mt8, ks8
        int ks = (idx >> 7) & 7, mt = idx >> 10;
        int row = mt*16 + gid + dr, col = ks*16 + tig*2 + dc;
        float w0 = c1_w[row*128 + col], w1 = c1_w[row*128 + col + 1];
        g_Afh[idx] = packbf(w0, w1);
        g_Afl[idx] = packbf(w0 - bf2f(f2bf(w0)), w1 - bf2f(f2bf(w1)));
    }
    if (idx < 8192) {   // e_w1 [64,256]: mt4, ks16
        int ks = (idx >> 7) & 15, mt = idx >> 11;
        int row = mt*16 + gid + dr, col = ks*16 + tig*2 + dc;
        float w0 = e_w1[row*256 + col], w1 = e_w1[row*256 + col + 1];
        g_W1fh[idx] = packbf(w0, w1);
        g_W1fl[idx] = packbf(w0 - bf2f(f2bf(w0)), w1 - bf2f(f2bf(w1)));
    }
    if (idx < 4608) {   // e_w2 [144,64]: mt9, ks4
        int ks = (idx >> 7) & 3, mt = idx >> 9;
        int row = mt*16 + gid + dr, col = ks*16 + tig*2 + dc;
        float w0 = e_w2[row*64 + col], w1 = e_w2[row*64 + col + 1];
        g_W2fh[idx] = packbf(w0, w1);
        g_W2fl[idx] = packbf(w0 - bf2f(f2bf(w0)), w1 - bf2f(f2bf(w1)));
    }
    {   // key_w [128,32,3,3] grouped: [g4][mt2][ks18][lane32][4], K-order k = tap*32 + ci
        int idx2 = idx >> 7;              // 0..143
        int ks = idx2 % 18, gmt = idx2 / 18;
        int mt = gmt & 1, gg = gmt >> 1;
        int row = mt*16 + gid + dr;       // co within group (0..31)
        int colk = ks*16 + tig*2 + dc;    // 0..286, even
        int t = colk >> 5, ci = colk & 31;
        const float* wb = key_w + ((size_t)(gg*32 + row)*32 + ci)*9 + t;
        float w0 = wb[0], w1 = wb[9];     // ci and ci+1 (same tap)
        g_KWfh[idx] = packbf(w0, w1);
        g_KWfl[idx] = packbf(w0 - bf2f(f2bf(w0)), w1 - bf2f(f2bf(w1)));
    }
}

// ---------------- K1: grouped 3x3 conv + ReLU via warp MMA ----------------
// block = (row h, group g, batch b); 384 threads = 12 warps, one ntile (8 px) each.
// B fragments built on the fly from padded row tile xs[32ci][3r][98col].
__global__ void __launch_bounds__(384) k1_mma(const float* __restrict__ x) {
    __shared__ float xs[32 * 294];
    int h = blockIdx.x, g = blockIdx.y, b = blockIdx.z;
    int tid = threadIdx.x, wid = tid >> 5, lane = tid & 31;
    for (int idx = tid; idx < 32 * 294; idx += 384) {
        int ci = idx / 294, rem = idx % 294, r = rem / 98, col = rem % 98;
        int hh = h + r - 1, wc = col - 1;
        float v = 0.f;
        if ((unsigned)hh < 96u && (unsigned)wc < 96u)
            v = x[(b*128 + g*32 + ci) * HW + hh*96 + wc];
        xs[idx] = v;
    }
    __syncthreads();

    int gid = lane >> 2, tig = lane & 3;
    int nbase = wid*8 + gid;          // pixel column this lane covers
    float acc0[4] = {0.f,0.f,0.f,0.f};
    float acc1[4] = {0.f,0.f,0.f,0.f};
    const uint4* AH = (const uint4*)g_KWfh + (size_t)g*2*18*32;
    const uint4* AL = (const uint4*)g_KWfl + (size_t)g*2*18*32;

#pragma unroll
    for (int ks = 0; ks < 18; ks++) {
        const int t = ks >> 1, cib = (ks & 1) * 16;
        const int r = t / 3, c = t - 3*r;
        int ci0 = cib + tig*2;
        const float* base = xs + r*98 + nbase + c;
        float v0 = base[ ci0      *294];
        float v1 = base[(ci0 + 1) *294];
        float v2 = base[(ci0 + 8) *294];
        float v3 = base[(ci0 + 9) *294];
        u32 bh0 = packbf(v0, v1), bh1 = packbf(v2, v3);
        u32 bl0 = packbf(v0 - bf2f(f2bf(v0)), v1 - bf2f(f2bf(v1)));
        u32 bl1 = packbf(v2 - bf2f(f2bf(v2)), v3 - bf2f(f2bf(v3)));
        uint4 ah0 = AH[(0*18 + ks)*32 + lane];
        uint4 al0 = AL[(0*18 + ks)*32 + lane];
        uint4 ah1 = AH[(1*18 + ks)*32 + lane];
        uint4 al1 = AL[(1*18 + ks)*32 + lane];
        mma_bf16(acc0, ah0.x, ah0.y, ah0.z, ah0.w, bh0, bh1);
        mma_bf16(acc0, ah0.x, ah0.y, ah0.z, ah0.w, bl0, bl1);
        mma_bf16(acc0, al0.x, al0.y, al0.z, al0.w, bh0, bh1);
        mma_bf16(acc1, ah1.x, ah1.y, ah1.z, ah1.w, bh0, bh1);
        mma_bf16(acc1, ah1.x, ah1.y, ah1.z, ah1.w, bl0, bl1);
        mma_bf16(acc1, al1.x, al1.y, al1.z, al1.w, bh0, bh1);
    }

    // epilogue: relu, C-frag mapping -> g_k
    int n0 = wid*8 + tig*2;
    {
        int co = g*32 + gid;              // mt0 rows gid, gid+8
        float* p = g_k + (size_t)(b*128 + co)*HW + h*96 + n0;
        *(float2*)p            = make_float2(fmaxf(acc0[0],0.f), fmaxf(acc0[1],0.f));
        *(float2*)(p + 8*HW)   = make_float2(fmaxf(acc0[2],0.f), fmaxf(acc0[3],0.f));
        float* q = p + 16*HW;             // mt1 rows gid+16, gid+24
        *(float2*)q            = make_float2(fmaxf(acc1[0],0.f), fmaxf(acc1[1],0.f));
        *(float2*)(q + 8*HW)   = make_float2(fmaxf(acc1[2],0.f), fmaxf(acc1[3],0.f));
    }
}

// ---------------- K2: fused embed GEMMs via warp MMA (bf16 hi/lo, 3 MMAs) ----------------
#define K2_SMEM (33280 + 32768)
__global__ void __launch_bounds__(256) k2_mma(const float* __restrict__ x,
                                              const float* __restrict__ e_b2) {
    extern __shared__ float sm[];
    float* xs = sm;                       // 64*130 floats (also hid later)
    u32* bh = (u32*)(sm + 8320);
    u32* bl = bh + 4096;
    int tid = threadIdx.x, wid = tid >> 5, lane = tid & 31;
    int gid = lane >> 2, tig = lane & 3;
    int pb = blockIdx.x * 128, b = pb / HW, hw0 = pb % HW;
    const float* xb = x   + (size_t)b*128*HW + hw0;
    const float* kb = g_k + (size_t)b*128*HW + hw0;

    int mt1 = wid & 3, ng = wid >> 2;
    float acc[8][4];
#pragma unroll
    for (int i = 0; i < 8; i++)
#pragma unroll
        for (int j = 0; j < 4; j++) acc[i][j] = 0.f;

    for (int kc = 0; kc < 4; kc++) {
        const float* src = (kc < 2) ? (xb + (size_t)kc*64*HW) : (kb + (size_t)(kc-2)*64*HW);
        for (int i = tid; i < 64*64; i += 256) {
            int k = i >> 6, n = (i & 63) * 2;
            float2 v = *(const float2*)(src + (size_t)k*HW + n);
            xs[k*130 + n] = v.x; xs[k*130 + n + 1] = v.y;
        }
        __syncthreads();
        for (int i = tid; i < 2048; i += 256) {
            int l2 = i & 31, nt = (i >> 5) & 15, ks = i >> 9;
            int g2 = l2 >> 2, t2 = l2 & 3;
            int n = nt*8 + g2, k = ks*16 + t2*2;
            float f0 = xs[k*130 + n],     f1 = xs[(k+1)*130 + n];
            float f2 = xs[(k+8)*130 + n], f3 = xs[(k+9)*130 + n];
            int base = i * 2;
            bh[base]     = packbf(f0, f1);
            bh[base + 1] = packbf(f2, f3);
            bl[base]     = packbf(f0 - bf2f(f2bf(f0)), f1 - bf2f(f2bf(f1)));
            bl[base + 1] = packbf(f2 - bf2f(f2bf(f2)), f3 - bf2f(f2bf(f3)));
        }
        __syncthreads();
#pragma unroll
        for (int ks = 0; ks < 4; ks++) {
            int gks = kc*4 + ks;
            uint4 ah = ((const uint4*)g_W1fh)[(mt1*16 + gks)*32 + lane];
            uint4 al = ((const uint4*)g_W1fl)[(mt1*16 + gks)*32 + lane];
#pragma unroll
            for (int nt2 = 0; nt2 < 8; nt2++) {
                int nt = ng*8 + nt2;
                int base = ((ks*16 + nt)*32 + lane) * 2;
                u32 bh0 = bh[base], bh1 = bh[base + 1];
                u32 bl0 = bl[base], bl1 = bl[base + 1];
                mma_bf16(acc[nt2], ah.x, ah.y, ah.z, ah.w, bh0, bh1);
                mma_bf16(acc[nt2], ah.x, ah.y, ah.z, ah.w, bl0, bl1);
                mma_bf16(acc[nt2], al.x, al.y, al.z, al.w, bh0, bh1);
            }
        }
        __syncthreads();
    }
#pragma unroll
    for (int nt2 = 0; nt2 < 8; nt2++) {
        int n0 = (ng*8 + nt2)*8 + tig*2;
        int r0 = mt1*16 + gid;
        xs[r0*130 + n0]       = fmaxf(acc[nt2][0], 0.f);
        xs[r0*130 + n0 + 1]   = fmaxf(acc[nt2][1], 0.f);
        xs[(r0+8)*130 + n0]   = fmaxf(acc[nt2][2], 0.f);
        xs[(r0+8)*130 + n0+1] = fmaxf(acc[nt2][3], 0.f);
    }
    __syncthreads();

    for (int i = tid; i < 2048; i += 256) {
        int l2 = i & 31, nt = (i >> 5) & 15, ks = i >> 9;
        int g2 = l2 >> 2, t2 = l2 & 3;
        int n = nt*8 + g2, k = ks*16 + t2*2;
        float f0 = xs[k*130 + n],     f1 = xs[(k+1)*130 + n];
        float f2 = xs[(k+8)*130 + n], f3 = xs[(k+9)*130 + n];
        int base = i * 2;
        bh[base]     = packbf(f0, f1);
        bh[base + 1] = packbf(f2, f3);
        bl[base]     = packbf(f0 - bf2f(f2bf(f0)), f1 - bf2f(f2bf(f1)));
        bl[base + 1] = packbf(f2 - bf2f(f2bf(f2)), f3 - bf2f(f2bf(f3)));
    }
    __syncthreads();

    float acc2[16][4];
    float acc3[2][4];
#pragma unroll
    for (int i = 0; i < 16; i++)
#pragma unroll
        for (int j = 0; j < 4; j++) acc2[i][j] = 0.f;
#pragma unroll
    for (int i = 0; i < 2; i++)
#pragma unroll
        for (int j = 0; j < 4; j++) acc3[i][j] = 0.f;

#pragma unroll
    for (int ks = 0; ks < 4; ks++) {
        uint4 ah  = ((const uint4*)g_W2fh)[(wid*4 + ks)*32 + lane];
        uint4 al  = ((const uint4*)g_W2fl)[(wid*4 + ks)*32 + lane];
        uint4 ah8 = ((const uint4*)g_W2fh)[(8*4 + ks)*32 + lane];
        uint4 al8 = ((const uint4*)g_W2fl)[(8*4 + ks)*32 + lane];
#pragma unroll
        for (int nt = 0; nt < 16; nt++) {
            int base = ((ks*16 + nt)*32 + lane) * 2;
            u32 bh0 = bh[base], bh1 = bh[base + 1];
            u32 bl0 = bl[base], bl1 = bl[base + 1];
            mma_bf16(acc2[nt], ah.x, ah.y, ah.z, ah.w, bh0, bh1);
            mma_bf16(acc2[nt], ah.x, ah.y, ah.z, ah.w, bl0, bl1);
            mma_bf16(acc2[nt], al.x, al.y, al.z, al.w, bh0, bh1);
        }
#pragma unroll
        for (int j = 0; j < 2; j++) {
            int nt = wid*2 + j;
            int base = ((ks*16 + nt)*32 + lane) * 2;
            u32 bh0 = bh[base], bh1 = bh[base + 1];
            u32 bl0 = bl[base], bl1 = bl[base + 1];
            mma_bf16(acc3[j], ah8.x, ah8.y, ah8.z, ah8.w, bh0, bh1);
            mma_bf16(acc3[j], ah8.x, ah8.y, ah8.z, ah8.w, bl0, bl1);
            mma_bf16(acc3[j], al8.x, al8.y, al8.z, al8.w, bh0, bh1);
        }
    }

    {
        int m0 = wid*16 + gid;
        float bias0 = __ldg(&e_b2[m0]), bias1 = __ldg(&e_b2[m0 + 8]);
        float* p0 = g_wpre + (size_t)(b*144 + m0)*HW + hw0 + tig*2;
        float* p1 = p0 + (size_t)8*HW;
#pragma unroll
        for (int nt = 0; nt < 16; nt++) {
            *(float2*)(p0 + nt*8) = make_float2(acc2[nt][0] + bias0, acc2[nt][1] + bias0);
            *(float2*)(p1 + nt*8) = make_float2(acc2[nt][2] + bias1, acc2[nt][3] + bias1);
        }
        int m8 = 128 + gid;
        float bias2 = __ldg(&e_b2[m8]), bias3 = __ldg(&e_b2[m8 + 8]);
        float* q0 = g_wpre + (size_t)(b*144 + m8)*HW + hw0 + tig*2;
        float* q1 = q0 + (size_t)8*HW;
#pragma unroll
        for (int j = 0; j < 2; j++) {
            int nt = wid*2 + j;
            *(float2*)(q0 + nt*8) = make_float2(acc3[j][0] + bias2, acc3[j][1] + bias2);
            *(float2*)(q1 + nt*8) = make_float2(acc3[j][2] + bias3, acc3[j][3] + bias3);
        }
    }
}

// ---------------- K3: value 1x1 conv via warp MMA ----------------
#define K3_SMEM (33280 + 32768)
__global__ void __launch_bounds__(256) k3_mma(const float* __restrict__ x) {
    extern __shared__ float sm[];
    float* xs = sm;
    u32* bhf = (u32*)(sm + 8320);
    u32* blf = bhf + 4096;
    int tid = threadIdx.x, wid = tid >> 5, lane = tid & 31;
    int pb = blockIdx.x * 64, b = pb / HW, hw0 = pb % HW;
    const float* xb = x + (size_t)b*128*HW + hw0;

    for (int i = tid; i < 128*32; i += 256) {
        int k = i >> 5, n = (i & 31) * 2;
        float2 v = *(const float2*)(xb + (size_t)k*HW + n);
        xs[k*65 + n] = v.x; xs[k*65 + n + 1] = v.y;
    }
    __syncthreads();

    for (int i = tid; i < 2048; i += 256) {
        int l2 = i & 31, nt = (i >> 5) & 7, ks = i >> 8;
        int g2 = l2 >> 2, t2 = l2 & 3;
        int n = nt*8 + g2, k = ks*16 + t2*2;
        float f0 = xs[k*65 + n],     f1 = xs[(k+1)*65 + n];
        float f2 = xs[(k+8)*65 + n], f3 = xs[(k+9)*65 + n];
        int base = i * 2;
        bhf[base]     = packbf(f0, f1);
        bhf[base + 1] = packbf(f2, f3);
        blf[base]     = packbf(f0 - bf2f(f2bf(f0)), f1 - bf2f(f2bf(f1)));
        blf[base + 1] = packbf(f2 - bf2f(f2bf(f2)), f3 - bf2f(f2bf(f3)));
    }
    __syncthreads();

    float acc[8][4];
#pragma unroll
    for (int i = 0; i < 8; i++)
#pragma unroll
        for (int j = 0; j < 4; j++) acc[i][j] = 0.f;

#pragma unroll
    for (int ks = 0; ks < 8; ks++) {
        uint4 ah = ((const uint4*)g_Afh)[(wid*8 + ks)*32 + lane];
        uint4 al = ((const uint4*)g_Afl)[(wid*8 + ks)*32 + lane];
#pragma unroll
        for (int nt = 0; nt < 8; nt++) {
            int base = ((ks*8 + nt)*32 + lane) * 2;
            u32 bh0 = bhf[base], bh1 = bhf[base + 1];
            u32 bl0 = blf[base], bl1 = blf[base + 1];
            mma_bf16(acc[nt], ah.x, ah.y, ah.z, ah.w, bh0, bh1);
            mma_bf16(acc[nt], ah.x, ah.y, ah.z, ah.w, bl0, bl1);
            mma_bf16(acc[nt], al.x, al.y, al.z, al.w, bh0, bh1);
        }
    }

    int gid = lane >> 2, tig = lane & 3;
    int m0 = wid*16 + gid;
    float* vb = g_v + (size_t)(b*128 + m0)*HW + hw0 + tig*2;
#pragma unroll
    for (int nt = 0; nt < 8; nt++) {
        *(float2*)(vb + nt*8)        = make_float2(acc[nt][0], acc[nt][1]);
        *(float2*)(vb + nt*8 + 8*HW) = make_float2(acc[nt][2], acc[nt][3]);
    }
}

// ---------------- K4: GroupNorm stats ----------------
__global__ void k4_gn() {
    __shared__ float rs[256], rq[256];
    int bg = blockIdx.x;
    int b = bg >> 4, g = bg & 15;
    const float* base = g_wpre + (size_t)(b*144 + g*9) * HW;
    float s = 0.f, q = 0.f;
    for (int idx = threadIdx.x; idx < 9*HW; idx += 256) {
        float v = base[idx]; s += v; q += v*v;
    }
    rs[threadIdx.x] = s; rq[threadIdx.x] = q;
    __syncthreads();
    for (int o = 128; o > 0; o >>= 1) {
        if (threadIdx.x < o) { rs[threadIdx.x] += rs[threadIdx.x+o]; rq[threadIdx.x] += rq[threadIdx.x+o]; }
        __syncthreads();
    }
    if (threadIdx.x == 0) {
        float inv = 1.f / (9.f*HW);
        float mean = rs[0] * inv;
        float var  = rq[0] * inv - mean*mean;
        g_gn[bg*2]     = mean;
        g_gn[bg*2 + 1] = rsqrtf(var + 1e-5f);
    }
}

// ---------------- K5: local dynamic conv + BN partials ----------------
__global__ void __launch_bounds__(96) k5_local(const float* __restrict__ gn_g,
                                               const float* __restrict__ gn_b) {
    __shared__ float wn[9 * 96];
    __shared__ float vs[8 * 294];
    __shared__ float red[48];
    int h = blockIdx.x, g = blockIdx.y, b = blockIdx.z;
    int w = threadIdx.x;
    float mean = g_gn[(b*16 + g)*2], rstd = g_gn[(b*16 + g)*2 + 1];
#pragma unroll
    for (int t = 0; t < 9; t++) {
        int ch = g*9 + t;
        float raw = g_wpre[(size_t)(b*144 + ch)*HW + h*96 + w];
        wn[t*96 + w] = (raw - mean) * rstd * __ldg(&gn_g[ch]) + __ldg(&gn_b[ch]);
    }
    for (int idx = w; idx < 8*294; idx += 96) {
        int s = idx / 294, rem = idx % 294, r = rem / 98, col = rem % 98;
        int hh = h + r - 1, wc = col - 1;
        float v = 0.f;
        if ((unsigned)hh < 96u && (unsigned)wc < 96u)
            v = g_v[(size_t)(b*128 + g*8 + s)*HW + hh*96 + wc];
        vs[idx] = v;
    }
    __syncthreads();
    int lane = w & 31, warp = w >> 5;
#pragma unroll
    for (int s = 0; s < 8; s++) {
        float acc = 0.f;
        const float* vb = vs + s*294;
#pragma unroll
        for (int r = 0; r < 3; r++)
#pragma unroll
            for (int c = 0; c < 3; c++)
                acc += vb[r*98 + w + c] * wn[(r*3 + c)*96 + w];
        g_ypre[(size_t)(b*128 + g*8 + s)*HW + h*96 + w] = acc;
        float v1 = acc, v2 = acc*acc;
        for (int off = 16; off; off >>= 1) {
            v1 += __shfl_down_sync(0xffffffffu, v1, off);
            v2 += __shfl_down_sync(0xffffffffu, v2, off);
        }
        if (lane == 0) { red[warp*8 + s] = v1; red[24 + warp*8 + s] = v2; }
    }
    __syncthreads();
    if (w < 8) {
        float s1 = red[w] + red[8 + w] + red[16 + w];
        float s2 = red[24 + w] + red[32 + w] + red[40 + w];
        int c = g*8 + w;
        g_bnS[c*768 + b*96 + h] = s1;
        g_bnQ[c*768 + b*96 + h] = s2;
    }
}

// ---------------- K6: BN finalize ----------------
__global__ void k6_bn() {
    __shared__ float rs[256], rq[256];
    int c = blockIdx.x;
    float s = 0.f, q = 0.f;
    for (int idx = threadIdx.x; idx < 768; idx += 256) {
        s += g_bnS[c*768 + idx]; q += g_bnQ[c*768 + idx];
    }
    rs[threadIdx.x] = s; rq[threadIdx.x] = q;
    __syncthreads();
    for (int o = 128; o > 0; o >>= 1) {
        if (threadIdx.x < o) { rs[threadIdx.x] += rs[threadIdx.x+o]; rq[threadIdx.x] += rq[threadIdx.x+o]; }
        __syncthreads();
    }
    if (threadIdx.x == 0) {
        float inv = 1.f / (float)PTOT;
        float mean = rs[0] * inv;
        float var  = rq[0] * inv - mean*mean;
        g_bn[c*2]     = mean;
        g_bn[c*2 + 1] = rsqrtf(var + 1e-5f);
    }
}

// ---------------- K7: BN apply + swish + GAP partials ----------------
__global__ void k7_swish(const float* __restrict__ bn_g, const float* __restrict__ bn_b) {
    __shared__ float rs[256];
    int c = blockIdx.x, b = blockIdx.y;
    float mean = g_bn[c*2], rstd = g_bn[c*2 + 1];
    float gg = __ldg(&bn_g[c]), bb = __ldg(&bn_b[c]);
    const float* yb = g_ypre + (size_t)(b*128 + c)*HW;
    const float* kb = g_k    + (size_t)(b*128 + c)*HW;
    float*       yo = g_y    + (size_t)(b*128 + c)*HW;
    float s = 0.f;
    for (int idx = threadIdx.x; idx < HW; idx += 256) {
        float t = (yb[idx] - mean) * rstd * gg + bb;
        float y = t * __frcp_rn(1.f + __expf(-t));
        yo[idx] = y;
        s += y + kb[idx];
    }
    rs[threadIdx.x] = s;
    __syncthreads();
    for (int o = 128; o > 0; o >>= 1) {
        if (threadIdx.x < o) rs[threadIdx.x] += rs[threadIdx.x + o];
        __syncthreads();
    }
    if (threadIdx.x == 0) g_gap[b*128 + c] = rs[0] * (1.f / (float)HW);
}

// ---------------- K8: SE MLP + radix softmax ----------------
__global__ void k8_se(const float* __restrict__ w1, const float* __restrict__ b1,
                      const float* __restrict__ w2, const float* __restrict__ b2) {
    __shared__ float gaps[128], a1s[64], a2s[256];
    int b = blockIdx.x, tid = threadIdx.x;
    if (tid < 128) gaps[tid] = g_gap[b*128 + tid];
    __syncthreads();
    if (tid < 64) {
        float s = __ldg(&b1[tid]);
        for (int c = 0; c < 128; c++) s += __ldg(&w1[tid*128 + c]) * gaps[c];
        a1s[tid] = fmaxf(s, 0.f);
    }
    __syncthreads();
    {
        float s = __ldg(&b2[tid]);
        for (int j = 0; j < 64; j++) s += __ldg(&w2[tid*64 + j]) * a1s[j];
        a2s[tid] = s;
    }
    __syncthreads();
    if (tid < 128) {
        float e0 = a2s[tid*2], e1 = a2s[tid*2 + 1];
        float m = fmaxf(e0, e1);
        float p0 = expf(e0 - m), p1 = expf(e1 - m);
        float d = p0 + p1;
        g_a[(b*128 + tid)*2]     = p0 / d;
        g_a[(b*128 + tid)*2 + 1] = p1 / d;
    }
}

// ---------------- K9: final mix ----------------
__global__ void k9_out(float* __restrict__ out) {
    int idx = blockIdx.x * 256 + threadIdx.x;
    const float4 y = ((const float4*)g_y)[idx];
    const float4 k = ((const float4*)g_k)[idx];
    int bc = idx / 2304;
    float a0 = g_a[bc*2], a1 = g_a[bc*2 + 1];
    ((float4*)out)[idx] = make_float4(y.x*a0 + k.x*a1, y.y*a0 + k.y*a1,
                                      y.z*a0 + k.z*a1, y.w*a0 + k.w*a1);
}

// ---------------- launch ----------------
extern "C" void kernel_launch(void* const* d_in, const int* in_sizes, int n_in,
                              void* d_out, int out_size) {
    const float* x     = (const float*)d_in[0];
    const float* key_w = (const float*)d_in[1];
    const float* e_w1  = (const float*)d_in[2];
    const float* e_w2  = (const float*)d_in[3];
    const float* e_b2  = (const float*)d_in[4];
    const float* gn_g  = (const float*)d_in[5];
    const float* gn_b  = (const float*)d_in[6];
    const float* c1_w  = (const float*)d_in[7];
    const float* bn_g  = (const float*)d_in[8];
    const float* bn_b  = (const float*)d_in[9];
    const float* se_w1 = (const float*)d_in[10];
    const float* se_b1 = (const float*)d_in[11];
    const float* se_w2 = (const float*)d_in[12];
    const float* se_b2 = (const float*)d_in[13];
    float* out = (float*)d_out;

    cudaFuncSetAttribute(k2_mma, cudaFuncAttributeMaxDynamicSharedMemorySize, K2_SMEM);
    cudaFuncSetAttribute(k3_mma, cudaFuncAttributeMaxDynamicSharedMemorySize, K3_SMEM);

    k0_prep <<<72, 256>>>(e_w1, c1_w, e_w2, key_w);
    k1_mma  <<<dim3(96, 4, 8), 384>>>(x);
    k2_mma  <<<PTOT/128, 256, K2_SMEM>>>(x, e_b2);
    k3_mma  <<<PTOT/64, 256, K3_SMEM>>>(x);
    k4_gn   <<<128, 256>>>();
    k5_local<<<dim3(96, 16, 8), 96>>>(gn_g, gn_b);
    k6_bn   <<<128, 256>>>();
    k7_swish<<<dim3(128, 8), 256>>>(bn_g, bn_b);
    k8_se   <<<8, 256>>>(se_w1, se_b1, se_w2, se_b2);
    k9_out  <<<PTOT*128/(256*4), 256>>>(out);
}

// round 8
// speedup vs baseline: 1.6549x; 1.0699x over previous
#include <cuda_runtime.h>
#include <cuda_bf16.h>
#include <math.h>
#include <stdint.h>

#define BB 8
#define CC 128
#define HH 96
#define WW 96
#define HW 9216            // 96*96
#define WC 144             // k*k*DIM/SP
#define PTOT (BB*HW)       // 73728

typedef unsigned long long u64;
typedef unsigned int u32;

__device__ __forceinline__ unsigned short f2bf(float f) {
    return __bfloat16_as_ushort(__float2bfloat16(f));
}
__device__ __forceinline__ float bf2f(unsigned short u) {
    return __bfloat162float(__ushort_as_bfloat16(u));
}
__device__ __forceinline__ u32 packbf(float a, float b) {
    return (u32)f2bf(a) | ((u32)f2bf(b) << 16);
}

// m16n8k16 bf16 MMA, fp32 accumulate
__device__ __forceinline__ void mma_bf16(float* c, u32 a0, u32 a1, u32 a2, u32 a3,
                                         u32 b0, u32 b1) {
    asm volatile(
        "mma.sync.aligned.m16n8k16.row.col.f32.bf16.bf16.f32 "
        "{%0,%1,%2,%3}, {%4,%5,%6,%7}, {%8,%9}, {%0,%1,%2,%3};"
        : "+f"(c[0]), "+f"(c[1]), "+f"(c[2]), "+f"(c[3])
        : "r"(a0), "r"(a1), "r"(a2), "r"(a3), "r"(b0), "r"(b1));
}

// ---------------- scratch ----------------
__device__ float g_k   [BB*CC*HW];
__device__ float g_v   [BB*CC*HW];
__device__ float g_wpre[BB*WC*HW];
__device__ float g_ypre[BB*CC*HW];
__device__ float g_y   [BB*CC*HW];
// A-fragment images (bf16 hi/lo) — static weights, built once in k0
__device__ __align__(16) u32 g_Afh [8192];    // c1_w:  [mt8][ks8][lane32][4]
__device__ __align__(16) u32 g_Afl [8192];
__device__ __align__(16) u32 g_W1fh[8192];    // e_w1:  [mt4][ks16][lane32][4]
__device__ __align__(16) u32 g_W1fl[8192];
__device__ __align__(16) u32 g_W2fh[4608];    // e_w2:  [mt9][ks4][lane32][4]
__device__ __align__(16) u32 g_W2fl[4608];
__device__ __align__(16) u32 g_KWfh[18432];   // key_w: [g4][mt2][ks18][lane32][4], k = tap*32+ci
__device__ __align__(16) u32 g_KWfl[18432];
__device__ float g_gn  [128*2];
__device__ float g_bnS [128*768];
__device__ float g_bnQ [128*768];
__device__ float g_bn  [128*2];
__device__ float g_gap [BB*CC];
__device__ float g_a   [BB*CC*2];

// ---------------- K0: weight prep (A-fragment images) ----------------
__global__ void k0_prep(const float* __restrict__ e_w1, const float* __restrict__ c1_w,
                        const float* __restrict__ e_w2, const float* __restrict__ key_w) {
    int idx = blockIdx.x * 256 + threadIdx.x;   // 0..18431
    int r = idx & 3, lane = (idx >> 2) & 31;
    int gid = lane >> 2, tig = lane & 3;
    int dr = (r & 1) * 8, dc = (r & 2) * 4;
    if (idx < 8192) {   // c1_w [128,128]: mt8, ks8
        int ks = (idx >> 7) & 7, mt = idx >> 10;
        int row = mt*16 + gid + dr, col = ks*16 + tig*2 + dc;
        float w0 = c1_w[row*128 + col], w1 = c1_w[row*128 + col + 1];
        g_Afh[idx] = packbf(w0, w1);
        g_Afl[idx] = packbf(w0 - bf2f(f2bf(w0)), w1 - bf2f(f2bf(w1)));
    }
    if (idx < 8192) {   // e_w1 [64,256]: mt4, ks16
        int ks = (idx >> 7) & 15, mt = idx >> 11;
        int row = mt*16 + gid + dr, col = ks*16 + tig*2 + dc;
        float w0 = e_w1[row*256 + col], w1 = e_w1[row*256 + col + 1];
        g_W1fh[idx] = packbf(w0, w1);
        g_W1fl[idx] = packbf(w0 - bf2f(f2bf(w0)), w1 - bf2f(f2bf(w1)));
    }
    if (idx < 4608) {   // e_w2 [144,64]: mt9, ks4
        int ks = (idx >> 7) & 3, mt = idx >> 9;
        int row = mt*16 + gid + dr, col = ks*16 + tig*2 + dc;
        float w0 = e_w2[row*64 + col], w1 = e_w2[row*64 + col + 1];
        g_W2fh[idx] = packbf(w0, w1);
        g_W2fl[idx] = packbf(w0 - bf2f(f2bf(w0)), w1 - bf2f(f2bf(w1)));
    }
    {   // key_w [128,32,3,3] grouped: [g4][mt2][ks18][lane32][4], K-order k = tap*32 + ci
        int idx2 = idx >> 7;              // 0..143
        int ks = idx2 % 18, gmt = idx2 / 18;
        int mt = gmt & 1, gg = gmt >> 1;
        int row = mt*16 + gid + dr;
        int colk = ks*16 + tig*2 + dc;
        int t = colk >> 5, ci = colk & 31;
        const float* wb = key_w + ((size_t)(gg*32 + row)*32 + ci)*9 + t;
        float w0 = wb[0], w1 = wb[9];
        g_KWfh[idx] = packbf(w0, w1);
        g_KWfl[idx] = packbf(w0 - bf2f(f2bf(w0)), w1 - bf2f(f2bf(w1)));
    }
}

// ---------------- K1: grouped 3x3 conv + ReLU via warp MMA ----------------
__global__ void __launch_bounds__(384) k1_mma(const float* __restrict__ x) {
    __shared__ float xs[32 * 294];
    int h = blockIdx.x, g = blockIdx.y, b = blockIdx.z;
    int tid = threadIdx.x, wid = tid >> 5, lane = tid & 31;
    for (int idx = tid; idx < 32 * 294; idx += 384) {
        int ci = idx / 294, rem = idx % 294, r = rem / 98, col = rem % 98;
        int hh = h + r - 1, wc = col - 1;
        float v = 0.f;
        if ((unsigned)hh < 96u && (unsigned)wc < 96u)
            v = x[(b*128 + g*32 + ci) * HW + hh*96 + wc];
        xs[idx] = v;
    }
    __syncthreads();

    int gid = lane >> 2, tig = lane & 3;
    int nbase = wid*8 + gid;
    float acc0[4] = {0.f,0.f,0.f,0.f};
    float acc1[4] = {0.f,0.f,0.f,0.f};
    const uint4* AH = (const uint4*)g_KWfh + (size_t)g*2*18*32;
    const uint4* AL = (const uint4*)g_KWfl + (size_t)g*2*18*32;

#pragma unroll
    for (int ks = 0; ks < 18; ks++) {
        const int t = ks >> 1, cib = (ks & 1) * 16;
        const int r = t / 3, c = t - 3*r;
        int ci0 = cib + tig*2;
        const float* base = xs + r*98 + nbase + c;
        float v0 = base[ ci0      *294];
        float v1 = base[(ci0 + 1) *294];
        float v2 = base[(ci0 + 8) *294];
        float v3 = base[(ci0 + 9) *294];
        u32 bh0 = packbf(v0, v1), bh1 = packbf(v2, v3);
        u32 bl0 = packbf(v0 - bf2f(f2bf(v0)), v1 - bf2f(f2bf(v1)));
        u32 bl1 = packbf(v2 - bf2f(f2bf(v2)), v3 - bf2f(f2bf(v3)));
        uint4 ah0 = AH[(0*18 + ks)*32 + lane];
        uint4 al0 = AL[(0*18 + ks)*32 + lane];
        uint4 ah1 = AH[(1*18 + ks)*32 + lane];
        uint4 al1 = AL[(1*18 + ks)*32 + lane];
        mma_bf16(acc0, ah0.x, ah0.y, ah0.z, ah0.w, bh0, bh1);
        mma_bf16(acc0, ah0.x, ah0.y, ah0.z, ah0.w, bl0, bl1);
        mma_bf16(acc0, al0.x, al0.y, al0.z, al0.w, bh0, bh1);
        mma_bf16(acc1, ah1.x, ah1.y, ah1.z, ah1.w, bh0, bh1);
        mma_bf16(acc1, ah1.x, ah1.y, ah1.z, ah1.w, bl0, bl1);
        mma_bf16(acc1, al1.x, al1.y, al1.z, al1.w, bh0, bh1);
    }

    int n0 = wid*8 + tig*2;
    {
        int co = g*32 + gid;
        float* p = g_k + (size_t)(b*128 + co)*HW + h*96 + n0;
        *(float2*)p            = make_float2(fmaxf(acc0[0],0.f), fmaxf(acc0[1],0.f));
        *(float2*)(p + 8*HW)   = make_float2(fmaxf(acc0[2],0.f), fmaxf(acc0[3],0.f));
        float* q = p + 16*HW;
        *(float2*)q            = make_float2(fmaxf(acc1[0],0.f), fmaxf(acc1[1],0.f));
        *(float2*)(q + 8*HW)   = make_float2(fmaxf(acc1[2],0.f), fmaxf(acc1[3],0.f));
    }
}

// ---------------- K2: fused embed GEMMs + value GEMM via warp MMA ----------------
// Stage1: hid[64,128px] = relu(W1 @ [x;k]);  v[128,128px] = c1_w @ x (rides on x chunks)
// Stage2: wpre[144,128px] = W2 @ hid + b2
#define K2_SMEM (33280 + 32768)
__global__ void __launch_bounds__(256) k2_mma(const float* __restrict__ x,
                                              const float* __restrict__ e_b2) {
    extern __shared__ float sm[];
    float* xs = sm;                       // 64*130 floats (also hid later)
    u32* bh = (u32*)(sm + 8320);
    u32* bl = bh + 4096;
    int tid = threadIdx.x, wid = tid >> 5, lane = tid & 31;
    int gid = lane >> 2, tig = lane & 3;
    int pb = blockIdx.x * 128, b = pb / HW, hw0 = pb % HW;
    const float* xb = x   + (size_t)b*128*HW + hw0;
    const float* kb = g_k + (size_t)b*128*HW + hw0;

    int mt1 = wid & 3, ng = wid >> 2;
    float acc[8][4];
#pragma unroll
    for (int i = 0; i < 8; i++)
#pragma unroll
        for (int j = 0; j < 4; j++) acc[i][j] = 0.f;

    // ---- chunks kc=0,1 (x): stage-1 MMAs + value-GEMM MMAs on shared B frags ----
    {
        float accv[16][4];
#pragma unroll
        for (int i = 0; i < 16; i++)
#pragma unroll
            for (int j = 0; j < 4; j++) accv[i][j] = 0.f;

        for (int kc = 0; kc < 2; kc++) {
            const float* src = xb + (size_t)kc*64*HW;
            for (int i = tid; i < 64*64; i += 256) {
                int k = i >> 6, n = (i & 63) * 2;
                float2 v = *(const float2*)(src + (size_t)k*HW + n);
                xs[k*130 + n] = v.x; xs[k*130 + n + 1] = v.y;
            }
            __syncthreads();
            for (int i = tid; i < 2048; i += 256) {
                int l2 = i & 31, nt = (i >> 5) & 15, ks = i >> 9;
                int g2 = l2 >> 2, t2 = l2 & 3;
                int n = nt*8 + g2, k = ks*16 + t2*2;
                float f0 = xs[k*130 + n],     f1 = xs[(k+1)*130 + n];
                float f2 = xs[(k+8)*130 + n], f3 = xs[(k+9)*130 + n];
                int base = i * 2;
                bh[base]     = packbf(f0, f1);
                bh[base + 1] = packbf(f2, f3);
                bl[base]     = packbf(f0 - bf2f(f2bf(f0)), f1 - bf2f(f2bf(f1)));
                bl[base + 1] = packbf(f2 - bf2f(f2bf(f2)), f3 - bf2f(f2bf(f3)));
            }
            __syncthreads();
#pragma unroll
            for (int ks = 0; ks < 4; ks++) {
                int gks = kc*4 + ks;
                // stage-1 (W1) MMAs
                uint4 ah = ((const uint4*)g_W1fh)[(mt1*16 + gks)*32 + lane];
                uint4 al = ((const uint4*)g_W1fl)[(mt1*16 + gks)*32 + lane];
#pragma unroll
                for (int nt2 = 0; nt2 < 8; nt2++) {
                    int nt = ng*8 + nt2;
                    int base = ((ks*16 + nt)*32 + lane) * 2;
                    u32 bh0 = bh[base], bh1 = bh[base + 1];
                    u32 bl0 = bl[base], bl1 = bl[base + 1];
                    mma_bf16(acc[nt2], ah.x, ah.y, ah.z, ah.w, bh0, bh1);
                    mma_bf16(acc[nt2], ah.x, ah.y, ah.z, ah.w, bl0, bl1);
                    mma_bf16(acc[nt2], al.x, al.y, al.z, al.w, bh0, bh1);
                }
                // value (c1_w) MMAs — warp owns v-mtile wid, all 16 ntiles
                uint4 vh = ((const uint4*)g_Afh)[(wid*8 + gks)*32 + lane];
                uint4 vl = ((const uint4*)g_Afl)[(wid*8 + gks)*32 + lane];
#pragma unroll
                for (int nt = 0; nt < 16; nt++) {
                    int base = ((ks*16 + nt)*32 + lane) * 2;
                    u32 bh0 = bh[base], bh1 = bh[base + 1];
                    u32 bl0 = bl[base], bl1 = bl[base + 1];
                    mma_bf16(accv[nt], vh.x, vh.y, vh.z, vh.w, bh0, bh1);
                    mma_bf16(accv[nt], vh.x, vh.y, vh.z, vh.w, bl0, bl1);
                    mma_bf16(accv[nt], vl.x, vl.y, vl.z, vl.w, bh0, bh1);
                }
            }
            __syncthreads();
        }
        // v epilogue (frees accv registers before stage 2)
        int m0 = wid*16 + gid;
        float* vb0 = g_v + (size_t)(b*128 + m0)*HW + hw0 + tig*2;
        float* vb1 = vb0 + (size_t)8*HW;
#pragma unroll
        for (int nt = 0; nt < 16; nt++) {
            *(float2*)(vb0 + nt*8) = make_float2(accv[nt][0], accv[nt][1]);
            *(float2*)(vb1 + nt*8) = make_float2(accv[nt][2], accv[nt][3]);
        }
    }

    // ---- chunks kc=2,3 (k): stage-1 only ----
    for (int kc = 2; kc < 4; kc++) {
        const float* src = kb + (size_t)(kc-2)*64*HW;
        for (int i = tid; i < 64*64; i += 256) {
            int k = i >> 6, n = (i & 63) * 2;
            float2 v = *(const float2*)(src + (size_t)k*HW + n);
            xs[k*130 + n] = v.x; xs[k*130 + n + 1] = v.y;
        }
        __syncthreads();
        for (int i = tid; i < 2048; i += 256) {
            int l2 = i & 31, nt = (i >> 5) & 15, ks = i >> 9;
            int g2 = l2 >> 2, t2 = l2 & 3;
            int n = nt*8 + g2, k = ks*16 + t2*2;
            float f0 = xs[k*130 + n],     f1 = xs[(k+1)*130 + n];
            float f2 = xs[(k+8)*130 + n], f3 = xs[(k+9)*130 + n];
            int base = i * 2;
            bh[base]     = packbf(f0, f1);
            bh[base + 1] = packbf(f2, f3);
            bl[base]     = packbf(f0 - bf2f(f2bf(f0)), f1 - bf2f(f2bf(f1)));
            bl[base + 1] = packbf(f2 - bf2f(f2bf(f2)), f3 - bf2f(f2bf(f3)));
        }
        __syncthreads();
#pragma unroll
        for (int ks = 0; ks < 4; ks++) {
            int gks = kc*4 + ks;
            uint4 ah = ((const uint4*)g_W1fh)[(mt1*16 + gks)*32 + lane];
            uint4 al = ((const uint4*)g_W1fl)[(mt1*16 + gks)*32 + lane];
#pragma unroll
            for (int nt2 = 0; nt2 < 8; nt2++) {
                int nt = ng*8 + nt2;
                int base = ((ks*16 + nt)*32 + lane) * 2;
                u32 bh0 = bh[base], bh1 = bh[base + 1];
                u32 bl0 = bl[base], bl1 = bl[base + 1];
                mma_bf16(acc[nt2], ah.x, ah.y, ah.z, ah.w, bh0, bh1);
                mma_bf16(acc[nt2], ah.x, ah.y, ah.z, ah.w, bl0, bl1);
                mma_bf16(acc[nt2], al.x, al.y, al.z, al.w, bh0, bh1);
            }
        }
        __syncthreads();
    }

    // write hidden (ReLU) into xs as fp32 hid[64][130]
#pragma unroll
    for (int nt2 = 0; nt2 < 8; nt2++) {
        int n0 = (ng*8 + nt2)*8 + tig*2;
        int r0 = mt1*16 + gid;
        xs[r0*130 + n0]       = fmaxf(acc[nt2][0], 0.f);
        xs[r0*130 + n0 + 1]   = fmaxf(acc[nt2][1], 0.f);
        xs[(r0+8)*130 + n0]   = fmaxf(acc[nt2][2], 0.f);
        xs[(r0+8)*130 + n0+1] = fmaxf(acc[nt2][3], 0.f);
    }
    __syncthreads();

    // stage-2 fragments from hid
    for (int i = tid; i < 2048; i += 256) {
        int l2 = i & 31, nt = (i >> 5) & 15, ks = i >> 9;
        int g2 = l2 >> 2, t2 = l2 & 3;
        int n = nt*8 + g2, k = ks*16 + t2*2;
        float f0 = xs[k*130 + n],     f1 = xs[(k+1)*130 + n];
        float f2 = xs[(k+8)*130 + n], f3 = xs[(k+9)*130 + n];
        int base = i * 2;
        bh[base]     = packbf(f0, f1);
        bh[base + 1] = packbf(f2, f3);
        bl[base]     = packbf(f0 - bf2f(f2bf(f0)), f1 - bf2f(f2bf(f1)));
        bl[base + 1] = packbf(f2 - bf2f(f2bf(f2)), f3 - bf2f(f2bf(f3)));
    }
    __syncthreads();

    float acc2[16][4];
    float acc3[2][4];
#pragma unroll
    for (int i = 0; i < 16; i++)
#pragma unroll
        for (int j = 0; j < 4; j++) acc2[i][j] = 0.f;
#pragma unroll
    for (int i = 0; i < 2; i++)
#pragma unroll
        for (int j = 0; j < 4; j++) acc3[i][j] = 0.f;

#pragma unroll
    for (int ks = 0; ks < 4; ks++) {
        uint4 ah  = ((const uint4*)g_W2fh)[(wid*4 + ks)*32 + lane];
        uint4 al  = ((const uint4*)g_W2fl)[(wid*4 + ks)*32 + lane];
        uint4 ah8 = ((const uint4*)g_W2fh)[(8*4 + ks)*32 + lane];
        uint4 al8 = ((const uint4*)g_W2fl)[(8*4 + ks)*32 + lane];
#pragma unroll
        for (int nt = 0; nt < 16; nt++) {
            int base = ((ks*16 + nt)*32 + lane) * 2;
            u32 bh0 = bh[base], bh1 = bh[base + 1];
            u32 bl0 = bl[base], bl1 = bl[base + 1];
            mma_bf16(acc2[nt], ah.x, ah.y, ah.z, ah.w, bh0, bh1);
            mma_bf16(acc2[nt], ah.x, ah.y, ah.z, ah.w, bl0, bl1);
            mma_bf16(acc2[nt], al.x, al.y, al.z, al.w, bh0, bh1);
        }
#pragma unroll
        for (int j = 0; j < 2; j++) {
            int nt = wid*2 + j;
            int base = ((ks*16 + nt)*32 + lane) * 2;
            u32 bh0 = bh[base], bh1 = bh[base + 1];
            u32 bl0 = bl[base], bl1 = bl[base + 1];
            mma_bf16(acc3[j], ah8.x, ah8.y, ah8.z, ah8.w, bh0, bh1);
            mma_bf16(acc3[j], ah8.x, ah8.y, ah8.z, ah8.w, bl0, bl1);
            mma_bf16(acc3[j], al8.x, al8.y, al8.z, al8.w, bh0, bh1);
        }
    }

    {
        int m0 = wid*16 + gid;
        float bias0 = __ldg(&e_b2[m0]), bias1 = __ldg(&e_b2[m0 + 8]);
        float* p0 = g_wpre + (size_t)(b*144 + m0)*HW + hw0 + tig*2;
        float* p1 = p0 + (size_t)8*HW;
#pragma unroll
        for (int nt = 0; nt < 16; nt++) {
            *(float2*)(p0 + nt*8) = make_float2(acc2[nt][0] + bias0, acc2[nt][1] + bias0);
            *(float2*)(p1 + nt*8) = make_float2(acc2[nt][2] + bias1, acc2[nt][3] + bias1);
        }
        int m8 = 128 + gid;
        float bias2 = __ldg(&e_b2[m8]), bias3 = __ldg(&e_b2[m8 + 8]);
        float* q0 = g_wpre + (size_t)(b*144 + m8)*HW + hw0 + tig*2;
        float* q1 = q0 + (size_t)8*HW;
#pragma unroll
        for (int j = 0; j < 2; j++) {
            int nt = wid*2 + j;
            *(float2*)(q0 + nt*8) = make_float2(acc3[j][0] + bias2, acc3[j][1] + bias2);
            *(float2*)(q1 + nt*8) = make_float2(acc3[j][2] + bias3, acc3[j][3] + bias3);
        }
    }
}

// ---------------- K4: GroupNorm stats ----------------
__global__ void k4_gn() {
    __shared__ float rs[256], rq[256];
    int bg = blockIdx.x;
    int b = bg >> 4, g = bg & 15;
    const float* base = g_wpre + (size_t)(b*144 + g*9) * HW;
    float s = 0.f, q = 0.f;
    for (int idx = threadIdx.x; idx < 9*HW; idx += 256) {
        float v = base[idx]; s += v; q += v*v;
    }
    rs[threadIdx.x] = s; rq[threadIdx.x] = q;
    __syncthreads();
    for (int o = 128; o > 0; o >>= 1) {
        if (threadIdx.x < o) { rs[threadIdx.x] += rs[threadIdx.x+o]; rq[threadIdx.x] += rq[threadIdx.x+o]; }
        __syncthreads();
    }
    if (threadIdx.x == 0) {
        float inv = 1.f / (9.f*HW);
        float mean = rs[0] * inv;
        float var  = rq[0] * inv - mean*mean;
        g_gn[bg*2]     = mean;
        g_gn[bg*2 + 1] = rsqrtf(var + 1e-5f);
    }
}

// ---------------- K5: local dynamic conv + BN partials ----------------
__global__ void __launch_bounds__(96) k5_local(const float* __restrict__ gn_g,
                                               const float* __restrict__ gn_b) {
    __shared__ float wn[9 * 96];
    __shared__ float vs[8 * 294];
    __shared__ float red[48];
    int h = blockIdx.x, g = blockIdx.y, b = blockIdx.z;
    int w = threadIdx.x;
    float mean = g_gn[(b*16 + g)*2], rstd = g_gn[(b*16 + g)*2 + 1];
#pragma unroll
    for (int t = 0; t < 9; t++) {
        int ch = g*9 + t;
        float raw = g_wpre[(size_t)(b*144 + ch)*HW + h*96 + w];
        wn[t*96 + w] = (raw - mean) * rstd * __ldg(&gn_g[ch]) + __ldg(&gn_b[ch]);
    }
    for (int idx = w; idx < 8*294; idx += 96) {
        int s = idx / 294, rem = idx % 294, r = rem / 98, col = rem % 98;
        int hh = h + r - 1, wc = col - 1;
        float v = 0.f;
        if ((unsigned)hh < 96u && (unsigned)wc < 96u)
            v = g_v[(size_t)(b*128 + g*8 + s)*HW + hh*96 + wc];
        vs[idx] = v;
    }
    __syncthreads();
    int lane = w & 31, warp = w >> 5;
#pragma unroll
    for (int s = 0; s < 8; s++) {
        float acc = 0.f;
        const float* vb = vs + s*294;
#pragma unroll
        for (int r = 0; r < 3; r++)
#pragma unroll
            for (int c = 0; c < 3; c++)
                acc += vb[r*98 + w + c] * wn[(r*3 + c)*96 + w];
        g_ypre[(size_t)(b*128 + g*8 + s)*HW + h*96 + w] = acc;
        float v1 = acc, v2 = acc*acc;
        for (int off = 16; off; off >>= 1) {
            v1 += __shfl_down_sync(0xffffffffu, v1, off);
            v2 += __shfl_down_sync(0xffffffffu, v2, off);
        }
        if (lane == 0) { red[warp*8 + s] = v1; red[24 + warp*8 + s] = v2; }
    }
    __syncthreads();
    if (w < 8) {
        float s1 = red[w] + red[8 + w] + red[16 + w];
        float s2 = red[24 + w] + red[32 + w] + red[40 + w];
        int c = g*8 + w;
        g_bnS[c*768 + b*96 + h] = s1;
        g_bnQ[c*768 + b*96 + h] = s2;
    }
}

// ---------------- K6: BN finalize ----------------
__global__ void k6_bn() {
    __shared__ float rs[256], rq[256];
    int c = blockIdx.x;
    float s = 0.f, q = 0.f;
    for (int idx = threadIdx.x; idx < 768; idx += 256) {
        s += g_bnS[c*768 + idx]; q += g_bnQ[c*768 + idx];
    }
    rs[threadIdx.x] = s; rq[threadIdx.x] = q;
    __syncthreads();
    for (int o = 128; o > 0; o >>= 1) {
        if (threadIdx.x < o) { rs[threadIdx.x] += rs[threadIdx.x+o]; rq[threadIdx.x] += rq[threadIdx.x+o]; }
        __syncthreads();
    }
    if (threadIdx.x == 0) {
        float inv = 1.f / (float)PTOT;
        float mean = rs[0] * inv;
        float var  = rq[0] * inv - mean*mean;
        g_bn[c*2]     = mean;
        g_bn[c*2 + 1] = rsqrtf(var + 1e-5f);
    }
}

// ---------------- K7: BN apply + swish + GAP partials ----------------
__global__ void k7_swish(const float* __restrict__ bn_g, const float* __restrict__ bn_b) {
    __shared__ float rs[256];
    int c = blockIdx.x, b = blockIdx.y;
    float mean = g_bn[c*2], rstd = g_bn[c*2 + 1];
    float gg = __ldg(&bn_g[c]), bb = __ldg(&bn_b[c]);
    const float* yb = g_ypre + (size_t)(b*128 + c)*HW;
    const float* kb = g_k    + (size_t)(b*128 + c)*HW;
    float*       yo = g_y    + (size_t)(b*128 + c)*HW;
    float s = 0.f;
    for (int idx = threadIdx.x; idx < HW; idx += 256) {
        float t = (yb[idx] - mean) * rstd * gg + bb;
        float y = t * __frcp_rn(1.f + __expf(-t));
        yo[idx] = y;
        s += y + kb[idx];
    }
    rs[threadIdx.x] = s;
    __syncthreads();
    for (int o = 128; o > 0; o >>= 1) {
        if (threadIdx.x < o) rs[threadIdx.x] += rs[threadIdx.x + o];
        __syncthreads();
    }
    if (threadIdx.x == 0) g_gap[b*128 + c] = rs[0] * (1.f / (float)HW);
}

// ---------------- K8: SE MLP + radix softmax ----------------
__global__ void k8_se(const float* __restrict__ w1, const float* __restrict__ b1,
                      const float* __restrict__ w2, const float* __restrict__ b2) {
    __shared__ float gaps[128], a1s[64], a2s[256];
    int b = blockIdx.x, tid = threadIdx.x;
    if (tid < 128) gaps[tid] = g_gap[b*128 + tid];
    __syncthreads();
    if (tid < 64) {
        float s = __ldg(&b1[tid]);
        for (int c = 0; c < 128; c++) s += __ldg(&w1[tid*128 + c]) * gaps[c];
        a1s[tid] = fmaxf(s, 0.f);
    }
    __syncthreads();
    {
        float s = __ldg(&b2[tid]);
        for (int j = 0; j < 64; j++) s += __ldg(&w2[tid*64 + j]) * a1s[j];
        a2s[tid] = s;
    }
    __syncthreads();
    if (tid < 128) {
        float e0 = a2s[tid*2], e1 = a2s[tid*2 + 1];
        float m = fmaxf(e0, e1);
        float p0 = expf(e0 - m), p1 = expf(e1 - m);
        float d = p0 + p1;
        g_a[(b*128 + tid)*2]     = p0 / d;
        g_a[(b*128 + tid)*2 + 1] = p1 / d;
    }
}

// ---------------- K9: final mix ----------------
__global__ void k9_out(float* __restrict__ out) {
    int idx = blockIdx.x * 256 + threadIdx.x;
    const float4 y = ((const float4*)g_y)[idx];
    const float4 k = ((const float4*)g_k)[idx];
    int bc = idx / 2304;
    float a0 = g_a[bc*2], a1 = g_a[bc*2 + 1];
    ((float4*)out)[idx] = make_float4(y.x*a0 + k.x*a1, y.y*a0 + k.y*a1,
                                      y.z*a0 + k.z*a1, y.w*a0 + k.w*a1);
}

// ---------------- launch ----------------
extern "C" void kernel_launch(void* const* d_in, const int* in_sizes, int n_in,
                              void* d_out, int out_size) {
    const float* x     = (const float*)d_in[0];
    const float* key_w = (const float*)d_in[1];
    const float* e_w1  = (const float*)d_in[2];
    const float* e_w2  = (const float*)d_in[3];
    const float* e_b2  = (const float*)d_in[4];
    const float* gn_g  = (const float*)d_in[5];
    const float* gn_b  = (const float*)d_in[6];
    const float* c1_w  = (const float*)d_in[7];
    const float* bn_g  = (const float*)d_in[8];
    const float* bn_b  = (const float*)d_in[9];
    const float* se_w1 = (const float*)d_in[10];
    const float* se_b1 = (const float*)d_in[11];
    const float* se_w2 = (const float*)d_in[12];
    const float* se_b2 = (const float*)d_in[13];
    float* out = (float*)d_out;

    cudaFuncSetAttribute(k2_mma, cudaFuncAttributeMaxDynamicSharedMemorySize, K2_SMEM);

    k0_prep <<<72, 256>>>(e_w1, c1_w, e_w2, key_w);
    k1_mma  <<<dim3(96, 4, 8), 384>>>(x);
    k2_mma  <<<PTOT/128, 256, K2_SMEM>>>(x, e_b2);
    k4_gn   <<<128, 256>>>();
    k5_local<<<dim3(96, 16, 8), 96>>>(gn_g, gn_b);
    k6_bn   <<<128, 256>>>();
    k7_swish<<<dim3(128, 8), 256>>>(bn_g, bn_b);
    k8_se   <<<8, 256>>>(se_w1, se_b1, se_w2, se_b2);
    k9_out  <<<PTOT*128/(256*4), 256>>>(out);
}

// round 9
// speedup vs baseline: 1.7084x; 1.0323x over previous
#include <cuda_runtime.h>
#include <cuda_bf16.h>
#include <math.h>
#include <stdint.h>

#define BB 8
#define CC 128
#define HH 96
#define WW 96
#define HW 9216            // 96*96
#define WC 144             // k*k*DIM/SP
#define PTOT (BB*HW)       // 73728

typedef unsigned long long u64;
typedef unsigned int u32;

__device__ __forceinline__ unsigned short f2bf(float f) {
    return __bfloat16_as_ushort(__float2bfloat16(f));
}
__device__ __forceinline__ float bf2f(unsigned short u) {
    return __bfloat162float(__ushort_as_bfloat16(u));
}
__device__ __forceinline__ u32 packbf(float a, float b) {
    return (u32)f2bf(a) | ((u32)f2bf(b) << 16);
}

// m16n8k16 bf16 MMA, fp32 accumulate
__device__ __forceinline__ void mma_bf16(float* c, u32 a0, u32 a1, u32 a2, u32 a3,
                                         u32 b0, u32 b1) {
    asm volatile(
        "mma.sync.aligned.m16n8k16.row.col.f32.bf16.bf16.f32 "
        "{%0,%1,%2,%3}, {%4,%5,%6,%7}, {%8,%9}, {%0,%1,%2,%3};"
        : "+f"(c[0]), "+f"(c[1]), "+f"(c[2]), "+f"(c[3])
        : "r"(a0), "r"(a1), "r"(a2), "r"(a3), "r"(b0), "r"(b1));
}

// ---------------- scratch ----------------
__device__ float g_k   [BB*CC*HW];
__device__ float g_v   [BB*CC*HW];
__device__ float g_wpre[BB*WC*HW];
__device__ float g_ypre[BB*CC*HW];
// A-fragment images (bf16 hi/lo) — static weights, built once in k0
__device__ __align__(16) u32 g_Afh [8192];    // c1_w:  [mt8][ks8][lane32][4]
__device__ __align__(16) u32 g_Afl [8192];
__device__ __align__(16) u32 g_W1fh[8192];    // e_w1:  [mt4][ks16][lane32][4]
__device__ __align__(16) u32 g_W1fl[8192];
__device__ __align__(16) u32 g_W2fh[4608];    // e_w2:  [mt9][ks4][lane32][4]
__device__ __align__(16) u32 g_W2fl[4608];
__device__ __align__(16) u32 g_KWfh[18432];   // key_w: [g4][mt2][ks18][lane32][4], k = tap*32+ci
__device__ __align__(16) u32 g_KWfl[18432];
__device__ float g_gnP [1024*2];   // GN partials
__device__ float g_gn  [128*2];
__device__ float g_bnS [128*96];   // per channel, per (b*12+hblk)
__device__ float g_bnQ [128*96];
__device__ float g_bn  [128*2];
__device__ float g_gap [BB*CC];
__device__ float g_a   [BB*CC*2];

// ---------------- K0: weight prep (A-fragment images) ----------------
__global__ void k0_prep(const float* __restrict__ e_w1, const float* __restrict__ c1_w,
                        const float* __restrict__ e_w2, const float* __restrict__ key_w) {
    int idx = blockIdx.x * 256 + threadIdx.x;   // 0..18431
    int r = idx & 3, lane = (idx >> 2) & 31;
    int gid = lane >> 2, tig = lane & 3;
    int dr = (r & 1) * 8, dc = (r & 2) * 4;
    if (idx < 8192) {   // c1_w [128,128]: mt8, ks8
        int ks = (idx >> 7) & 7, mt = idx >> 10;
        int row = mt*16 + gid + dr, col = ks*16 + tig*2 + dc;
        float w0 = c1_w[row*128 + col], w1 = c1_w[row*128 + col + 1];
        g_Afh[idx] = packbf(w0, w1);
        g_Afl[idx] = packbf(w0 - bf2f(f2bf(w0)), w1 - bf2f(f2bf(w1)));
    }
    if (idx < 8192) {   // e_w1 [64,256]: mt4, ks16
        int ks = (idx >> 7) & 15, mt = idx >> 11;
        int row = mt*16 + gid + dr, col = ks*16 + tig*2 + dc;
        float w0 = e_w1[row*256 + col], w1 = e_w1[row*256 + col + 1];
        g_W1fh[idx] = packbf(w0, w1);
        g_W1fl[idx] = packbf(w0 - bf2f(f2bf(w0)), w1 - bf2f(f2bf(w1)));
    }
    if (idx < 4608) {   // e_w2 [144,64]: mt9, ks4
        int ks = (idx >> 7) & 3, mt = idx >> 9;
        int row = mt*16 + gid + dr, col = ks*16 + tig*2 + dc;
        float w0 = e_w2[row*64 + col], w1 = e_w2[row*64 + col + 1];
        g_W2fh[idx] = packbf(w0, w1);
        g_W2fl[idx] = packbf(w0 - bf2f(f2bf(w0)), w1 - bf2f(f2bf(w1)));
    }
    {   // key_w grouped: [g4][mt2][ks18][lane32][4], k = tap*32 + ci
        int idx2 = idx >> 7;
        int ks = idx2 % 18, gmt = idx2 / 18;
        int mt = gmt & 1, gg = gmt >> 1;
        int row = mt*16 + gid + dr;
        int colk = ks*16 + tig*2 + dc;
        int t = colk >> 5, ci = colk & 31;
        const float* wb = key_w + ((size_t)(gg*32 + row)*32 + ci)*9 + t;
        float w0 = wb[0], w1 = wb[9];
        g_KWfh[idx] = packbf(w0, w1);
        g_KWfl[idx] = packbf(w0 - bf2f(f2bf(w0)), w1 - bf2f(f2bf(w1)));
    }
}

// ---------------- K1: grouped 3x3 conv + ReLU via warp MMA ----------------
__global__ void __launch_bounds__(384) k1_mma(const float* __restrict__ x) {
    __shared__ float xs[32 * 294];
    int h = blockIdx.x, g = blockIdx.y, b = blockIdx.z;
    int tid = threadIdx.x, wid = tid >> 5, lane = tid & 31;
    for (int idx = tid; idx < 32 * 294; idx += 384) {
        int ci = idx / 294, rem = idx % 294, r = rem / 98, col = rem % 98;
        int hh = h + r - 1, wc = col - 1;
        float v = 0.f;
        if ((unsigned)hh < 96u && (unsigned)wc < 96u)
            v = x[(b*128 + g*32 + ci) * HW + hh*96 + wc];
        xs[idx] = v;
    }
    __syncthreads();

    int gid = lane >> 2, tig = lane & 3;
    int nbase = wid*8 + gid;
    float acc0[4] = {0.f,0.f,0.f,0.f};
    float acc1[4] = {0.f,0.f,0.f,0.f};
    const uint4* AH = (const uint4*)g_KWfh + (size_t)g*2*18*32;
    const uint4* AL = (const uint4*)g_KWfl + (size_t)g*2*18*32;

#pragma unroll
    for (int ks = 0; ks < 18; ks++) {
        const int t = ks >> 1, cib = (ks & 1) * 16;
        const int r = t / 3, c = t - 3*r;
        int ci0 = cib + tig*2;
        const float* base = xs + r*98 + nbase + c;
        float v0 = base[ ci0      *294];
        float v1 = base[(ci0 + 1) *294];
        float v2 = base[(ci0 + 8) *294];
        float v3 = base[(ci0 + 9) *294];
        u32 bh0 = packbf(v0, v1), bh1 = packbf(v2, v3);
        u32 bl0 = packbf(v0 - bf2f(f2bf(v0)), v1 - bf2f(f2bf(v1)));
        u32 bl1 = packbf(v2 - bf2f(f2bf(v2)), v3 - bf2f(f2bf(v3)));
        uint4 ah0 = AH[(0*18 + ks)*32 + lane];
        uint4 al0 = AL[(0*18 + ks)*32 + lane];
        uint4 ah1 = AH[(1*18 + ks)*32 + lane];
        uint4 al1 = AL[(1*18 + ks)*32 + lane];
        mma_bf16(acc0, ah0.x, ah0.y, ah0.z, ah0.w, bh0, bh1);
        mma_bf16(acc0, ah0.x, ah0.y, ah0.z, ah0.w, bl0, bl1);
        mma_bf16(acc0, al0.x, al0.y, al0.z, al0.w, bh0, bh1);
        mma_bf16(acc1, ah1.x, ah1.y, ah1.z, ah1.w, bh0, bh1);
        mma_bf16(acc1, ah1.x, ah1.y, ah1.z, ah1.w, bl0, bl1);
        mma_bf16(acc1, al1.x, al1.y, al1.z, al1.w, bh0, bh1);
    }

    int n0 = wid*8 + tig*2;
    {
        int co = g*32 + gid;
        float* p = g_k + (size_t)(b*128 + co)*HW + h*96 + n0;
        *(float2*)p            = make_float2(fmaxf(acc0[0],0.f), fmaxf(acc0[1],0.f));
        *(float2*)(p + 8*HW)   = make_float2(fmaxf(acc0[2],0.f), fmaxf(acc0[3],0.f));
        float* q = p + 16*HW;
        *(float2*)q            = make_float2(fmaxf(acc1[0],0.f), fmaxf(acc1[1],0.f));
        *(float2*)(q + 8*HW)   = make_float2(fmaxf(acc1[2],0.f), fmaxf(acc1[3],0.f));
    }
}

// ---------------- K2: fused embed GEMMs + value GEMM via warp MMA ----------------
#define K2_SMEM (33280 + 32768)
__global__ void __launch_bounds__(256) k2_mma(const float* __restrict__ x,
                                              const float* __restrict__ e_b2) {
    extern __shared__ float sm[];
    float* xs = sm;
    u32* bh = (u32*)(sm + 8320);
    u32* bl = bh + 4096;
    int tid = threadIdx.x, wid = tid >> 5, lane = tid & 31;
    int gid = lane >> 2, tig = lane & 3;
    int pb = blockIdx.x * 128, b = pb / HW, hw0 = pb % HW;
    const float* xb = x   + (size_t)b*128*HW + hw0;
    const float* kb = g_k + (size_t)b*128*HW + hw0;

    int mt1 = wid & 3, ng = wid >> 2;
    float acc[8][4];
#pragma unroll
    for (int i = 0; i < 8; i++)
#pragma unroll
        for (int j = 0; j < 4; j++) acc[i][j] = 0.f;

    {
        float accv[16][4];
#pragma unroll
        for (int i = 0; i < 16; i++)
#pragma unroll
            for (int j = 0; j < 4; j++) accv[i][j] = 0.f;

        for (int kc = 0; kc < 2; kc++) {
            const float* src = xb + (size_t)kc*64*HW;
            for (int i = tid; i < 64*64; i += 256) {
                int k = i >> 6, n = (i & 63) * 2;
                float2 v = *(const float2*)(src + (size_t)k*HW + n);
                xs[k*130 + n] = v.x; xs[k*130 + n + 1] = v.y;
            }
            __syncthreads();
            for (int i = tid; i < 2048; i += 256) {
                int l2 = i & 31, nt = (i >> 5) & 15, ks = i >> 9;
                int g2 = l2 >> 2, t2 = l2 & 3;
                int n = nt*8 + g2, k = ks*16 + t2*2;
                float f0 = xs[k*130 + n],     f1 = xs[(k+1)*130 + n];
                float f2 = xs[(k+8)*130 + n], f3 = xs[(k+9)*130 + n];
                int base = i * 2;
                bh[base]     = packbf(f0, f1);
                bh[base + 1] = packbf(f2, f3);
                bl[base]     = packbf(f0 - bf2f(f2bf(f0)), f1 - bf2f(f2bf(f1)));
                bl[base + 1] = packbf(f2 - bf2f(f2bf(f2)), f3 - bf2f(f2bf(f3)));
            }
            __syncthreads();
#pragma unroll
            for (int ks = 0; ks < 4; ks++) {
                int gks = kc*4 + ks;
                uint4 ah = ((const uint4*)g_W1fh)[(mt1*16 + gks)*32 + lane];
                uint4 al = ((const uint4*)g_W1fl)[(mt1*16 + gks)*32 + lane];
#pragma unroll
                for (int nt2 = 0; nt2 < 8; nt2++) {
                    int nt = ng*8 + nt2;
                    int base = ((ks*16 + nt)*32 + lane) * 2;
                    u32 bh0 = bh[base], bh1 = bh[base + 1];
                    u32 bl0 = bl[base], bl1 = bl[base + 1];
                    mma_bf16(acc[nt2], ah.x, ah.y, ah.z, ah.w, bh0, bh1);
                    mma_bf16(acc[nt2], ah.x, ah.y, ah.z, ah.w, bl0, bl1);
                    mma_bf16(acc[nt2], al.x, al.y, al.z, al.w, bh0, bh1);
                }
                uint4 vh = ((const uint4*)g_Afh)[(wid*8 + gks)*32 + lane];
                uint4 vl = ((const uint4*)g_Afl)[(wid*8 + gks)*32 + lane];
#pragma unroll
                for (int nt = 0; nt < 16; nt++) {
                    int base = ((ks*16 + nt)*32 + lane) * 2;
                    u32 bh0 = bh[base], bh1 = bh[base + 1];
                    u32 bl0 = bl[base], bl1 = bl[base + 1];
                    mma_bf16(accv[nt], vh.x, vh.y, vh.z, vh.w, bh0, bh1);
                    mma_bf16(accv[nt], vh.x, vh.y, vh.z, vh.w, bl0, bl1);
                    mma_bf16(accv[nt], vl.x, vl.y, vl.z, vl.w, bh0, bh1);
                }
            }
            __syncthreads();
        }
        int m0 = wid*16 + gid;
        float* vb0 = g_v + (size_t)(b*128 + m0)*HW + hw0 + tig*2;
        float* vb1 = vb0 + (size_t)8*HW;
#pragma unroll
        for (int nt = 0; nt < 16; nt++) {
            *(float2*)(vb0 + nt*8) = make_float2(accv[nt][0], accv[nt][1]);
            *(float2*)(vb1 + nt*8) = make_float2(accv[nt][2], accv[nt][3]);
        }
    }

    for (int kc = 2; kc < 4; kc++) {
        const float* src = kb + (size_t)(kc-2)*64*HW;
        for (int i = tid; i < 64*64; i += 256) {
            int k = i >> 6, n = (i & 63) * 2;
            float2 v = *(const float2*)(src + (size_t)k*HW + n);
            xs[k*130 + n] = v.x; xs[k*130 + n + 1] = v.y;
        }
        __syncthreads();
        for (int i = tid; i < 2048; i += 256) {
            int l2 = i & 31, nt = (i >> 5) & 15, ks = i >> 9;
            int g2 = l2 >> 2, t2 = l2 & 3;
            int n = nt*8 + g2, k = ks*16 + t2*2;
            float f0 = xs[k*130 + n],     f1 = xs[(k+1)*130 + n];
            float f2 = xs[(k+8)*130 + n], f3 = xs[(k+9)*130 + n];
            int base = i * 2;
            bh[base]     = packbf(f0, f1);
            bh[base + 1] = packbf(f2, f3);
            bl[base]     = packbf(f0 - bf2f(f2bf(f0)), f1 - bf2f(f2bf(f1)));
            bl[base + 1] = packbf(f2 - bf2f(f2bf(f2)), f3 - bf2f(f2bf(f3)));
        }
        __syncthreads();
#pragma unroll
        for (int ks = 0; ks < 4; ks++) {
            int gks = kc*4 + ks;
            uint4 ah = ((const uint4*)g_W1fh)[(mt1*16 + gks)*32 + lane];
            uint4 al = ((const uint4*)g_W1fl)[(mt1*16 + gks)*32 + lane];
#pragma unroll
            for (int nt2 = 0; nt2 < 8; nt2++) {
                int nt = ng*8 + nt2;
                int base = ((ks*16 + nt)*32 + lane) * 2;
                u32 bh0 = bh[base], bh1 = bh[base + 1];
                u32 bl0 = bl[base], bl1 = bl[base + 1];
                mma_bf16(acc[nt2], ah.x, ah.y, ah.z, ah.w, bh0, bh1);
                mma_bf16(acc[nt2], ah.x, ah.y, ah.z, ah.w, bl0, bl1);
                mma_bf16(acc[nt2], al.x, al.y, al.z, al.w, bh0, bh1);
            }
        }
        __syncthreads();
    }

#pragma unroll
    for (int nt2 = 0; nt2 < 8; nt2++) {
        int n0 = (ng*8 + nt2)*8 + tig*2;
        int r0 = mt1*16 + gid;
        xs[r0*130 + n0]       = fmaxf(acc[nt2][0], 0.f);
        xs[r0*130 + n0 + 1]   = fmaxf(acc[nt2][1], 0.f);
        xs[(r0+8)*130 + n0]   = fmaxf(acc[nt2][2], 0.f);
        xs[(r0+8)*130 + n0+1] = fmaxf(acc[nt2][3], 0.f);
    }
    __syncthreads();

    for (int i = tid; i < 2048; i += 256) {
        int l2 = i & 31, nt = (i >> 5) & 15, ks = i >> 9;
        int g2 = l2 >> 2, t2 = l2 & 3;
        int n = nt*8 + g2, k = ks*16 + t2*2;
        float f0 = xs[k*130 + n],     f1 = xs[(k+1)*130 + n];
        float f2 = xs[(k+8)*130 + n], f3 = xs[(k+9)*130 + n];
        int base = i * 2;
        bh[base]     = packbf(f0, f1);
        bh[base + 1] = packbf(f2, f3);
        bl[base]     = packbf(f0 - bf2f(f2bf(f0)), f1 - bf2f(f2bf(f1)));
        bl[base + 1] = packbf(f2 - bf2f(f2bf(f2)), f3 - bf2f(f2bf(f3)));
    }
    __syncthreads();

    float acc2[16][4];
    float acc3[2][4];
#pragma unroll
    for (int i = 0; i < 16; i++)
#pragma unroll
        for (int j = 0; j < 4; j++) acc2[i][j] = 0.f;
#pragma unroll
    for (int i = 0; i < 2; i++)
#pragma unroll
        for (int j = 0; j < 4; j++) acc3[i][j] = 0.f;

#pragma unroll
    for (int ks = 0; ks < 4; ks++) {
        uint4 ah  = ((const uint4*)g_W2fh)[(wid*4 + ks)*32 + lane];
        uint4 al  = ((const uint4*)g_W2fl)[(wid*4 + ks)*32 + lane];
        uint4 ah8 = ((const uint4*)g_W2fh)[(8*4 + ks)*32 + lane];
        uint4 al8 = ((const uint4*)g_W2fl)[(8*4 + ks)*32 + lane];
#pragma unroll
        for (int nt = 0; nt < 16; nt++) {
            int base = ((ks*16 + nt)*32 + lane) * 2;
            u32 bh0 = bh[base], bh1 = bh[base + 1];
            u32 bl0 = bl[base], bl1 = bl[base + 1];
            mma_bf16(acc2[nt], ah.x, ah.y, ah.z, ah.w, bh0, bh1);
            mma_bf16(acc2[nt], ah.x, ah.y, ah.z, ah.w, bl0, bl1);
            mma_bf16(acc2[nt], al.x, al.y, al.z, al.w, bh0, bh1);
        }
#pragma unroll
        for (int j = 0; j < 2; j++) {
            int nt = wid*2 + j;
            int base = ((ks*16 + nt)*32 + lane) * 2;
            u32 bh0 = bh[base], bh1 = bh[base + 1];
            u32 bl0 = bl[base], bl1 = bl[base + 1];
            mma_bf16(acc3[j], ah8.x, ah8.y, ah8.z, ah8.w, bh0, bh1);
            mma_bf16(acc3[j], ah8.x, ah8.y, ah8.z, ah8.w, bl0, bl1);
            mma_bf16(acc3[j], al8.x, al8.y, al8.z, al8.w, bh0, bh1);
        }
    }

    {
        int m0 = wid*16 + gid;
        float bias0 = __ldg(&e_b2[m0]), bias1 = __ldg(&e_b2[m0 + 8]);
        float* p0 = g_wpre + (size_t)(b*144 + m0)*HW + hw0 + tig*2;
        float* p1 = p0 + (size_t)8*HW;
#pragma unroll
        for (int nt = 0; nt < 16; nt++) {
            *(float2*)(p0 + nt*8) = make_float2(acc2[nt][0] + bias0, acc2[nt][1] + bias0);
            *(float2*)(p1 + nt*8) = make_float2(acc2[nt][2] + bias1, acc2[nt][3] + bias1);
        }
        int m8 = 128 + gid;
        float bias2 = __ldg(&e_b2[m8]), bias3 = __ldg(&e_b2[m8 + 8]);
        float* q0 = g_wpre + (size_t)(b*144 + m8)*HW + hw0 + tig*2;
        float* q1 = q0 + (size_t)8*HW;
#pragma unroll
        for (int j = 0; j < 2; j++) {
            int nt = wid*2 + j;
            *(float2*)(q0 + nt*8) = make_float2(acc3[j][0] + bias2, acc3[j][1] + bias2);
            *(float2*)(q1 + nt*8) = make_float2(acc3[j][2] + bias3, acc3[j][3] + bias3);
        }
    }
}

// ---------------- K4a: GroupNorm partial sums (1024 blocks) ----------------
__global__ void k4a_gn() {
    __shared__ float rs[256], rq[256];
    int bg = blockIdx.x >> 3, s = blockIdx.x & 7;
    int b = bg >> 4, g = bg & 15;
    const float* base = g_wpre + (size_t)(b*144 + g*9) * HW + s * 10368;
    float sm = 0.f, q = 0.f;
    for (int idx = threadIdx.x; idx < 10368; idx += 256) {
        float v = base[idx]; sm += v; q += v*v;
    }
    rs[threadIdx.x] = sm; rq[threadIdx.x] = q;
    __syncthreads();
    for (int o = 128; o > 0; o >>= 1) {
        if (threadIdx.x < o) { rs[threadIdx.x] += rs[threadIdx.x+o]; rq[threadIdx.x] += rq[threadIdx.x+o]; }
        __syncthreads();
    }
    if (threadIdx.x == 0) {
        g_gnP[blockIdx.x*2]     = rs[0];
        g_gnP[blockIdx.x*2 + 1] = rq[0];
    }
}
// ---------------- K4b: GN finalize ----------------
__global__ void k4b_gn() {
    int bg = threadIdx.x;   // 0..127
    float s = 0.f, q = 0.f;
#pragma unroll
    for (int i = 0; i < 8; i++) {
        s += g_gnP[(bg*8 + i)*2];
        q += g_gnP[(bg*8 + i)*2 + 1];
    }
    float inv = 1.f / (9.f*HW);
    float mean = s * inv;
    float var  = q * inv - mean*mean;
    g_gn[bg*2]     = mean;
    g_gn[bg*2 + 1] = rsqrtf(var + 1e-5f);
}

// ---------------- K5: local dynamic conv + BN partials (8 rows/block) ----------------
// block = (hblk 0..11, g, b); 384 threads; dynamic smem: wn[9][8][96], vs[8][10][98], red[192]
#define K5_SMEM ((6912 + 7840 + 192) * 4)
__global__ void __launch_bounds__(384) k5_local(const float* __restrict__ gn_g,
                                                const float* __restrict__ gn_b) {
    extern __shared__ float sm5[];
    float* wn  = sm5;            // 9*8*96 = 6912
    float* vs  = sm5 + 6912;     // 8*10*98 = 7840
    float* red = sm5 + 6912 + 7840;
    int h0 = blockIdx.x * 8, g = blockIdx.y, b = blockIdx.z;
    int tid = threadIdx.x;
    float mean = g_gn[(b*16 + g)*2], rstd = g_gn[(b*16 + g)*2 + 1];

    for (int idx = tid; idx < 6912; idx += 384) {
        int t = idx / 768, rem = idx % 768;          // rem = r*96 + w
        int ch = g*9 + t;
        float raw = g_wpre[(size_t)(b*144 + ch)*HW + h0*96 + rem];
        wn[idx] = (raw - mean) * rstd * __ldg(&gn_g[ch]) + __ldg(&gn_b[ch]);
    }
    for (int idx = tid; idx < 7840; idx += 384) {
        int s = idx / 980, rem = idx % 980, r = rem / 98, col = rem % 98;
        int hh = h0 + r - 1, wc = col - 1;
        float v = 0.f;
        if ((unsigned)hh < 96u && (unsigned)wc < 96u)
            v = g_v[(size_t)(b*128 + g*8 + s)*HW + hh*96 + wc];
        vs[idx] = v;
    }
    __syncthreads();

    int w = tid % 96, rq = tid / 96;   // rq 0..3, rows rq*2, rq*2+1
    int lane = tid & 31, warp = tid >> 5;
#pragma unroll
    for (int s = 0; s < 8; s++) {
        float p1 = 0.f, p2 = 0.f;
        const float* vb = vs + s*980;
#pragma unroll
        for (int rr = 0; rr < 2; rr++) {
            int row = rq*2 + rr;
            float acc = 0.f;
#pragma unroll
            for (int dr = 0; dr < 3; dr++)
#pragma unroll
                for (int dc = 0; dc < 3; dc++)
                    acc += vb[(row+dr)*98 + w + dc] * wn[(dr*3+dc)*768 + row*96 + w];
            g_ypre[(size_t)(b*128 + g*8 + s)*HW + (h0+row)*96 + w] = acc;
            p1 += acc; p2 += acc*acc;
        }
        for (int off = 16; off; off >>= 1) {
            p1 += __shfl_down_sync(0xffffffffu, p1, off);
            p2 += __shfl_down_sync(0xffffffffu, p2, off);
        }
        if (lane == 0) { red[warp*16 + s*2] = p1; red[warp*16 + s*2 + 1] = p2; }
    }
    __syncthreads();
    if (tid < 8) {
        float s1 = 0.f, s2 = 0.f;
#pragma unroll
        for (int wp = 0; wp < 12; wp++) {
            s1 += red[wp*16 + tid*2];
            s2 += red[wp*16 + tid*2 + 1];
        }
        int c = g*8 + tid;
        g_bnS[c*96 + b*12 + blockIdx.x] = s1;
        g_bnQ[c*96 + b*12 + blockIdx.x] = s2;
    }
}

// ---------------- K6: BN finalize ----------------
__global__ void k6_bn() {
    __shared__ float rs[96], rq[96];
    int c = blockIdx.x, tid = threadIdx.x;
    if (tid < 96) { rs[tid] = g_bnS[c*96 + tid]; rq[tid] = g_bnQ[c*96 + tid]; }
    __syncthreads();
    if (tid < 32) {
        float s = rs[tid] + rs[tid+32] + rs[tid+64];
        float q = rq[tid] + rq[tid+32] + rq[tid+64];
        for (int off = 16; off; off >>= 1) {
            s += __shfl_down_sync(0xffffffffu, s, off);
            q += __shfl_down_sync(0xffffffffu, q, off);
        }
        if (tid == 0) {
            float inv = 1.f / (float)PTOT;
            float mean = s * inv;
            float var  = q * inv - mean*mean;
            g_bn[c*2]     = mean;
            g_bn[c*2 + 1] = rsqrtf(var + 1e-5f);
        }
    }
}

// ---------------- K7: GAP partials (swish computed on the fly, no y store) ----------------
__global__ void k7_gap(const float* __restrict__ bn_g, const float* __restrict__ bn_b) {
    __shared__ float rs[256];
    int c = blockIdx.x, b = blockIdx.y;
    float mean = g_bn[c*2], rstd = g_bn[c*2 + 1];
    float gg = __ldg(&bn_g[c]), bb = __ldg(&bn_b[c]);
    const float* yb = g_ypre + (size_t)(b*128 + c)*HW;
    const float* kb = g_k    + (size_t)(b*128 + c)*HW;
    float s = 0.f;
    for (int idx = threadIdx.x; idx < HW; idx += 256) {
        float t = (yb[idx] - mean) * rstd * gg + bb;
        float y = t * __frcp_rn(1.f + __expf(-t));
        s += y + kb[idx];
    }
    rs[threadIdx.x] = s;
    __syncthreads();
    for (int o = 128; o > 0; o >>= 1) {
        if (threadIdx.x < o) rs[threadIdx.x] += rs[threadIdx.x + o];
        __syncthreads();
    }
    if (threadIdx.x == 0) g_gap[b*128 + c] = rs[0] * (1.f / (float)HW);
}

// ---------------- K8: SE MLP + radix softmax ----------------
__global__ void k8_se(const float* __restrict__ w1, const float* __restrict__ b1,
                      const float* __restrict__ w2, const float* __restrict__ b2) {
    __shared__ float gaps[128], a1s[64], a2s[256];
    int b = blockIdx.x, tid = threadIdx.x;
    if (tid < 128) gaps[tid] = g_gap[b*128 + tid];
    __syncthreads();
    if (tid < 64) {
        float s = __ldg(&b1[tid]);
        for (int c = 0; c < 128; c++) s += __ldg(&w1[tid*128 + c]) * gaps[c];
        a1s[tid] = fmaxf(s, 0.f);
    }
    __syncthreads();
    {
        float s = __ldg(&b2[tid]);
        for (int j = 0; j < 64; j++) s += __ldg(&w2[tid*64 + j]) * a1s[j];
        a2s[tid] = s;
    }
    __syncthreads();
    if (tid < 128) {
        float e0 = a2s[tid*2], e1 = a2s[tid*2 + 1];
        float m = fmaxf(e0, e1);
        float p0 = expf(e0 - m), p1 = expf(e1 - m);
        float d = p0 + p1;
        g_a[(b*128 + tid)*2]     = p0 / d;
        g_a[(b*128 + tid)*2 + 1] = p1 / d;
    }
}

// ---------------- K9: final mix (recompute swish from ypre) ----------------
__global__ void k9_out(float* __restrict__ out, const float* __restrict__ bn_g,
                       const float* __restrict__ bn_b) {
    int idx = blockIdx.x * 256 + threadIdx.x;       // float4 index
    int bc = idx / 2304;
    int c = bc & 127;
    float mean = g_bn[c*2], rstd = g_bn[c*2 + 1];
    float gg = __ldg(&bn_g[c]), bb = __ldg(&bn_b[c]);
    float a0 = g_a[bc*2], a1 = g_a[bc*2 + 1];
    const float4 yp = ((const float4*)g_ypre)[idx];
    const float4 kv = ((const float4*)g_k)[idx];
    float t0 = (yp.x - mean) * rstd * gg + bb;
    float t1 = (yp.y - mean) * rstd * gg + bb;
    float t2 = (yp.z - mean) * rstd * gg + bb;
    float t3 = (yp.w - mean) * rstd * gg + bb;
    float y0 = t0 * __frcp_rn(1.f + __expf(-t0));
    float y1 = t1 * __frcp_rn(1.f + __expf(-t1));
    float y2 = t2 * __frcp_rn(1.f + __expf(-t2));
    float y3 = t3 * __frcp_rn(1.f + __expf(-t3));
    ((float4*)out)[idx] = make_float4(y0*a0 + kv.x*a1, y1*a0 + kv.y*a1,
                                      y2*a0 + kv.z*a1, y3*a0 + kv.w*a1);
}

// ---------------- launch ----------------
extern "C" void kernel_launch(void* const* d_in, const int* in_sizes, int n_in,
                              void* d_out, int out_size) {
    const float* x     = (const float*)d_in[0];
    const float* key_w = (const float*)d_in[1];
    const float* e_w1  = (const float*)d_in[2];
    const float* e_w2  = (const float*)d_in[3];
    const float* e_b2  = (const float*)d_in[4];
    const float* gn_g  = (const float*)d_in[5];
    const float* gn_b  = (const float*)d_in[6];
    const float* c1_w  = (const float*)d_in[7];
    const float* bn_g  = (const float*)d_in[8];
    const float* bn_b  = (const float*)d_in[9];
    const float* se_w1 = (const float*)d_in[10];
    const float* se_b1 = (const float*)d_in[11];
    const float* se_w2 = (const float*)d_in[12];
    const float* se_b2 = (const float*)d_in[13];
    float* out = (float*)d_out;

    cudaFuncSetAttribute(k2_mma,   cudaFuncAttributeMaxDynamicSharedMemorySize, K2_SMEM);
    cudaFuncSetAttribute(k5_local, cudaFuncAttributeMaxDynamicSharedMemorySize, K5_SMEM);

    k0_prep <<<72, 256>>>(e_w1, c1_w, e_w2, key_w);
    k1_mma  <<<dim3(96, 4, 8), 384>>>(x);
    k2_mma  <<<PTOT/128, 256, K2_SMEM>>>(x, e_b2);
    k4a_gn  <<<1024, 256>>>();
    k4b_gn  <<<1, 128>>>();
    k5_local<<<dim3(12, 16, 8), 384, K5_SMEM>>>(gn_g, gn_b);
    k6_bn   <<<128, 128>>>();
    k7_gap  <<<dim3(128, 8), 256>>>(bn_g, bn_b);
    k8_se   <<<8, 256>>>(se_w1, se_b1, se_w2, se_b2);
    k9_out  <<<PTOT*128/(256*4), 256>>>(out, bn_g, bn_b);
}

// round 10
// speedup vs baseline: 1.7250x; 1.0097x over previous
#include <cuda_runtime.h>
#include <cuda_bf16.h>
#include <math.h>
#include <stdint.h>

#define BB 8
#define CC 128
#define HH 96
#define WW 96
#define HW 9216            // 96*96
#define WC 144             // k*k*DIM/SP
#define PTOT (BB*HW)       // 73728

typedef unsigned long long u64;
typedef unsigned int u32;

__device__ __forceinline__ unsigned short f2bf(float f) {
    return __bfloat16_as_ushort(__float2bfloat16(f));
}
__device__ __forceinline__ float bf2f(unsigned short u) {
    return __bfloat162float(__ushort_as_bfloat16(u));
}
__device__ __forceinline__ u32 packbf(float a, float b) {
    return (u32)f2bf(a) | ((u32)f2bf(b) << 16);
}

// m16n8k16 bf16 MMA, fp32 accumulate
__device__ __forceinline__ void mma_bf16(float* c, u32 a0, u32 a1, u32 a2, u32 a3,
                                         u32 b0, u32 b1) {
    asm volatile(
        "mma.sync.aligned.m16n8k16.row.col.f32.bf16.bf16.f32 "
        "{%0,%1,%2,%3}, {%4,%5,%6,%7}, {%8,%9}, {%0,%1,%2,%3};"
        : "+f"(c[0]), "+f"(c[1]), "+f"(c[2]), "+f"(c[3])
        : "r"(a0), "r"(a1), "r"(a2), "r"(a3), "r"(b0), "r"(b1));
}

// ---------------- scratch ----------------
__device__ float g_k   [BB*CC*HW];
__device__ float g_v   [BB*CC*HW];
__device__ float g_wpre[BB*WC*HW];
__device__ float g_ypre[BB*CC*HW];
// A-fragment images (bf16 hi/lo) — static weights, built once in k0
__device__ __align__(16) u32 g_Afh [8192];    // c1_w:  [mt8][ks8][lane32][4]
__device__ __align__(16) u32 g_Afl [8192];
__device__ __align__(16) u32 g_W1fh[8192];    // e_w1:  [mt4][ks16][lane32][4]
__device__ __align__(16) u32 g_W1fl[8192];
__device__ __align__(16) u32 g_W2fh[4608];    // e_w2:  [mt9][ks4][lane32][4]
__device__ __align__(16) u32 g_W2fl[4608];
__device__ __align__(16) u32 g_KWfh[18432];   // key_w: [g4][mt2][ks18][lane32][4], k = tap*32+ci
__device__ __align__(16) u32 g_KWfl[18432];
__device__ float g_gnS2[144*576];  // GN per-(channel, k2-block) partial sums
__device__ float g_gnQ2[144*576];
__device__ float g_gn  [128*2];
__device__ float g_bnS [128*96];
__device__ float g_bnQ [128*96];
__device__ float g_bn  [128*2];
__device__ float g_gap [BB*CC];
__device__ float g_a   [BB*CC*2];

// ---------------- K0: weight prep (A-fragment images) ----------------
__global__ void k0_prep(const float* __restrict__ e_w1, const float* __restrict__ c1_w,
                        const float* __restrict__ e_w2, const float* __restrict__ key_w) {
    int idx = blockIdx.x * 256 + threadIdx.x;   // 0..18431
    int r = idx & 3, lane = (idx >> 2) & 31;
    int gid = lane >> 2, tig = lane & 3;
    int dr = (r & 1) * 8, dc = (r & 2) * 4;
    if (idx < 8192) {   // c1_w [128,128]: mt8, ks8
        int ks = (idx >> 7) & 7, mt = idx >> 10;
        int row = mt*16 + gid + dr, col = ks*16 + tig*2 + dc;
        float w0 = c1_w[row*128 + col], w1 = c1_w[row*128 + col + 1];
        g_Afh[idx] = packbf(w0, w1);
        g_Afl[idx] = packbf(w0 - bf2f(f2bf(w0)), w1 - bf2f(f2bf(w1)));
    }
    if (idx < 8192) {   // e_w1 [64,256]: mt4, ks16
        int ks = (idx >> 7) & 15, mt = idx >> 11;
        int row = mt*16 + gid + dr, col = ks*16 + tig*2 + dc;
        float w0 = e_w1[row*256 + col], w1 = e_w1[row*256 + col + 1];
        g_W1fh[idx] = packbf(w0, w1);
        g_W1fl[idx] = packbf(w0 - bf2f(f2bf(w0)), w1 - bf2f(f2bf(w1)));
    }
    if (idx < 4608) {   // e_w2 [144,64]: mt9, ks4
        int ks = (idx >> 7) & 3, mt = idx >> 9;
        int row = mt*16 + gid + dr, col = ks*16 + tig*2 + dc;
        float w0 = e_w2[row*64 + col], w1 = e_w2[row*64 + col + 1];
        g_W2fh[idx] = packbf(w0, w1);
        g_W2fl[idx] = packbf(w0 - bf2f(f2bf(w0)), w1 - bf2f(f2bf(w1)));
    }
    {   // key_w grouped: [g4][mt2][ks18][lane32][4], k = tap*32 + ci
        int idx2 = idx >> 7;
        int ks = idx2 % 18, gmt = idx2 / 18;
        int mt = gmt & 1, gg = gmt >> 1;
        int row = mt*16 + gid + dr;
        int colk = ks*16 + tig*2 + dc;
        int t = colk >> 5, ci = colk & 31;
        const float* wb = key_w + ((size_t)(gg*32 + row)*32 + ci)*9 + t;
        float w0 = wb[0], w1 = wb[9];
        g_KWfh[idx] = packbf(w0, w1);
        g_KWfl[idx] = packbf(w0 - bf2f(f2bf(w0)), w1 - bf2f(f2bf(w1)));
    }
}

// ---------------- K1: grouped 3x3 conv + ReLU via warp MMA ----------------
__global__ void __launch_bounds__(384) k1_mma(const float* __restrict__ x) {
    __shared__ float xs[32 * 294];
    int h = blockIdx.x, g = blockIdx.y, b = blockIdx.z;
    int tid = threadIdx.x, wid = tid >> 5, lane = tid & 31;
    for (int idx = tid; idx < 32 * 294; idx += 384) {
        int ci = idx / 294, rem = idx % 294, r = rem / 98, col = rem % 98;
        int hh = h + r - 1, wc = col - 1;
        float v = 0.f;
        if ((unsigned)hh < 96u && (unsigned)wc < 96u)
            v = x[(b*128 + g*32 + ci) * HW + hh*96 + wc];
        xs[idx] = v;
    }
    __syncthreads();

    int gid = lane >> 2, tig = lane & 3;
    int nbase = wid*8 + gid;
    float acc0[4] = {0.f,0.f,0.f,0.f};
    float acc1[4] = {0.f,0.f,0.f,0.f};
    const uint4* AH = (const uint4*)g_KWfh + (size_t)g*2*18*32;
    const uint4* AL = (const uint4*)g_KWfl + (size_t)g*2*18*32;

#pragma unroll
    for (int ks = 0; ks < 18; ks++) {
        const int t = ks >> 1, cib = (ks & 1) * 16;
        const int r = t / 3, c = t - 3*r;
        int ci0 = cib + tig*2;
        const float* base = xs + r*98 + nbase + c;
        float v0 = base[ ci0      *294];
        float v1 = base[(ci0 + 1) *294];
        float v2 = base[(ci0 + 8) *294];
        float v3 = base[(ci0 + 9) *294];
        u32 bh0 = packbf(v0, v1), bh1 = packbf(v2, v3);
        u32 bl0 = packbf(v0 - bf2f(f2bf(v0)), v1 - bf2f(f2bf(v1)));
        u32 bl1 = packbf(v2 - bf2f(f2bf(v2)), v3 - bf2f(f2bf(v3)));
        uint4 ah0 = AH[(0*18 + ks)*32 + lane];
        uint4 al0 = AL[(0*18 + ks)*32 + lane];
        uint4 ah1 = AH[(1*18 + ks)*32 + lane];
        uint4 al1 = AL[(1*18 + ks)*32 + lane];
        mma_bf16(acc0, ah0.x, ah0.y, ah0.z, ah0.w, bh0, bh1);
        mma_bf16(acc0, ah0.x, ah0.y, ah0.z, ah0.w, bl0, bl1);
        mma_bf16(acc0, al0.x, al0.y, al0.z, al0.w, bh0, bh1);
        mma_bf16(acc1, ah1.x, ah1.y, ah1.z, ah1.w, bh0, bh1);
        mma_bf16(acc1, ah1.x, ah1.y, ah1.z, ah1.w, bl0, bl1);
        mma_bf16(acc1, al1.x, al1.y, al1.z, al1.w, bh0, bh1);
    }

    int n0 = wid*8 + tig*2;
    {
        int co = g*32 + gid;
        float* p = g_k + (size_t)(b*128 + co)*HW + h*96 + n0;
        *(float2*)p            = make_float2(fmaxf(acc0[0],0.f), fmaxf(acc0[1],0.f));
        *(float2*)(p + 8*HW)   = make_float2(fmaxf(acc0[2],0.f), fmaxf(acc0[3],0.f));
        float* q = p + 16*HW;
        *(float2*)q            = make_float2(fmaxf(acc1[0],0.f), fmaxf(acc1[1],0.f));
        *(float2*)(q + 8*HW)   = make_float2(fmaxf(acc1[2],0.f), fmaxf(acc1[3],0.f));
    }
}

// ---------------- K2: fused embed GEMMs + value GEMM + GN partials ----------------
#define K2_SMEM (33280 + 32768)
__global__ void __launch_bounds__(256) k2_mma(const float* __restrict__ x,
                                              const float* __restrict__ e_b2) {
    extern __shared__ float sm[];
    float* xs = sm;
    u32* bh = (u32*)(sm + 8320);
    u32* bl = bh + 4096;
    int tid = threadIdx.x, wid = tid >> 5, lane = tid & 31;
    int gid = lane >> 2, tig = lane & 3;
    int pb = blockIdx.x * 128, b = pb / HW, hw0 = pb % HW;
    const float* xb = x   + (size_t)b*128*HW + hw0;
    const float* kb = g_k + (size_t)b*128*HW + hw0;

    int mt1 = wid & 3, ng = wid >> 2;
    float acc[8][4];
#pragma unroll
    for (int i = 0; i < 8; i++)
#pragma unroll
        for (int j = 0; j < 4; j++) acc[i][j] = 0.f;

    {
        float accv[16][4];
#pragma unroll
        for (int i = 0; i < 16; i++)
#pragma unroll
            for (int j = 0; j < 4; j++) accv[i][j] = 0.f;

        for (int kc = 0; kc < 2; kc++) {
            const float* src = xb + (size_t)kc*64*HW;
            for (int i = tid; i < 64*64; i += 256) {
                int k = i >> 6, n = (i & 63) * 2;
                float2 v = *(const float2*)(src + (size_t)k*HW + n);
                xs[k*130 + n] = v.x; xs[k*130 + n + 1] = v.y;
            }
            __syncthreads();
            for (int i = tid; i < 2048; i += 256) {
                int l2 = i & 31, nt = (i >> 5) & 15, ks = i >> 9;
                int g2 = l2 >> 2, t2 = l2 & 3;
                int n = nt*8 + g2, k = ks*16 + t2*2;
                float f0 = xs[k*130 + n],     f1 = xs[(k+1)*130 + n];
                float f2 = xs[(k+8)*130 + n], f3 = xs[(k+9)*130 + n];
                int base = i * 2;
                bh[base]     = packbf(f0, f1);
                bh[base + 1] = packbf(f2, f3);
                bl[base]     = packbf(f0 - bf2f(f2bf(f0)), f1 - bf2f(f2bf(f1)));
                bl[base + 1] = packbf(f2 - bf2f(f2bf(f2)), f3 - bf2f(f2bf(f3)));
            }
            __syncthreads();
#pragma unroll
            for (int ks = 0; ks < 4; ks++) {
                int gks = kc*4 + ks;
                uint4 ah = ((const uint4*)g_W1fh)[(mt1*16 + gks)*32 + lane];
                uint4 al = ((const uint4*)g_W1fl)[(mt1*16 + gks)*32 + lane];
#pragma unroll
                for (int nt2 = 0; nt2 < 8; nt2++) {
                    int nt = ng*8 + nt2;
                    int base = ((ks*16 + nt)*32 + lane) * 2;
                    u32 bh0 = bh[base], bh1 = bh[base + 1];
                    u32 bl0 = bl[base], bl1 = bl[base + 1];
                    mma_bf16(acc[nt2], ah.x, ah.y, ah.z, ah.w, bh0, bh1);
                    mma_bf16(acc[nt2], ah.x, ah.y, ah.z, ah.w, bl0, bl1);
                    mma_bf16(acc[nt2], al.x, al.y, al.z, al.w, bh0, bh1);
                }
                uint4 vh = ((const uint4*)g_Afh)[(wid*8 + gks)*32 + lane];
                uint4 vl = ((const uint4*)g_Afl)[(wid*8 + gks)*32 + lane];
#pragma unroll
                for (int nt = 0; nt < 16; nt++) {
                    int base = ((ks*16 + nt)*32 + lane) * 2;
                    u32 bh0 = bh[base], bh1 = bh[base + 1];
                    u32 bl0 = bl[base], bl1 = bl[base + 1];
                    mma_bf16(accv[nt], vh.x, vh.y, vh.z, vh.w, bh0, bh1);
                    mma_bf16(accv[nt], vh.x, vh.y, vh.z, vh.w, bl0, bl1);
                    mma_bf16(accv[nt], vl.x, vl.y, vl.z, vl.w, bh0, bh1);
                }
            }
            __syncthreads();
        }
        int m0 = wid*16 + gid;
        float* vb0 = g_v + (size_t)(b*128 + m0)*HW + hw0 + tig*2;
        float* vb1 = vb0 + (size_t)8*HW;
#pragma unroll
        for (int nt = 0; nt < 16; nt++) {
            *(float2*)(vb0 + nt*8) = make_float2(accv[nt][0], accv[nt][1]);
            *(float2*)(vb1 + nt*8) = make_float2(accv[nt][2], accv[nt][3]);
        }
    }

    for (int kc = 2; kc < 4; kc++) {
        const float* src = kb + (size_t)(kc-2)*64*HW;
        for (int i = tid; i < 64*64; i += 256) {
            int k = i >> 6, n = (i & 63) * 2;
            float2 v = *(const float2*)(src + (size_t)k*HW + n);
            xs[k*130 + n] = v.x; xs[k*130 + n + 1] = v.y;
        }
        __syncthreads();
        for (int i = tid; i < 2048; i += 256) {
            int l2 = i & 31, nt = (i >> 5) & 15, ks = i >> 9;
            int g2 = l2 >> 2, t2 = l2 & 3;
            int n = nt*8 + g2, k = ks*16 + t2*2;
            float f0 = xs[k*130 + n],     f1 = xs[(k+1)*130 + n];
            float f2 = xs[(k+8)*130 + n], f3 = xs[(k+9)*130 + n];
            int base = i * 2;
            bh[base]     = packbf(f0, f1);
            bh[base + 1] = packbf(f2, f3);
            bl[base]     = packbf(f0 - bf2f(f2bf(f0)), f1 - bf2f(f2bf(f1)));
            bl[base + 1] = packbf(f2 - bf2f(f2bf(f2)), f3 - bf2f(f2bf(f3)));
        }
        __syncthreads();
#pragma unroll
        for (int ks = 0; ks < 4; ks++) {
            int gks = kc*4 + ks;
            uint4 ah = ((const uint4*)g_W1fh)[(mt1*16 + gks)*32 + lane];
            uint4 al = ((const uint4*)g_W1fl)[(mt1*16 + gks)*32 + lane];
#pragma unroll
            for (int nt2 = 0; nt2 < 8; nt2++) {
                int nt = ng*8 + nt2;
                int base = ((ks*16 + nt)*32 + lane) * 2;
                u32 bh0 = bh[base], bh1 = bh[base + 1];
                u32 bl0 = bl[base], bl1 = bl[base + 1];
                mma_bf16(acc[nt2], ah.x, ah.y, ah.z, ah.w, bh0, bh1);
                mma_bf16(acc[nt2], ah.x, ah.y, ah.z, ah.w, bl0, bl1);
                mma_bf16(acc[nt2], al.x, al.y, al.z, al.w, bh0, bh1);
            }
        }
        __syncthreads();
    }

#pragma unroll
    for (int nt2 = 0; nt2 < 8; nt2++) {
        int n0 = (ng*8 + nt2)*8 + tig*2;
        int r0 = mt1*16 + gid;
        xs[r0*130 + n0]       = fmaxf(acc[nt2][0], 0.f);
        xs[r0*130 + n0 + 1]   = fmaxf(acc[nt2][1], 0.f);
        xs[(r0+8)*130 + n0]   = fmaxf(acc[nt2][2], 0.f);
        xs[(r0+8)*130 + n0+1] = fmaxf(acc[nt2][3], 0.f);
    }
    __syncthreads();

    for (int i = tid; i < 2048; i += 256) {
        int l2 = i & 31, nt = (i >> 5) & 15, ks = i >> 9;
        int g2 = l2 >> 2, t2 = l2 & 3;
        int n = nt*8 + g2, k = ks*16 + t2*2;
        float f0 = xs[k*130 + n],     f1 = xs[(k+1)*130 + n];
        float f2 = xs[(k+8)*130 + n], f3 = xs[(k+9)*130 + n];
        int base = i * 2;
        bh[base]     = packbf(f0, f1);
        bh[base + 1] = packbf(f2, f3);
        bl[base]     = packbf(f0 - bf2f(f2bf(f0)), f1 - bf2f(f2bf(f1)));
        bl[base + 1] = packbf(f2 - bf2f(f2bf(f2)), f3 - bf2f(f2bf(f3)));
    }
    __syncthreads();

    float acc2[16][4];
    float acc3[2][4];
#pragma unroll
    for (int i = 0; i < 16; i++)
#pragma unroll
        for (int j = 0; j < 4; j++) acc2[i][j] = 0.f;
#pragma unroll
    for (int i = 0; i < 2; i++)
#pragma unroll
        for (int j = 0; j < 4; j++) acc3[i][j] = 0.f;

#pragma unroll
    for (int ks = 0; ks < 4; ks++) {
        uint4 ah  = ((const uint4*)g_W2fh)[(wid*4 + ks)*32 + lane];
        uint4 al  = ((const uint4*)g_W2fl)[(wid*4 + ks)*32 + lane];
        uint4 ah8 = ((const uint4*)g_W2fh)[(8*4 + ks)*32 + lane];
        uint4 al8 = ((const uint4*)g_W2fl)[(8*4 + ks)*32 + lane];
#pragma unroll
        for (int nt = 0; nt < 16; nt++) {
            int base = ((ks*16 + nt)*32 + lane) * 2;
            u32 bh0 = bh[base], bh1 = bh[base + 1];
            u32 bl0 = bl[base], bl1 = bl[base + 1];
            mma_bf16(acc2[nt], ah.x, ah.y, ah.z, ah.w, bh0, bh1);
            mma_bf16(acc2[nt], ah.x, ah.y, ah.z, ah.w, bl0, bl1);
            mma_bf16(acc2[nt], al.x, al.y, al.z, al.w, bh0, bh1);
        }
#pragma unroll
        for (int j = 0; j < 2; j++) {
            int nt = wid*2 + j;
            int base = ((ks*16 + nt)*32 + lane) * 2;
            u32 bh0 = bh[base], bh1 = bh[base + 1];
            u32 bl0 = bl[base], bl1 = bl[base + 1];
            mma_bf16(acc3[j], ah8.x, ah8.y, ah8.z, ah8.w, bh0, bh1);
            mma_bf16(acc3[j], ah8.x, ah8.y, ah8.z, ah8.w, bl0, bl1);
            mma_bf16(acc3[j], al8.x, al8.y, al8.z, al8.w, bh0, bh1);
        }
    }
    __syncthreads();   // frag buffers free; reuse bh as float scratch for m8 partials

    {
        float* fsc = (float*)bh;    // [8 warp][8 gid][4]
        int m0 = wid*16 + gid;
        float bias0 = __ldg(&e_b2[m0]), bias1 = __ldg(&e_b2[m0 + 8]);
        float* p0 = g_wpre + (size_t)(b*144 + m0)*HW + hw0 + tig*2;
        float* p1 = p0 + (size_t)8*HW;
        float s0 = 0.f, q0 = 0.f, s1 = 0.f, q1 = 0.f;
#pragma unroll
        for (int nt = 0; nt < 16; nt++) {
            float t0 = acc2[nt][0] + bias0, t1 = acc2[nt][1] + bias0;
            float t2 = acc2[nt][2] + bias1, t3 = acc2[nt][3] + bias1;
            *(float2*)(p0 + nt*8) = make_float2(t0, t1);
            *(float2*)(p1 + nt*8) = make_float2(t2, t3);
            s0 += t0 + t1; q0 += t0*t0 + t1*t1;
            s1 += t2 + t3; q1 += t2*t2 + t3*t3;
        }
        int m8 = 128 + gid;
        float bias2 = __ldg(&e_b2[m8]), bias3 = __ldg(&e_b2[m8 + 8]);
        float* q0p = g_wpre + (size_t)(b*144 + m8)*HW + hw0 + tig*2;
        float* q1p = q0p + (size_t)8*HW;
        float s2 = 0.f, q2 = 0.f, s3 = 0.f, q3 = 0.f;
#pragma unroll
        for (int j = 0; j < 2; j++) {
            int nt = wid*2 + j;
            float t0 = acc3[j][0] + bias2, t1 = acc3[j][1] + bias2;
            float t2 = acc3[j][2] + bias3, t3 = acc3[j][3] + bias3;
            *(float2*)(q0p + nt*8) = make_float2(t0, t1);
            *(float2*)(q1p + nt*8) = make_float2(t2, t3);
            s2 += t0 + t1; q2 += t0*t0 + t1*t1;
            s3 += t2 + t3; q3 += t2*t2 + t3*t3;
        }
        // quad reduce (sum over tig: covers all 128 px for acc2 channels)
#pragma unroll
        for (int off = 1; off < 4; off <<= 1) {
            s0 += __shfl_down_sync(0xffffffffu, s0, off, 4);
            q0 += __shfl_down_sync(0xffffffffu, q0, off, 4);
            s1 += __shfl_down_sync(0xffffffffu, s1, off, 4);
            q1 += __shfl_down_sync(0xffffffffu, q1, off, 4);
            s2 += __shfl_down_sync(0xffffffffu, s2, off, 4);
            q2 += __shfl_down_sync(0xffffffffu, q2, off, 4);
            s3 += __shfl_down_sync(0xffffffffu, s3, off, 4);
            q3 += __shfl_down_sync(0xffffffffu, q3, off, 4);
        }
        if (tig == 0) {
            int blk = blockIdx.x;
            g_gnS2[m0*576 + blk]       = s0;
            g_gnQ2[m0*576 + blk]       = q0;
            g_gnS2[(m0+8)*576 + blk]   = s1;
            g_gnQ2[(m0+8)*576 + blk]   = q1;
            float* f = fsc + (wid*8 + gid)*4;
            f[0] = s2; f[1] = q2; f[2] = s3; f[3] = q3;
        }
        __syncthreads();
        if (tid < 16) {
            int g2 = tid & 7, sel = tid >> 3;
            float ss = 0.f, qq = 0.f;
#pragma unroll
            for (int wp = 0; wp < 8; wp++) {
                const float* f = fsc + (wp*8 + g2)*4 + sel*2;
                ss += f[0]; qq += f[1];
            }
            int ch = 128 + sel*8 + g2;
            g_gnS2[ch*576 + blockIdx.x] = ss;
            g_gnQ2[ch*576 + blockIdx.x] = qq;
        }
    }
}

// ---------------- K4: GN finalize from k2 partials ----------------
__global__ void k4_gn2() {
    __shared__ float rs[256], rq[256];
    int bg = blockIdx.x, b = bg >> 4, g = bg & 15;
    int tid = threadIdx.x;
    float s = 0.f, q = 0.f;
    for (int idx = tid; idx < 9*72; idx += 256) {
        int t = idx / 72, i = idx % 72;
        int ch = g*9 + t;
        s += g_gnS2[ch*576 + b*72 + i];
        q += g_gnQ2[ch*576 + b*72 + i];
    }
    rs[tid] = s; rq[tid] = q;
    __syncthreads();
    for (int o = 128; o > 0; o >>= 1) {
        if (tid < o) { rs[tid] += rs[tid+o]; rq[tid] += rq[tid+o]; }
        __syncthreads();
    }
    if (tid == 0) {
        float inv = 1.f / (9.f*HW);
        float mean = rs[0] * inv;
        float var  = rq[0] * inv - mean*mean;
        g_gn[bg*2]     = mean;
        g_gn[bg*2 + 1] = rsqrtf(var + 1e-5f);
    }
}

// ---------------- K5: local dynamic conv + BN partials (8 rows/block) ----------------
#define K5_SMEM ((6912 + 7840 + 192) * 4)
__global__ void __launch_bounds__(384) k5_local(const float* __restrict__ gn_g,
                                                const float* __restrict__ gn_b) {
    extern __shared__ float sm5[];
    float* wn  = sm5;            // 9*8*96
    float* vs  = sm5 + 6912;     // 8*10*98
    float* red = sm5 + 6912 + 7840;
    int h0 = blockIdx.x * 8, g = blockIdx.y, b = blockIdx.z;
    int tid = threadIdx.x;
    float mean = g_gn[(b*16 + g)*2], rstd = g_gn[(b*16 + g)*2 + 1];

    for (int idx = tid; idx < 6912; idx += 384) {
        int t = idx / 768, rem = idx % 768;
        int ch = g*9 + t;
        float raw = g_wpre[(size_t)(b*144 + ch)*HW + h0*96 + rem];
        wn[idx] = (raw - mean) * rstd * __ldg(&gn_g[ch]) + __ldg(&gn_b[ch]);
    }
    for (int idx = tid; idx < 7840; idx += 384) {
        int s = idx / 980, rem = idx % 980, r = rem / 98, col = rem % 98;
        int hh = h0 + r - 1, wc = col - 1;
        float v = 0.f;
        if ((unsigned)hh < 96u && (unsigned)wc < 96u)
            v = g_v[(size_t)(b*128 + g*8 + s)*HW + hh*96 + wc];
        vs[idx] = v;
    }
    __syncthreads();

    int w = tid % 96, rq = tid / 96;
    int lane = tid & 31, warp = tid >> 5;
#pragma unroll
    for (int s = 0; s < 8; s++) {
        float p1 = 0.f, p2 = 0.f;
        const float* vb = vs + s*980;
#pragma unroll
        for (int rr = 0; rr < 2; rr++) {
            int row = rq*2 + rr;
            float acc = 0.f;
#pragma unroll
            for (int dr = 0; dr < 3; dr++)
#pragma unroll
                for (int dc = 0; dc < 3; dc++)
                    acc += vb[(row+dr)*98 + w + dc] * wn[(dr*3+dc)*768 + row*96 + w];
            g_ypre[(size_t)(b*128 + g*8 + s)*HW + (h0+row)*96 + w] = acc;
            p1 += acc; p2 += acc*acc;
        }
        for (int off = 16; off; off >>= 1) {
            p1 += __shfl_down_sync(0xffffffffu, p1, off);
            p2 += __shfl_down_sync(0xffffffffu, p2, off);
        }
        if (lane == 0) { red[warp*16 + s*2] = p1; red[warp*16 + s*2 + 1] = p2; }
    }
    __syncthreads();
    if (tid < 8) {
        float s1 = 0.f, s2 = 0.f;
#pragma unroll
        for (int wp = 0; wp < 12; wp++) {
            s1 += red[wp*16 + tid*2];
            s2 += red[wp*16 + tid*2 + 1];
        }
        int c = g*8 + tid;
        g_bnS[c*96 + b*12 + blockIdx.x] = s1;
        g_bnQ[c*96 + b*12 + blockIdx.x] = s2;
    }
}

// ---------------- K6: BN finalize ----------------
__global__ void k6_bn() {
    __shared__ float rs[96], rq[96];
    int c = blockIdx.x, tid = threadIdx.x;
    if (tid < 96) { rs[tid] = g_bnS[c*96 + tid]; rq[tid] = g_bnQ[c*96 + tid]; }
    __syncthreads();
    if (tid < 32) {
        float s = rs[tid] + rs[tid+32] + rs[tid+64];
        float q = rq[tid] + rq[tid+32] + rq[tid+64];
        for (int off = 16; off; off >>= 1) {
            s += __shfl_down_sync(0xffffffffu, s, off);
            q += __shfl_down_sync(0xffffffffu, q, off);
        }
        if (tid == 0) {
            float inv = 1.f / (float)PTOT;
            float mean = s * inv;
            float var  = q * inv - mean*mean;
            g_bn[c*2]     = mean;
            g_bn[c*2 + 1] = rsqrtf(var + 1e-5f);
        }
    }
}

// ---------------- K7: GAP partials (float4, swish on the fly) ----------------
__global__ void k7_gap(const float* __restrict__ bn_g, const float* __restrict__ bn_b) {
    __shared__ float rs[256];
    int c = blockIdx.x, b = blockIdx.y;
    float mean = g_bn[c*2], rstd = g_bn[c*2 + 1];
    float gg = __ldg(&bn_g[c]), bb = __ldg(&bn_b[c]);
    const float4* yb = (const float4*)(g_ypre + (size_t)(b*128 + c)*HW);
    const float4* kb = (const float4*)(g_k    + (size_t)(b*128 + c)*HW);
    float s = 0.f;
    for (int idx = threadIdx.x; idx < HW/4; idx += 256) {
        float4 yp = yb[idx];
        float4 kv = kb[idx];
        float t0 = (yp.x - mean) * rstd * gg + bb;
        float t1 = (yp.y - mean) * rstd * gg + bb;
        float t2 = (yp.z - mean) * rstd * gg + bb;
        float t3 = (yp.w - mean) * rstd * gg + bb;
        s += t0 * __frcp_rn(1.f + __expf(-t0)) + kv.x;
        s += t1 * __frcp_rn(1.f + __expf(-t1)) + kv.y;
        s += t2 * __frcp_rn(1.f + __expf(-t2)) + kv.z;
        s += t3 * __frcp_rn(1.f + __expf(-t3)) + kv.w;
    }
    rs[threadIdx.x] = s;
    __syncthreads();
    for (int o = 128; o > 0; o >>= 1) {
        if (threadIdx.x < o) rs[threadIdx.x] += rs[threadIdx.x + o];
        __syncthreads();
    }
    if (threadIdx.x == 0) g_gap[b*128 + c] = rs[0] * (1.f / (float)HW);
}

// ---------------- K8: SE MLP + radix softmax ----------------
__global__ void k8_se(const float* __restrict__ w1, const float* __restrict__ b1,
                      const float* __restrict__ w2, const float* __restrict__ b2) {
    __shared__ float gaps[128], a1s[64], a2s[256];
    int b = blockIdx.x, tid = threadIdx.x;
    if (tid < 128) gaps[tid] = g_gap[b*128 + tid];
    __syncthreads();
    if (tid < 64) {
        float s = __ldg(&b1[tid]);
        for (int c = 0; c < 128; c++) s += __ldg(&w1[tid*128 + c]) * gaps[c];
        a1s[tid] = fmaxf(s, 0.f);
    }
    __syncthreads();
    {
        float s = __ldg(&b2[tid]);
        for (int j = 0; j < 64; j++) s += __ldg(&w2[tid*64 + j]) * a1s[j];
        a2s[tid] = s;
    }
    __syncthreads();
    if (tid < 128) {
        float e0 = a2s[tid*2], e1 = a2s[tid*2 + 1];
        float m = fmaxf(e0, e1);
        float p0 = expf(e0 - m), p1 = expf(e1 - m);
        float d = p0 + p1;
        g_a[(b*128 + tid)*2]     = p0 / d;
        g_a[(b*128 + tid)*2 + 1] = p1 / d;
    }
}

// ---------------- K9: final mix (recompute swish from ypre) ----------------
__global__ void k9_out(float* __restrict__ out, const float* __restrict__ bn_g,
                       const float* __restrict__ bn_b) {
    int idx = blockIdx.x * 256 + threadIdx.x;
    int bc = idx / 2304;
    int c = bc & 127;
    float mean = g_bn[c*2], rstd = g_bn[c*2 + 1];
    float gg = __ldg(&bn_g[c]), bb = __ldg(&bn_b[c]);
    float a0 = g_a[bc*2], a1 = g_a[bc*2 + 1];
    const float4 yp = ((const float4*)g_ypre)[idx];
    const float4 kv = ((const float4*)g_k)[idx];
    float t0 = (yp.x - mean) * rstd * gg + bb;
    float t1 = (yp.y - mean) * rstd * gg + bb;
    float t2 = (yp.z - mean) * rstd * gg + bb;
    float t3 = (yp.w - mean) * rstd * gg + bb;
    float y0 = t0 * __frcp_rn(1.f + __expf(-t0));
    float y1 = t1 * __frcp_rn(1.f + __expf(-t1));
    float y2 = t2 * __frcp_rn(1.f + __expf(-t2));
    float y3 = t3 * __frcp_rn(1.f + __expf(-t3));
    ((float4*)out)[idx] = make_float4(y0*a0 + kv.x*a1, y1*a0 + kv.y*a1,
                                      y2*a0 + kv.z*a1, y3*a0 + kv.w*a1);
}

// ---------------- launch ----------------
extern "C" void kernel_launch(void* const* d_in, const int* in_sizes, int n_in,
                              void* d_out, int out_size) {
    const float* x     = (const float*)d_in[0];
    const float* key_w = (const float*)d_in[1];
    const float* e_w1  = (const float*)d_in[2];
    const float* e_w2  = (const float*)d_in[3];
    const float* e_b2  = (const float*)d_in[4];
    const float* gn_g  = (const float*)d_in[5];
    const float* gn_b  = (const float*)d_in[6];
    const float* c1_w  = (const float*)d_in[7];
    const float* bn_g  = (const float*)d_in[8];
    const float* bn_b  = (const float*)d_in[9];
    const float* se_w1 = (const float*)d_in[10];
    const float* se_b1 = (const float*)d_in[11];
    const float* se_w2 = (const float*)d_in[12];
    const float* se_b2 = (const float*)d_in[13];
    float* out = (float*)d_out;

    cudaFuncSetAttribute(k2_mma,   cudaFuncAttributeMaxDynamicSharedMemorySize, K2_SMEM);
    cudaFuncSetAttribute(k5_local, cudaFuncAttributeMaxDynamicSharedMemorySize, K5_SMEM);

    k0_prep <<<72, 256>>>(e_w1, c1_w, e_w2, key_w);
    k1_mma  <<<dim3(96, 4, 8), 384>>>(x);
    k2_mma  <<<PTOT/128, 256, K2_SMEM>>>(x, e_b2);
    k4_gn2  <<<128, 256>>>();
    k5_local<<<dim3(12, 16, 8), 384, K5_SMEM>>>(gn_g, gn_b);
    k6_bn   <<<128, 128>>>();
    k7_gap  <<<dim3(128, 8), 256>>>(bn_g, bn_b);
    k8_se   <<<8, 256>>>(se_w1, se_b1, se_w2, se_b2);
    k9_out  <<<PTOT*128/(256*4), 256>>>(out, bn_g, bn_b);
}

// round 12
// speedup vs baseline: 1.9755x; 1.1452x over previous
#include <cuda_runtime.h>
#include <cuda_bf16.h>
#include <math.h>
#include <stdint.h>

#define BB 8
#define CC 128
#define HH 96
#define WW 96
#define HW 9216            // 96*96
#define WC 144             // k*k*DIM/SP
#define PTOT (BB*HW)       // 73728

typedef unsigned long long u64;
typedef unsigned int u32;

__device__ __forceinline__ unsigned short f2bf(float f) {
    return __bfloat16_as_ushort(__float2bfloat16(f));
}
__device__ __forceinline__ float bf2f(unsigned short u) {
    return __bfloat162float(__ushort_as_bfloat16(u));
}
__device__ __forceinline__ u32 packbf(float a, float b) {
    return (u32)f2bf(a) | ((u32)f2bf(b) << 16);
}

// m16n8k16 bf16 MMA, fp32 accumulate
__device__ __forceinline__ void mma_bf16(float* c, u32 a0, u32 a1, u32 a2, u32 a3,
                                         u32 b0, u32 b1) {
    asm volatile(
        "mma.sync.aligned.m16n8k16.row.col.f32.bf16.bf16.f32 "
        "{%0,%1,%2,%3}, {%4,%5,%6,%7}, {%8,%9}, {%0,%1,%2,%3};"
        : "+f"(c[0]), "+f"(c[1]), "+f"(c[2]), "+f"(c[3])
        : "r"(a0), "r"(a1), "r"(a2), "r"(a3), "r"(b0), "r"(b1));
}
// 3-term bf16-split MMA from packed u64 fragment pairs
__device__ __forceinline__ void mma3(float* c, const uint4& ah, const uint4& al,
                                     u64 bhp, u64 blp) {
    u32 bh0 = (u32)bhp, bh1 = (u32)(bhp >> 32);
    u32 bl0 = (u32)blp, bl1 = (u32)(blp >> 32);
    mma_bf16(c, ah.x, ah.y, ah.z, ah.w, bh0, bh1);
    mma_bf16(c, ah.x, ah.y, ah.z, ah.w, bl0, bl1);
    mma_bf16(c, al.x, al.y, al.z, al.w, bh0, bh1);
}

// ---------------- scratch ----------------
__device__ float g_k   [BB*CC*HW];
__device__ float g_v   [BB*CC*HW];
__device__ float g_wpre[BB*WC*HW];
__device__ float g_ypre[BB*CC*HW];
__device__ __align__(16) u32 g_Afh [8192];    // c1_w:  [mt8][ks8][lane32][4]
__device__ __align__(16) u32 g_Afl [8192];
__device__ __align__(16) u32 g_W1fh[8192];    // e_w1:  [mt4][ks16][lane32][4]
__device__ __align__(16) u32 g_W1fl[8192];
__device__ __align__(16) u32 g_W2fh[4608];    // e_w2:  [mt9][ks4][lane32][4]
__device__ __align__(16) u32 g_W2fl[4608];
__device__ __align__(16) u32 g_KWfh[18432];   // key_w: [g4][mt2][ks18][lane32][4]
__device__ __align__(16) u32 g_KWfl[18432];
__device__ float g_gnS2[144*576];
__device__ float g_gnQ2[144*576];
__device__ float g_gn  [128*2];
__device__ float g_bnS [128*96];
__device__ float g_bnQ [128*96];
__device__ float g_bn  [128*2];
__device__ float g_gap [BB*CC];
__device__ float g_a   [BB*CC*2];
__device__ int   g_sink;

// ---------------- dummy (slots k2 into ncu capture position 4) ----------------
__global__ void kdummy() {
    if (threadIdx.x == 1024) g_sink = 1;   // never true; prevents empty-kernel elision
}

// ---------------- K0: weight prep ----------------
__global__ void k0_prep(const float* __restrict__ e_w1, const float* __restrict__ c1_w,
                        const float* __restrict__ e_w2, const float* __restrict__ key_w) {
    int idx = blockIdx.x * 256 + threadIdx.x;   // 0..18431
    int r = idx & 3, lane = (idx >> 2) & 31;
    int gid = lane >> 2, tig = lane & 3;
    int dr = (r & 1) * 8, dc = (r & 2) * 4;
    if (idx < 8192) {
        int ks = (idx >> 7) & 7, mt = idx >> 10;
        int row = mt*16 + gid + dr, col = ks*16 + tig*2 + dc;
        float w0 = c1_w[row*128 + col], w1 = c1_w[row*128 + col + 1];
        g_Afh[idx] = packbf(w0, w1);
        g_Afl[idx] = packbf(w0 - bf2f(f2bf(w0)), w1 - bf2f(f2bf(w1)));
    }
    if (idx < 8192) {
        int ks = (idx >> 7) & 15, mt = idx >> 11;
        int row = mt*16 + gid + dr, col = ks*16 + tig*2 + dc;
        float w0 = e_w1[row*256 + col], w1 = e_w1[row*256 + col + 1];
        g_W1fh[idx] = packbf(w0, w1);
        g_W1fl[idx] = packbf(w0 - bf2f(f2bf(w0)), w1 - bf2f(f2bf(w1)));
    }
    if (idx < 4608) {
        int ks = (idx >> 7) & 3, mt = idx >> 9;
        int row = mt*16 + gid + dr, col = ks*16 + tig*2 + dc;
        float w0 = e_w2[row*64 + col], w1 = e_w2[row*64 + col + 1];
        g_W2fh[idx] = packbf(w0, w1);
        g_W2fl[idx] = packbf(w0 - bf2f(f2bf(w0)), w1 - bf2f(f2bf(w1)));
    }
    {
        int idx2 = idx >> 7;
        int ks = idx2 % 18, gmt = idx2 / 18;
        int mt = gmt & 1, gg = gmt >> 1;
        int row = mt*16 + gid + dr;
        int colk = ks*16 + tig*2 + dc;
        int t = colk >> 5, ci = colk & 31;
        const float* wb = key_w + ((size_t)(gg*32 + row)*32 + ci)*9 + t;
        float w0 = wb[0], w1 = wb[9];
        g_KWfh[idx] = packbf(w0, w1);
        g_KWfl[idx] = packbf(w0 - bf2f(f2bf(w0)), w1 - bf2f(f2bf(w1)));
    }
}

// ---------------- K1: grouped 3x3 conv + ReLU via warp MMA ----------------
__global__ void __launch_bounds__(384) k1_mma(const float* __restrict__ x) {
    __shared__ float xs[32 * 294];
    int h = blockIdx.x, g = blockIdx.y, b = blockIdx.z;
    int tid = threadIdx.x, wid = tid >> 5, lane = tid & 31;
    for (int idx = tid; idx < 32 * 294; idx += 384) {
        int ci = idx / 294, rem = idx % 294, r = rem / 98, col = rem % 98;
        int hh = h + r - 1, wc = col - 1;
        float v = 0.f;
        if ((unsigned)hh < 96u && (unsigned)wc < 96u)
            v = x[(b*128 + g*32 + ci) * HW + hh*96 + wc];
        xs[idx] = v;
    }
    __syncthreads();

    int gid = lane >> 2, tig = lane & 3;
    int nbase = wid*8 + gid;
    float acc0[4] = {0.f,0.f,0.f,0.f};
    float acc1[4] = {0.f,0.f,0.f,0.f};
    const uint4* AH = (const uint4*)g_KWfh + (size_t)g*2*18*32;
    const uint4* AL = (const uint4*)g_KWfl + (size_t)g*2*18*32;

#pragma unroll
    for (int ks = 0; ks < 18; ks++) {
        const int t = ks >> 1, cib = (ks & 1) * 16;
        const int r = t / 3, c = t - 3*r;
        int ci0 = cib + tig*2;
        const float* base = xs + r*98 + nbase + c;
        float v0 = base[ ci0      *294];
        float v1 = base[(ci0 + 1) *294];
        float v2 = base[(ci0 + 8) *294];
        float v3 = base[(ci0 + 9) *294];
        u32 bh0 = packbf(v0, v1), bh1 = packbf(v2, v3);
        u32 bl0 = packbf(v0 - bf2f(f2bf(v0)), v1 - bf2f(f2bf(v1)));
        u32 bl1 = packbf(v2 - bf2f(f2bf(v2)), v3 - bf2f(f2bf(v3)));
        uint4 ah0 = AH[(0*18 + ks)*32 + lane];
        uint4 al0 = AL[(0*18 + ks)*32 + lane];
        uint4 ah1 = AH[(1*18 + ks)*32 + lane];
        uint4 al1 = AL[(1*18 + ks)*32 + lane];
        mma_bf16(acc0, ah0.x, ah0.y, ah0.z, ah0.w, bh0, bh1);
        mma_bf16(acc0, ah0.x, ah0.y, ah0.z, ah0.w, bl0, bl1);
        mma_bf16(acc0, al0.x, al0.y, al0.z, al0.w, bh0, bh1);
        mma_bf16(acc1, ah1.x, ah1.y, ah1.z, ah1.w, bh0, bh1);
        mma_bf16(acc1, ah1.x, ah1.y, ah1.z, ah1.w, bl0, bl1);
        mma_bf16(acc1, al1.x, al1.y, al1.z, al1.w, bh0, bh1);
    }

    int n0 = wid*8 + tig*2;
    {
        int co = g*32 + gid;
        float* p = g_k + (size_t)(b*128 + co)*HW + h*96 + n0;
        *(float2*)p            = make_float2(fmaxf(acc0[0],0.f), fmaxf(acc0[1],0.f));
        *(float2*)(p + 8*HW)   = make_float2(fmaxf(acc0[2],0.f), fmaxf(acc0[3],0.f));
        float* q = p + 16*HW;
        *(float2*)q            = make_float2(fmaxf(acc1[0],0.f), fmaxf(acc1[1],0.f));
        *(float2*)(q + 8*HW)   = make_float2(fmaxf(acc1[2],0.f), fmaxf(acc1[3],0.f));
    }
}

// ---------------- K2: fused embed GEMMs + value GEMM + GN partials ----------------
#define K2_SMEM (33280 + 32768)
__global__ void __launch_bounds__(256, 2) k2_mma(const float* __restrict__ x,
                                                 const float* __restrict__ e_b2) {
    extern __shared__ float sm[];
    float* xs = sm;
    u32* bh = (u32*)(sm + 8320);
    u32* bl = bh + 4096;
    const u64* bh64 = (const u64*)bh;
    const u64* bl64 = (const u64*)bl;
    int tid = threadIdx.x, wid = tid >> 5, lane = tid & 31;
    int gid = lane >> 2, tig = lane & 3;
    int pb = blockIdx.x * 128, b = pb / HW, hw0 = pb % HW;
    const float* xb = x   + (size_t)b*128*HW + hw0;
    const float* kb = g_k + (size_t)b*128*HW + hw0;

    int mt1 = wid & 3, ng = wid >> 2;
    float acc[8][4];
#pragma unroll
    for (int i = 0; i < 8; i++)
#pragma unroll
        for (int j = 0; j < 4; j++) acc[i][j] = 0.f;

    {
        float accv[16][4];
#pragma unroll
        for (int i = 0; i < 16; i++)
#pragma unroll
            for (int j = 0; j < 4; j++) accv[i][j] = 0.f;

        for (int kc = 0; kc < 2; kc++) {
            const float* src = xb + (size_t)kc*64*HW;
            for (int i = tid; i < 64*64; i += 256) {
                int k = i >> 6, n = (i & 63) * 2;
                float2 v = *(const float2*)(src + (size_t)k*HW + n);
                xs[k*130 + n] = v.x; xs[k*130 + n + 1] = v.y;
            }
            __syncthreads();
            for (int i = tid; i < 2048; i += 256) {
                int l2 = i & 31, nt = (i >> 5) & 15, ks = i >> 9;
                int g2 = l2 >> 2, t2 = l2 & 3;
                int n = nt*8 + g2, k = ks*16 + t2*2;
                float f0 = xs[k*130 + n],     f1 = xs[(k+1)*130 + n];
                float f2 = xs[(k+8)*130 + n], f3 = xs[(k+9)*130 + n];
                int base = i * 2;
                bh[base]     = packbf(f0, f1);
                bh[base + 1] = packbf(f2, f3);
                bl[base]     = packbf(f0 - bf2f(f2bf(f0)), f1 - bf2f(f2bf(f1)));
                bl[base + 1] = packbf(f2 - bf2f(f2bf(f2)), f3 - bf2f(f2bf(f3)));
            }
            __syncthreads();
#pragma unroll
            for (int ks = 0; ks < 4; ks++) {
                int gks = kc*4 + ks;
                uint4 ah = ((const uint4*)g_W1fh)[(mt1*16 + gks)*32 + lane];
                uint4 al = ((const uint4*)g_W1fl)[(mt1*16 + gks)*32 + lane];
#pragma unroll
                for (int nt2 = 0; nt2 < 8; nt2++) {
                    int nt = ng*8 + nt2;
                    int base = (ks*16 + nt)*32 + lane;
                    mma3(acc[nt2], ah, al, bh64[base], bl64[base]);
                }
                uint4 vh = ((const uint4*)g_Afh)[(wid*8 + gks)*32 + lane];
                uint4 vl = ((const uint4*)g_Afl)[(wid*8 + gks)*32 + lane];
#pragma unroll
                for (int nt = 0; nt < 16; nt++) {
                    int base = (ks*16 + nt)*32 + lane;
                    mma3(accv[nt], vh, vl, bh64[base], bl64[base]);
                }
            }
            __syncthreads();
        }
        int m0 = wid*16 + gid;
        float* vb0 = g_v + (size_t)(b*128 + m0)*HW + hw0 + tig*2;
        float* vb1 = vb0 + (size_t)8*HW;
#pragma unroll
        for (int nt = 0; nt < 16; nt++) {
            *(float2*)(vb0 + nt*8) = make_float2(accv[nt][0], accv[nt][1]);
            *(float2*)(vb1 + nt*8) = make_float2(accv[nt][2], accv[nt][3]);
        }
    }

    for (int kc = 2; kc < 4; kc++) {
        const float* src = kb + (size_t)(kc-2)*64*HW;
        for (int i = tid; i < 64*64; i += 256) {
            int k = i >> 6, n = (i & 63) * 2;
            float2 v = *(const float2*)(src + (size_t)k*HW + n);
            xs[k*130 + n] = v.x; xs[k*130 + n + 1] = v.y;
        }
        __syncthreads();
        for (int i = tid; i < 2048; i += 256) {
            int l2 = i & 31, nt = (i >> 5) & 15, ks = i >> 9;
            int g2 = l2 >> 2, t2 = l2 & 3;
            int n = nt*8 + g2, k = ks*16 + t2*2;
            float f0 = xs[k*130 + n],     f1 = xs[(k+1)*130 + n];
            float f2 = xs[(k+8)*130 + n], f3 = xs[(k+9)*130 + n];
            int base = i * 2;
            bh[base]     = packbf(f0, f1);
            bh[base + 1] = packbf(f2, f3);
            bl[base]     = packbf(f0 - bf2f(f2bf(f0)), f1 - bf2f(f2bf(f1)));
            bl[base + 1] = packbf(f2 - bf2f(f2bf(f2)), f3 - bf2f(f2bf(f3)));
        }
        __syncthreads();
#pragma unroll
        for (int ks = 0; ks < 4; ks++) {
            int gks = kc*4 + ks;
            uint4 ah = ((const uint4*)g_W1fh)[(mt1*16 + gks)*32 + lane];
            uint4 al = ((const uint4*)g_W1fl)[(mt1*16 + gks)*32 + lane];
#pragma unroll
            for (int nt2 = 0; nt2 < 8; nt2++) {
                int nt = ng*8 + nt2;
                int base = (ks*16 + nt)*32 + lane;
                mma3(acc[nt2], ah, al, bh64[base], bl64[base]);
            }
        }
        __syncthreads();
    }

#pragma unroll
    for (int nt2 = 0; nt2 < 8; nt2++) {
        int n0 = (ng*8 + nt2)*8 + tig*2;
        int r0 = mt1*16 + gid;
        xs[r0*130 + n0]       = fmaxf(acc[nt2][0], 0.f);
        xs[r0*130 + n0 + 1]   = fmaxf(acc[nt2][1], 0.f);
        xs[(r0+8)*130 + n0]   = fmaxf(acc[nt2][2], 0.f);
        xs[(r0+8)*130 + n0+1] = fmaxf(acc[nt2][3], 0.f);
    }
    __syncthreads();

    for (int i = tid; i < 2048; i += 256) {
        int l2 = i & 31, nt = (i >> 5) & 15, ks = i >> 9;
        int g2 = l2 >> 2, t2 = l2 & 3;
        int n = nt*8 + g2, k = ks*16 + t2*2;
        float f0 = xs[k*130 + n],     f1 = xs[(k+1)*130 + n];
        float f2 = xs[(k+8)*130 + n], f3 = xs[(k+9)*130 + n];
        int base = i * 2;
        bh[base]     = packbf(f0, f1);
        bh[base + 1] = packbf(f2, f3);
        bl[base]     = packbf(f0 - bf2f(f2bf(f0)), f1 - bf2f(f2bf(f1)));
        bl[base + 1] = packbf(f2 - bf2f(f2bf(f2)), f3 - bf2f(f2bf(f3)));
    }
    __syncthreads();

    float acc2[16][4];
    float acc3[2][4];
#pragma unroll
    for (int i = 0; i < 16; i++)
#pragma unroll
        for (int j = 0; j < 4; j++) acc2[i][j] = 0.f;
#pragma unroll
    for (int i = 0; i < 2; i++)
#pragma unroll
        for (int j = 0; j < 4; j++) acc3[i][j] = 0.f;

#pragma unroll
    for (int ks = 0; ks < 4; ks++) {
        uint4 ah  = ((const uint4*)g_W2fh)[(wid*4 + ks)*32 + lane];
        uint4 al  = ((const uint4*)g_W2fl)[(wid*4 + ks)*32 + lane];
        uint4 ah8 = ((const uint4*)g_W2fh)[(8*4 + ks)*32 + lane];
        uint4 al8 = ((const uint4*)g_W2fl)[(8*4 + ks)*32 + lane];
#pragma unroll
        for (int nt = 0; nt < 16; nt++) {
            int base = (ks*16 + nt)*32 + lane;
            mma3(acc2[nt], ah, al, bh64[base], bl64[base]);
        }
#pragma unroll
        for (int j = 0; j < 2; j++) {
            int nt = wid*2 + j;
            int base = (ks*16 + nt)*32 + lane;
            mma3(acc3[j], ah8, al8, bh64[base], bl64[base]);
        }
    }
    __syncthreads();

    {
        float* fsc = (float*)bh;
        int m0 = wid*16 + gid;
        float bias0 = __ldg(&e_b2[m0]), bias1 = __ldg(&e_b2[m0 + 8]);
        float* p0 = g_wpre + (size_t)(b*144 + m0)*HW + hw0 + tig*2;
        float* p1 = p0 + (size_t)8*HW;
        float s0 = 0.f, q0 = 0.f, s1 = 0.f, q1 = 0.f;
#pragma unroll
        for (int nt = 0; nt < 16; nt++) {
            float t0 = acc2[nt][0] + bias0, t1 = acc2[nt][1] + bias0;
            float t2 = acc2[nt][2] + bias1, t3 = acc2[nt][3] + bias1;
            *(float2*)(p0 + nt*8) = make_float2(t0, t1);
            *(float2*)(p1 + nt*8) = make_float2(t2, t3);
            s0 += t0 + t1; q0 += t0*t0 + t1*t1;
            s1 += t2 + t3; q1 += t2*t2 + t3*t3;
        }
        int m8 = 128 + gid;
        float bias2 = __ldg(&e_b2[m8]), bias3 = __ldg(&e_b2[m8 + 8]);
        float* q0p = g_wpre + (size_t)(b*144 + m8)*HW + hw0 + tig*2;
        float* q1p = q0p + (size_t)8*HW;
        float s2 = 0.f, q2 = 0.f, s3 = 0.f, q3 = 0.f;
#pragma unroll
        for (int j = 0; j < 2; j++) {
            int nt = wid*2 + j;
            float t0 = acc3[j][0] + bias2, t1 = acc3[j][1] + bias2;
            float t2 = acc3[j][2] + bias3, t3 = acc3[j][3] + bias3;
            *(float2*)(q0p + nt*8) = make_float2(t0, t1);
            *(float2*)(q1p + nt*8) = make_float2(t2, t3);
            s2 += t0 + t1; q2 += t0*t0 + t1*t1;
            s3 += t2 + t3; q3 += t2*t2 + t3*t3;
        }
#pragma unroll
        for (int off = 1; off < 4; off <<= 1) {
            s0 += __shfl_down_sync(0xffffffffu, s0, off, 4);
            q0 += __shfl_down_sync(0xffffffffu, q0, off, 4);
            s1 += __shfl_down_sync(0xffffffffu, s1, off, 4);
            q1 += __shfl_down_sync(0xffffffffu, q1, off, 4);
            s2 += __shfl_down_sync(0xffffffffu, s2, off, 4);
            q2 += __shfl_down_sync(0xffffffffu, q2, off, 4);
            s3 += __shfl_down_sync(0xffffffffu, s3, off, 4);
            q3 += __shfl_down_sync(0xffffffffu, q3, off, 4);
        }
        if (tig == 0) {
            int blk = blockIdx.x;
            g_gnS2[m0*576 + blk]       = s0;
            g_gnQ2[m0*576 + blk]       = q0;
            g_gnS2[(m0+8)*576 + blk]   = s1;
            g_gnQ2[(m0+8)*576 + blk]   = q1;
            float* f = fsc + (wid*8 + gid)*4;
            f[0] = s2; f[1] = q2; f[2] = s3; f[3] = q3;
        }
        __syncthreads();
        if (tid < 16) {
            int g2 = tid & 7, sel = tid >> 3;
            float ss = 0.f, qq = 0.f;
#pragma unroll
            for (int wp = 0; wp < 8; wp++) {
                const float* f = fsc + (wp*8 + g2)*4 + sel*2;
                ss += f[0]; qq += f[1];
            }
            int ch = 128 + sel*8 + g2;
            g_gnS2[ch*576 + blockIdx.x] = ss;
            g_gnQ2[ch*576 + blockIdx.x] = qq;
        }
    }
}

// ---------------- K4: GN finalize from k2 partials ----------------
__global__ void k4_gn2() {
    __shared__ float rs[256], rq[256];
    int bg = blockIdx.x, b = bg >> 4, g = bg & 15;
    int tid = threadIdx.x;
    float s = 0.f, q = 0.f;
    for (int idx = tid; idx < 9*72; idx += 256) {
        int t = idx / 72, i = idx % 72;
        int ch = g*9 + t;
        s += g_gnS2[ch*576 + b*72 + i];
        q += g_gnQ2[ch*576 + b*72 + i];
    }
    rs[tid] = s; rq[tid] = q;
    __syncthreads();
    for (int o = 128; o > 0; o >>= 1) {
        if (tid < o) { rs[tid] += rs[tid+o]; rq[tid] += rq[tid+o]; }
        __syncthreads();
    }
    if (tid == 0) {
        float inv = 1.f / (9.f*HW);
        float mean = rs[0] * inv;
        float var  = rq[0] * inv - mean*mean;
        g_gn[bg*2]     = mean;
        g_gn[bg*2 + 1] = rsqrtf(var + 1e-5f);
    }
}

// ---------------- K5: local dynamic conv + BN partials ----------------
#define K5_SMEM ((6912 + 7840 + 192) * 4)
__global__ void __launch_bounds__(384) k5_local(const float* __restrict__ gn_g,
                                                const float* __restrict__ gn_b) {
    extern __shared__ float sm5[];
    float* wn  = sm5;
    float* vs  = sm5 + 6912;
    float* red = sm5 + 6912 + 7840;
    int h0 = blockIdx.x * 8, g = blockIdx.y, b = blockIdx.z;
    int tid = threadIdx.x;
    float mean = g_gn[(b*16 + g)*2], rstd = g_gn[(b*16 + g)*2 + 1];

    for (int idx = tid; idx < 6912; idx += 384) {
        int t = idx / 768, rem = idx % 768;
        int ch = g*9 + t;
        float raw = g_wpre[(size_t)(b*144 + ch)*HW + h0*96 + rem];
        wn[idx] = (raw - mean) * rstd * __ldg(&gn_g[ch]) + __ldg(&gn_b[ch]);
    }
    for (int idx = tid; idx < 7840; idx += 384) {
        int s = idx / 980, rem = idx % 980, r = rem / 98, col = rem % 98;
        int hh = h0 + r - 1, wc = col - 1;
        float v = 0.f;
        if ((unsigned)hh < 96u && (unsigned)wc < 96u)
            v = g_v[(size_t)(b*128 + g*8 + s)*HW + hh*96 + wc];
        vs[idx] = v;
    }
    __syncthreads();

    int w = tid % 96, rq = tid / 96;
    int lane = tid & 31, warp = tid >> 5;
#pragma unroll
    for (int s = 0; s < 8; s++) {
        float p1 = 0.f, p2 = 0.f;
        const float* vb = vs + s*980;
#pragma unroll
        for (int rr = 0; rr < 2; rr++) {
            int row = rq*2 + rr;
            float acc = 0.f;
#pragma unroll
            for (int dr = 0; dr < 3; dr++)
#pragma unroll
                for (int dc = 0; dc < 3; dc++)
                    acc += vb[(row+dr)*98 + w + dc] * wn[(dr*3+dc)*768 + row*96 + w];
            g_ypre[(size_t)(b*128 + g*8 + s)*HW + (h0+row)*96 + w] = acc;
            p1 += acc; p2 += acc*acc;
        }
        for (int off = 16; off; off >>= 1) {
            p1 += __shfl_down_sync(0xffffffffu, p1, off);
            p2 += __shfl_down_sync(0xffffffffu, p2, off);
        }
        if (lane == 0) { red[warp*16 + s*2] = p1; red[warp*16 + s*2 + 1] = p2; }
    }
    __syncthreads();
    if (tid < 8) {
        float s1 = 0.f, s2 = 0.f;
#pragma unroll
        for (int wp = 0; wp < 12; wp++) {
            s1 += red[wp*16 + tid*2];
            s2 += red[wp*16 + tid*2 + 1];
        }
        int c = g*8 + tid;
        g_bnS[c*96 + b*12 + blockIdx.x] = s1;
        g_bnQ[c*96 + b*12 + blockIdx.x] = s2;
    }
}

// ---------------- K6: BN finalize ----------------
__global__ void k6_bn() {
    __shared__ float rs[96], rq[96];
    int c = blockIdx.x, tid = threadIdx.x;
    if (tid < 96) { rs[tid] = g_bnS[c*96 + tid]; rq[tid] = g_bnQ[c*96 + tid]; }
    __syncthreads();
    if (tid < 32) {
        float s = rs[tid] + rs[tid+32] + rs[tid+64];
        float q = rq[tid] + rq[tid+32] + rq[tid+64];
        for (int off = 16; off; off >>= 1) {
            s += __shfl_down_sync(0xffffffffu, s, off);
            q += __shfl_down_sync(0xffffffffu, q, off);
        }
        if (tid == 0) {
            float inv = 1.f / (float)PTOT;
            float mean = s * inv;
            float var  = q * inv - mean*mean;
            g_bn[c*2]     = mean;
            g_bn[c*2 + 1] = rsqrtf(var + 1e-5f);
        }
    }
}

// ---------------- K7: GAP partials ----------------
__global__ void k7_gap(const float* __restrict__ bn_g, const float* __restrict__ bn_b) {
    __shared__ float rs[256];
    int c = blockIdx.x, b = blockIdx.y;
    float mean = g_bn[c*2], rstd = g_bn[c*2 + 1];
    float gg = __ldg(&bn_g[c]), bb = __ldg(&bn_b[c]);
    const float4* yb = (const float4*)(g_ypre + (size_t)(b*128 + c)*HW);
    const float4* kb = (const float4*)(g_k    + (size_t)(b*128 + c)*HW);
    float s = 0.f;
    for (int idx = threadIdx.x; idx < HW/4; idx += 256) {
        float4 yp = yb[idx];
        float4 kv = kb[idx];
        float t0 = (yp.x - mean) * rstd * gg + bb;
        float t1 = (yp.y - mean) * rstd * gg + bb;
        float t2 = (yp.z - mean) * rstd * gg + bb;
        float t3 = (yp.w - mean) * rstd * gg + bb;
        s += t0 * __frcp_rn(1.f + __expf(-t0)) + kv.x;
        s += t1 * __frcp_rn(1.f + __expf(-t1)) + kv.y;
        s += t2 * __frcp_rn(1.f + __expf(-t2)) + kv.z;
        s += t3 * __frcp_rn(1.f + __expf(-t3)) + kv.w;
    }
    rs[threadIdx.x] = s;
    __syncthreads();
    for (int o = 128; o > 0; o >>= 1) {
        if (threadIdx.x < o) rs[threadIdx.x] += rs[threadIdx.x + o];
        __syncthreads();
    }
    if (threadIdx.x == 0) g_gap[b*128 + c] = rs[0] * (1.f / (float)HW);
}

// ---------------- K8: SE MLP + radix softmax ----------------
__global__ void k8_se(const float* __restrict__ w1, const float* __restrict__ b1,
                      const float* __restrict__ w2, const float* __restrict__ b2) {
    __shared__ float gaps[128], a1s[64], a2s[256];
    int b = blockIdx.x, tid = threadIdx.x;
    if (tid < 128) gaps[tid] = g_gap[b*128 + tid];
    __syncthreads();
    if (tid < 64) {
        float s = __ldg(&b1[tid]);
        for (int c = 0; c < 128; c++) s += __ldg(&w1[tid*128 + c]) * gaps[c];
        a1s[tid] = fmaxf(s, 0.f);
    }
    __syncthreads();
    {
        float s = __ldg(&b2[tid]);
        for (int j = 0; j < 64; j++) s += __ldg(&w2[tid*64 + j]) * a1s[j];
        a2s[tid] = s;
    }
    __syncthreads();
    if (tid < 128) {
        float e0 = a2s[tid*2], e1 = a2s[tid*2 + 1];
        float m = fmaxf(e0, e1);
        float p0 = expf(e0 - m), p1 = expf(e1 - m);
        float d = p0 + p1;
        g_a[(b*128 + tid)*2]     = p0 / d;
        g_a[(b*128 + tid)*2 + 1] = p1 / d;
    }
}

// ---------------- K9: final mix ----------------
__global__ void k9_out(float* __restrict__ out, const float* __restrict__ bn_g,
                       const float* __restrict__ bn_b) {
    int idx = blockIdx.x * 256 + threadIdx.x;
    int bc = idx / 2304;
    int c = bc & 127;
    float mean = g_bn[c*2], rstd = g_bn[c*2 + 1];
    float gg = __ldg(&bn_g[c]), bb = __ldg(&bn_b[c]);
    float a0 = g_a[bc*2], a1 = g_a[bc*2 + 1];
    const float4 yp = ((const float4*)g_ypre)[idx];
    const float4 kv = ((const float4*)g_k)[idx];
    float t0 = (yp.x - mean) * rstd * gg + bb;
    float t1 = (yp.y - mean) * rstd * gg + bb;
    float t2 = (yp.z - mean) * rstd * gg + bb;
    float t3 = (yp.w - mean) * rstd * gg + bb;
    float y0 = t0 * __frcp_rn(1.f + __expf(-t0));
    float y1 = t1 * __frcp_rn(1.f + __expf(-t1));
    float y2 = t2 * __frcp_rn(1.f + __expf(-t2));
    float y3 = t3 * __frcp_rn(1.f + __expf(-t3));
    ((float4*)out)[idx] = make_float4(y0*a0 + kv.x*a1, y1*a0 + kv.y*a1,
                                      y2*a0 + kv.z*a1, y3*a0 + kv.w*a1);
}

// ---------------- launch ----------------
extern "C" void kernel_launch(void* const* d_in, const int* in_sizes, int n_in,
                              void* d_out, int out_size) {
    const float* x     = (const float*)d_in[0];
    const float* key_w = (const float*)d_in[1];
    const float* e_w1  = (const float*)d_in[2];
    const float* e_w2  = (const float*)d_in[3];
    const float* e_b2  = (const float*)d_in[4];
    const float* gn_g  = (const float*)d_in[5];
    const float* gn_b  = (const float*)d_in[6];
    const float* c1_w  = (const float*)d_in[7];
    const float* bn_g  = (const float*)d_in[8];
    const float* bn_b  = (const float*)d_in[9];
    const float* se_w1 = (const float*)d_in[10];
    const float* se_b1 = (const float*)d_in[11];
    const float* se_w2 = (const float*)d_in[12];
    const float* se_b2 = (const float*)d_in[13];
    float* out = (float*)d_out;

    cudaFuncSetAttribute(k2_mma,   cudaFuncAttributeMaxDynamicSharedMemorySize, K2_SMEM);
    cudaFuncSetAttribute(k5_local, cudaFuncAttributeMaxDynamicSharedMemorySize, K5_SMEM);

    k0_prep <<<72, 256>>>(e_w1, c1_w, e_w2, key_w);
    k1_mma  <<<dim3(96, 4, 8), 384>>>(x);
    kdummy  <<<1, 32>>>();                        // positions k2 at ncu capture slot 4
    k2_mma  <<<PTOT/128, 256, K2_SMEM>>>(x, e_b2);
    k4_gn2  <<<128, 256>>>();
    k5_local<<<dim3(12, 16, 8), 384, K5_SMEM>>>(gn_g, gn_b);
    k6_bn   <<<128, 128>>>();
    k7_gap  <<<dim3(128, 8), 256>>>(bn_g, bn_b);
    k8_se   <<<8, 256>>>(se_w1, se_b1, se_w2, se_b2);
    k9_out  <<<PTOT*128/(256*4), 256>>>(out, bn_g, bn_b);
}

// round 13
// speedup vs baseline: 2.0053x; 1.0151x over previous
#include <cuda_runtime.h>
#include <cuda_bf16.h>
#include <math.h>
#include <stdint.h>

#define BB 8
#define CC 128
#define HH 96
#define WW 96
#define HW 9216            // 96*96
#define WC 144             // k*k*DIM/SP
#define PTOT (BB*HW)       // 73728

typedef unsigned long long u64;
typedef unsigned int u32;
typedef unsigned short u16;

__device__ __forceinline__ u16 f2bf(float f) {
    return __bfloat16_as_ushort(__float2bfloat16(f));
}
__device__ __forceinline__ float bf2f(u16 u) {
    return __bfloat162float(__ushort_as_bfloat16(u));
}
__device__ __forceinline__ u32 packbf(float a, float b) {
    return (u32)f2bf(a) | ((u32)f2bf(b) << 16);
}
// pack one value as {hi16, lo16}
__device__ __forceinline__ u32 packhl(float v) {
    u16 hi = f2bf(v);
    u16 lo = f2bf(v - bf2f(hi));
    return (u32)hi | ((u32)lo << 16);
}

// m16n8k16 bf16 MMA, fp32 accumulate
__device__ __forceinline__ void mma_bf16(float* c, u32 a0, u32 a1, u32 a2, u32 a3,
                                         u32 b0, u32 b1) {
    asm volatile(
        "mma.sync.aligned.m16n8k16.row.col.f32.bf16.bf16.f32 "
        "{%0,%1,%2,%3}, {%4,%5,%6,%7}, {%8,%9}, {%0,%1,%2,%3};"
        : "+f"(c[0]), "+f"(c[1]), "+f"(c[2]), "+f"(c[3])
        : "r"(a0), "r"(a1), "r"(a2), "r"(a3), "r"(b0), "r"(b1));
}
// 3-term bf16-split MMA from packed u64 fragment pairs
__device__ __forceinline__ void mma3(float* c, const uint4& ah, const uint4& al,
                                     u64 bhp, u64 blp) {
    u32 bh0 = (u32)bhp, bh1 = (u32)(bhp >> 32);
    u32 bl0 = (u32)blp, bl1 = (u32)(blp >> 32);
    mma_bf16(c, ah.x, ah.y, ah.z, ah.w, bh0, bh1);
    mma_bf16(c, ah.x, ah.y, ah.z, ah.w, bl0, bl1);
    mma_bf16(c, al.x, al.y, al.z, al.w, bh0, bh1);
}

// ---------------- scratch ----------------
__device__ float g_k   [BB*CC*HW];
__device__ float g_v   [BB*CC*HW];
__device__ float g_wpre[BB*WC*HW];
__device__ float g_ypre[BB*CC*HW];
__device__ __align__(16) u32 g_Afh [8192];    // c1_w:  [mt8][ks8][lane32][4]
__device__ __align__(16) u32 g_Afl [8192];
__device__ __align__(16) u32 g_W1fh[8192];    // e_w1:  [mt4][ks16][lane32][4]
__device__ __align__(16) u32 g_W1fl[8192];
__device__ __align__(16) u32 g_W2fh[4608];    // e_w2:  [mt9][ks4][lane32][4]
__device__ __align__(16) u32 g_W2fl[4608];
__device__ __align__(16) u32 g_KWfh[18432];   // key_w: [g4][mt2][ks18][lane32][4]
__device__ __align__(16) u32 g_KWfl[18432];
__device__ float g_gnS2[144*576];
__device__ float g_gnQ2[144*576];
__device__ float g_gn  [128*2];
__device__ float g_bnS [128*96];
__device__ float g_bnQ [128*96];
__device__ float g_bn  [128*2];
__device__ float g_gap [BB*CC];
__device__ float g_a   [BB*CC*2];
__device__ int   g_sink;

// ---------------- dummy (slots k2 into ncu capture position 4) ----------------
__global__ void kdummy() {
    if (threadIdx.x == 1024) g_sink = 1;
}

// ---------------- K0: weight prep ----------------
__global__ void k0_prep(const float* __restrict__ e_w1, const float* __restrict__ c1_w,
                        const float* __restrict__ e_w2, const float* __restrict__ key_w) {
    int idx = blockIdx.x * 256 + threadIdx.x;   // 0..18431
    int r = idx & 3, lane = (idx >> 2) & 31;
    int gid = lane >> 2, tig = lane & 3;
    int dr = (r & 1) * 8, dc = (r & 2) * 4;
    if (idx < 8192) {
        int ks = (idx >> 7) & 7, mt = idx >> 10;
        int row = mt*16 + gid + dr, col = ks*16 + tig*2 + dc;
        float w0 = c1_w[row*128 + col], w1 = c1_w[row*128 + col + 1];
        g_Afh[idx] = packbf(w0, w1);
        g_Afl[idx] = packbf(w0 - bf2f(f2bf(w0)), w1 - bf2f(f2bf(w1)));
    }
    if (idx < 8192) {
        int ks = (idx >> 7) & 15, mt = idx >> 11;
        int row = mt*16 + gid + dr, col = ks*16 + tig*2 + dc;
        float w0 = e_w1[row*256 + col], w1 = e_w1[row*256 + col + 1];
        g_W1fh[idx] = packbf(w0, w1);
        g_W1fl[idx] = packbf(w0 - bf2f(f2bf(w0)), w1 - bf2f(f2bf(w1)));
    }
    if (idx < 4608) {
        int ks = (idx >> 7) & 3, mt = idx >> 9;
        int row = mt*16 + gid + dr, col = ks*16 + tig*2 + dc;
        float w0 = e_w2[row*64 + col], w1 = e_w2[row*64 + col + 1];
        g_W2fh[idx] = packbf(w0, w1);
        g_W2fl[idx] = packbf(w0 - bf2f(f2bf(w0)), w1 - bf2f(f2bf(w1)));
    }
    {
        int idx2 = idx >> 7;
        int ks = idx2 % 18, gmt = idx2 / 18;
        int mt = gmt & 1, gg = gmt >> 1;
        int row = mt*16 + gid + dr;
        int colk = ks*16 + tig*2 + dc;
        int t = colk >> 5, ci = colk & 31;
        const float* wb = key_w + ((size_t)(gg*32 + row)*32 + ci)*9 + t;
        float w0 = wb[0], w1 = wb[9];
        g_KWfh[idx] = packbf(w0, w1);
        g_KWfl[idx] = packbf(w0 - bf2f(f2bf(w0)), w1 - bf2f(f2bf(w1)));
    }
}

// ---------------- K1: grouped 3x3 conv + ReLU via warp MMA (pre-packed staging) ----------------
__global__ void __launch_bounds__(384) k1_mma(const float* __restrict__ x) {
    __shared__ u32 xs[32 * 294];   // {bf16hi, bf16lo} packed per value
    int h = blockIdx.x, g = blockIdx.y, b = blockIdx.z;
    int tid = threadIdx.x, wid = tid >> 5, lane = tid & 31;
    for (int idx = tid; idx < 32 * 294; idx += 384) {
        int ci = idx / 294, rem = idx % 294, r = rem / 98, col = rem % 98;
        int hh = h + r - 1, wc = col - 1;
        float v = 0.f;
        if ((unsigned)hh < 96u && (unsigned)wc < 96u)
            v = x[(b*128 + g*32 + ci) * HW + hh*96 + wc];
        xs[idx] = packhl(v);
    }
    __syncthreads();

    int gid = lane >> 2, tig = lane & 3;
    int nbase = wid*8 + gid;
    float acc0[4] = {0.f,0.f,0.f,0.f};
    float acc1[4] = {0.f,0.f,0.f,0.f};
    const uint4* AH = (const uint4*)g_KWfh + (size_t)g*2*18*32;
    const uint4* AL = (const uint4*)g_KWfl + (size_t)g*2*18*32;

#pragma unroll
    for (int ks = 0; ks < 18; ks++) {
        const int t = ks >> 1, cib = (ks & 1) * 16;
        const int r = t / 3, c = t - 3*r;
        int ci0 = cib + tig*2;
        const u32* base = xs + r*98 + nbase + c;
        u32 p0 = base[ ci0      *294];
        u32 p1 = base[(ci0 + 1) *294];
        u32 p2 = base[(ci0 + 8) *294];
        u32 p3 = base[(ci0 + 9) *294];
        u32 bh0 = __byte_perm(p0, p1, 0x5410);
        u32 bh1 = __byte_perm(p2, p3, 0x5410);
        u32 bl0 = __byte_perm(p0, p1, 0x7632);
        u32 bl1 = __byte_perm(p2, p3, 0x7632);
        uint4 ah0 = AH[(0*18 + ks)*32 + lane];
        uint4 al0 = AL[(0*18 + ks)*32 + lane];
        uint4 ah1 = AH[(1*18 + ks)*32 + lane];
        uint4 al1 = AL[(1*18 + ks)*32 + lane];
        mma_bf16(acc0, ah0.x, ah0.y, ah0.z, ah0.w, bh0, bh1);
        mma_bf16(acc0, ah0.x, ah0.y, ah0.z, ah0.w, bl0, bl1);
        mma_bf16(acc0, al0.x, al0.y, al0.z, al0.w, bh0, bh1);
        mma_bf16(acc1, ah1.x, ah1.y, ah1.z, ah1.w, bh0, bh1);
        mma_bf16(acc1, ah1.x, ah1.y, ah1.z, ah1.w, bl0, bl1);
        mma_bf16(acc1, al1.x, al1.y, al1.z, al1.w, bh0, bh1);
    }

    int n0 = wid*8 + tig*2;
    {
        int co = g*32 + gid;
        float* p = g_k + (size_t)(b*128 + co)*HW + h*96 + n0;
        *(float2*)p            = make_float2(fmaxf(acc0[0],0.f), fmaxf(acc0[1],0.f));
        *(float2*)(p + 8*HW)   = make_float2(fmaxf(acc0[2],0.f), fmaxf(acc0[3],0.f));
        float* q = p + 16*HW;
        *(float2*)q            = make_float2(fmaxf(acc1[0],0.f), fmaxf(acc1[1],0.f));
        *(float2*)(q + 8*HW)   = make_float2(fmaxf(acc1[2],0.f), fmaxf(acc1[3],0.f));
    }
}

// ---------------- K2: fused embed GEMMs + value GEMM + GN partials ----------------
#define K2_SMEM (33280 + 32768)
__global__ void __launch_bounds__(256, 2) k2_mma(const float* __restrict__ x,
                                                 const float* __restrict__ e_b2) {
    extern __shared__ float sm[];
    float* xs = sm;
    u32* bh = (u32*)(sm + 8320);
    u32* bl = bh + 4096;
    const u64* bh64 = (const u64*)bh;
    const u64* bl64 = (const u64*)bl;
    int tid = threadIdx.x, wid = tid >> 5, lane = tid & 31;
    int gid = lane >> 2, tig = lane & 3;
    int pb = blockIdx.x * 128, b = pb / HW, hw0 = pb % HW;
    const float* xb = x   + (size_t)b*128*HW + hw0;
    const float* kb = g_k + (size_t)b*128*HW + hw0;

    int mt1 = wid & 3, ng = wid >> 2;
    float acc[8][4];
#pragma unroll
    for (int i = 0; i < 8; i++)
#pragma unroll
        for (int j = 0; j < 4; j++) acc[i][j] = 0.f;

    {
        float accv[16][4];
#pragma unroll
        for (int i = 0; i < 16; i++)
#pragma unroll
            for (int j = 0; j < 4; j++) accv[i][j] = 0.f;

        for (int kc = 0; kc < 2; kc++) {
            const float* src = xb + (size_t)kc*64*HW;
            for (int i = tid; i < 64*64; i += 256) {
                int k = i >> 6, n = (i & 63) * 2;
                float2 v = *(const float2*)(src + (size_t)k*HW + n);
                xs[k*130 + n] = v.x; xs[k*130 + n + 1] = v.y;
            }
            __syncthreads();
            for (int i = tid; i < 2048; i += 256) {
                int l2 = i & 31, nt = (i >> 5) & 15, ks = i >> 9;
                int g2 = l2 >> 2, t2 = l2 & 3;
                int n = nt*8 + g2, k = ks*16 + t2*2;
                float f0 = xs[k*130 + n],     f1 = xs[(k+1)*130 + n];
                float f2 = xs[(k+8)*130 + n], f3 = xs[(k+9)*130 + n];
                int base = i * 2;
                bh[base]     = packbf(f0, f1);
                bh[base + 1] = packbf(f2, f3);
                bl[base]     = packbf(f0 - bf2f(f2bf(f0)), f1 - bf2f(f2bf(f1)));
                bl[base + 1] = packbf(f2 - bf2f(f2bf(f2)), f3 - bf2f(f2bf(f3)));
            }
            __syncthreads();
#pragma unroll
            for (int ks = 0; ks < 4; ks++) {
                int gks = kc*4 + ks;
                uint4 ah = ((const uint4*)g_W1fh)[(mt1*16 + gks)*32 + lane];
                uint4 al = ((const uint4*)g_W1fl)[(mt1*16 + gks)*32 + lane];
#pragma unroll
                for (int nt2 = 0; nt2 < 8; nt2++) {
                    int nt = ng*8 + nt2;
                    int base = (ks*16 + nt)*32 + lane;
                    mma3(acc[nt2], ah, al, bh64[base], bl64[base]);
                }
                uint4 vh = ((const uint4*)g_Afh)[(wid*8 + gks)*32 + lane];
                uint4 vl = ((const uint4*)g_Afl)[(wid*8 + gks)*32 + lane];
#pragma unroll
                for (int nt = 0; nt < 16; nt++) {
                    int base = (ks*16 + nt)*32 + lane;
                    mma3(accv[nt], vh, vl, bh64[base], bl64[base]);
                }
            }
            __syncthreads();
        }
        int m0 = wid*16 + gid;
        float* vb0 = g_v + (size_t)(b*128 + m0)*HW + hw0 + tig*2;
        float* vb1 = vb0 + (size_t)8*HW;
#pragma unroll
        for (int nt = 0; nt < 16; nt++) {
            *(float2*)(vb0 + nt*8) = make_float2(accv[nt][0], accv[nt][1]);
            *(float2*)(vb1 + nt*8) = make_float2(accv[nt][2], accv[nt][3]);
        }
    }

    for (int kc = 2; kc < 4; kc++) {
        const float* src = kb + (size_t)(kc-2)*64*HW;
        for (int i = tid; i < 64*64; i += 256) {
            int k = i >> 6, n = (i & 63) * 2;
            float2 v = *(const float2*)(src + (size_t)k*HW + n);
            xs[k*130 + n] = v.x; xs[k*130 + n + 1] = v.y;
        }
        __syncthreads();
        for (int i = tid; i < 2048; i += 256) {
            int l2 = i & 31, nt = (i >> 5) & 15, ks = i >> 9;
            int g2 = l2 >> 2, t2 = l2 & 3;
            int n = nt*8 + g2, k = ks*16 + t2*2;
            float f0 = xs[k*130 + n],     f1 = xs[(k+1)*130 + n];
            float f2 = xs[(k+8)*130 + n], f3 = xs[(k+9)*130 + n];
            int base = i * 2;
            bh[base]     = packbf(f0, f1);
            bh[base + 1] = packbf(f2, f3);
            bl[base]     = packbf(f0 - bf2f(f2bf(f0)), f1 - bf2f(f2bf(f1)));
            bl[base + 1] = packbf(f2 - bf2f(f2bf(f2)), f3 - bf2f(f2bf(f3)));
        }
        __syncthreads();
#pragma unroll
        for (int ks = 0; ks < 4; ks++) {
            int gks = kc*4 + ks;
            uint4 ah = ((const uint4*)g_W1fh)[(mt1*16 + gks)*32 + lane];
            uint4 al = ((const uint4*)g_W1fl)[(mt1*16 + gks)*32 + lane];
#pragma unroll
            for (int nt2 = 0; nt2 < 8; nt2++) {
                int nt = ng*8 + nt2;
                int base = (ks*16 + nt)*32 + lane;
                mma3(acc[nt2], ah, al, bh64[base], bl64[base]);
            }
        }
        __syncthreads();
    }

    // ---- stage-1 epilogue: ReLU + convert + write DIRECTLY into fragment buffers ----
    // value (r, n): r = mt1*16 + gid + (j>=2)*8; n = (ng*8+nt2)*8 + tig*2 + (j&1)
    // frag slot: u32idx = ((mt1*16 + nt)*32 + (g2*4 + t2))*2 + sel;  u16 half = gid&1
    {
        u16* bh16 = (u16*)bh;
        u16* bl16 = (u16*)bl;
        int t2 = gid >> 1, half = gid & 1;
#pragma unroll
        for (int nt2 = 0; nt2 < 8; nt2++) {
            int nt = ng*8 + nt2;
#pragma unroll
            for (int j = 0; j < 4; j++) {
                int g2 = tig*2 + (j & 1);
                int lane2 = g2*4 + t2;
                int sel = j >> 1;
                int u32idx = ((mt1*16 + nt)*32 + lane2)*2 + sel;
                float v = fmaxf(acc[nt2][j], 0.f);
                u16 hi = f2bf(v);
                u16 lo = f2bf(v - bf2f(hi));
                bh16[u32idx*2 + half] = hi;
                bl16[u32idx*2 + half] = lo;
            }
        }
    }
    __syncthreads();

    float acc2[16][4];
    float acc3[2][4];
#pragma unroll
    for (int i = 0; i < 16; i++)
#pragma unroll
        for (int j = 0; j < 4; j++) acc2[i][j] = 0.f;
#pragma unroll
    for (int i = 0; i < 2; i++)
#pragma unroll
        for (int j = 0; j < 4; j++) acc3[i][j] = 0.f;

#pragma unroll
    for (int ks = 0; ks < 4; ks++) {
        uint4 ah  = ((const uint4*)g_W2fh)[(wid*4 + ks)*32 + lane];
        uint4 al  = ((const uint4*)g_W2fl)[(wid*4 + ks)*32 + lane];
        uint4 ah8 = ((const uint4*)g_W2fh)[(8*4 + ks)*32 + lane];
        uint4 al8 = ((const uint4*)g_W2fl)[(8*4 + ks)*32 + lane];
#pragma unroll
        for (int nt = 0; nt < 16; nt++) {
            int base = (ks*16 + nt)*32 + lane;
            mma3(acc2[nt], ah, al, bh64[base], bl64[base]);
        }
#pragma unroll
        for (int j = 0; j < 2; j++) {
            int nt = wid*2 + j;
            int base = (ks*16 + nt)*32 + lane;
            mma3(acc3[j], ah8, al8, bh64[base], bl64[base]);
        }
    }
    __syncthreads();

    {
        float* fsc = (float*)bh;
        int m0 = wid*16 + gid;
        float bias0 = __ldg(&e_b2[m0]), bias1 = __ldg(&e_b2[m0 + 8]);
        float* p0 = g_wpre + (size_t)(b*144 + m0)*HW + hw0 + tig*2;
        float* p1 = p0 + (size_t)8*HW;
        float s0 = 0.f, q0 = 0.f, s1 = 0.f, q1 = 0.f;
#pragma unroll
        for (int nt = 0; nt < 16; nt++) {
            float t0 = acc2[nt][0] + bias0, t1 = acc2[nt][1] + bias0;
            float t2 = acc2[nt][2] + bias1, t3 = acc2[nt][3] + bias1;
            *(float2*)(p0 + nt*8) = make_float2(t0, t1);
            *(float2*)(p1 + nt*8) = make_float2(t2, t3);
            s0 += t0 + t1; q0 += t0*t0 + t1*t1;
            s1 += t2 + t3; q1 += t2*t2 + t3*t3;
        }
        int m8 = 128 + gid;
        float bias2 = __ldg(&e_b2[m8]), bias3 = __ldg(&e_b2[m8 + 8]);
        float* q0p = g_wpre + (size_t)(b*144 + m8)*HW + hw0 + tig*2;
        float* q1p = q0p + (size_t)8*HW;
        float s2 = 0.f, q2 = 0.f, s3 = 0.f, q3 = 0.f;
#pragma unroll
        for (int j = 0; j < 2; j++) {
            int nt = wid*2 + j;
            float t0 = acc3[j][0] + bias2, t1 = acc3[j][1] + bias2;
            float t2 = acc3[j][2] + bias3, t3 = acc3[j][3] + bias3;
            *(float2*)(q0p + nt*8) = make_float2(t0, t1);
            *(float2*)(q1p + nt*8) = make_float2(t2, t3);
            s2 += t0 + t1; q2 += t0*t0 + t1*t1;
            s3 += t2 + t3; q3 += t2*t2 + t3*t3;
        }
#pragma unroll
        for (int off = 1; off < 4; off <<= 1) {
            s0 += __shfl_down_sync(0xffffffffu, s0, off, 4);
            q0 += __shfl_down_sync(0xffffffffu, q0, off, 4);
            s1 += __shfl_down_sync(0xffffffffu, s1, off, 4);
            q1 += __shfl_down_sync(0xffffffffu, q1, off, 4);
            s2 += __shfl_down_sync(0xffffffffu, s2, off, 4);
            q2 += __shfl_down_sync(0xffffffffu, q2, off, 4);
            s3 += __shfl_down_sync(0xffffffffu, s3, off, 4);
            q3 += __shfl_down_sync(0xffffffffu, q3, off, 4);
        }
        if (tig == 0) {
            int blk = blockIdx.x;
            g_gnS2[m0*576 + blk]       = s0;
            g_gnQ2[m0*576 + blk]       = q0;
            g_gnS2[(m0+8)*576 + blk]   = s1;
            g_gnQ2[(m0+8)*576 + blk]   = q1;
            float* f = fsc + (wid*8 + gid)*4;
            f[0] = s2; f[1] = q2; f[2] = s3; f[3] = q3;
        }
        __syncthreads();
        if (tid < 16) {
            int g2 = tid & 7, sel = tid >> 3;
            float ss = 0.f, qq = 0.f;
#pragma unroll
            for (int wp = 0; wp < 8; wp++) {
                const float* f = fsc + (wp*8 + g2)*4 + sel*2;
                ss += f[0]; qq += f[1];
            }
            int ch = 128 + sel*8 + g2;
            g_gnS2[ch*576 + blockIdx.x] = ss;
            g_gnQ2[ch*576 + blockIdx.x] = qq;
        }
    }
}

// ---------------- K4: GN finalize from k2 partials ----------------
__global__ void k4_gn2() {
    __shared__ float rs[256], rq[256];
    int bg = blockIdx.x, b = bg >> 4, g = bg & 15;
    int tid = threadIdx.x;
    float s = 0.f, q = 0.f;
    for (int idx = tid; idx < 9*72; idx += 256) {
        int t = idx / 72, i = idx % 72;
        int ch = g*9 + t;
        s += g_gnS2[ch*576 + b*72 + i];
        q += g_gnQ2[ch*576 + b*72 + i];
    }
    rs[tid] = s; rq[tid] = q;
    __syncthreads();
    for (int o = 128; o > 0; o >>= 1) {
        if (tid < o) { rs[tid] += rs[tid+o]; rq[tid] += rq[tid+o]; }
        __syncthreads();
    }
    if (tid == 0) {
        float inv = 1.f / (9.f*HW);
        float mean = rs[0] * inv;
        float var  = rq[0] * inv - mean*mean;
        g_gn[bg*2]     = mean;
        g_gn[bg*2 + 1] = rsqrtf(var + 1e-5f);
    }
}

// ---------------- K5: local dynamic conv + BN partials ----------------
#define K5_SMEM ((6912 + 7840 + 192) * 4)
__global__ void __launch_bounds__(384) k5_local(const float* __restrict__ gn_g,
                                                const float* __restrict__ gn_b) {
    extern __shared__ float sm5[];
    float* wn  = sm5;
    float* vs  = sm5 + 6912;
    float* red = sm5 + 6912 + 7840;
    int h0 = blockIdx.x * 8, g = blockIdx.y, b = blockIdx.z;
    int tid = threadIdx.x;
    float mean = g_gn[(b*16 + g)*2], rstd = g_gn[(b*16 + g)*2 + 1];

    for (int idx = tid; idx < 6912; idx += 384) {
        int t = idx / 768, rem = idx % 768;
        int ch = g*9 + t;
        float raw = g_wpre[(size_t)(b*144 + ch)*HW + h0*96 + rem];
        wn[idx] = (raw - mean) * rstd * __ldg(&gn_g[ch]) + __ldg(&gn_b[ch]);
    }
    for (int idx = tid; idx < 7840; idx += 384) {
        int s = idx / 980, rem = idx % 980, r = rem / 98, col = rem % 98;
        int hh = h0 + r - 1, wc = col - 1;
        float v = 0.f;
        if ((unsigned)hh < 96u && (unsigned)wc < 96u)
            v = g_v[(size_t)(b*128 + g*8 + s)*HW + hh*96 + wc];
        vs[idx] = v;
    }
    __syncthreads();

    int w = tid % 96, rq = tid / 96;
    int lane = tid & 31, warp = tid >> 5;
#pragma unroll
    for (int s = 0; s < 8; s++) {
        float p1 = 0.f, p2 = 0.f;
        const float* vb = vs + s*980;
#pragma unroll
        for (int rr = 0; rr < 2; rr++) {
            int row = rq*2 + rr;
            float acc = 0.f;
#pragma unroll
            for (int dr = 0; dr < 3; dr++)
#pragma unroll
                for (int dc = 0; dc < 3; dc++)
                    acc += vb[(row+dr)*98 + w + dc] * wn[(dr*3+dc)*768 + row*96 + w];
            g_ypre[(size_t)(b*128 + g*8 + s)*HW + (h0+row)*96 + w] = acc;
            p1 += acc; p2 += acc*acc;
        }
        for (int off = 16; off; off >>= 1) {
            p1 += __shfl_down_sync(0xffffffffu, p1, off);
            p2 += __shfl_down_sync(0xffffffffu, p2, off);
        }
        if (lane == 0) { red[warp*16 + s*2] = p1; red[warp*16 + s*2 + 1] = p2; }
    }
    __syncthreads();
    if (tid < 8) {
        float s1 = 0.f, s2 = 0.f;
#pragma unroll
        for (int wp = 0; wp < 12; wp++) {
            s1 += red[wp*16 + tid*2];
            s2 += red[wp*16 + tid*2 + 1];
        }
        int c = g*8 + tid;
        g_bnS[c*96 + b*12 + blockIdx.x] = s1;
        g_bnQ[c*96 + b*12 + blockIdx.x] = s2;
    }
}

// ---------------- K6: BN finalize ----------------
__global__ void k6_bn() {
    __shared__ float rs[96], rq[96];
    int c = blockIdx.x, tid = threadIdx.x;
    if (tid < 96) { rs[tid] = g_bnS[c*96 + tid]; rq[tid] = g_bnQ[c*96 + tid]; }
    __syncthreads();
    if (tid < 32) {
        float s = rs[tid] + rs[tid+32] + rs[tid+64];
        float q = rq[tid] + rq[tid+32] + rq[tid+64];
        for (int off = 16; off; off >>= 1) {
            s += __shfl_down_sync(0xffffffffu, s, off);
            q += __shfl_down_sync(0xffffffffu, q, off);
        }
        if (tid == 0) {
            float inv = 1.f / (float)PTOT;
            float mean = s * inv;
            float var  = q * inv - mean*mean;
            g_bn[c*2]     = mean;
            g_bn[c*2 + 1] = rsqrtf(var + 1e-5f);
        }
    }
}

// ---------------- K7: GAP partials ----------------
__global__ void k7_gap(const float* __restrict__ bn_g, const float* __restrict__ bn_b) {
    __shared__ float rs[256];
    int c = blockIdx.x, b = blockIdx.y;
    float mean = g_bn[c*2], rstd = g_bn[c*2 + 1];
    float gg = __ldg(&bn_g[c]), bb = __ldg(&bn_b[c]);
    const float4* yb = (const float4*)(g_ypre + (size_t)(b*128 + c)*HW);
    const float4* kb = (const float4*)(g_k    + (size_t)(b*128 + c)*HW);
    float s = 0.f;
    for (int idx = threadIdx.x; idx < HW/4; idx += 256) {
        float4 yp = yb[idx];
        float4 kv = kb[idx];
        float t0 = (yp.x - mean) * rstd * gg + bb;
        float t1 = (yp.y - mean) * rstd * gg + bb;
        float t2 = (yp.z - mean) * rstd * gg + bb;
        float t3 = (yp.w - mean) * rstd * gg + bb;
        s += t0 * __frcp_rn(1.f + __expf(-t0)) + kv.x;
        s += t1 * __frcp_rn(1.f + __expf(-t1)) + kv.y;
        s += t2 * __frcp_rn(1.f + __expf(-t2)) + kv.z;
        s += t3 * __frcp_rn(1.f + __expf(-t3)) + kv.w;
    }
    rs[threadIdx.x] = s;
    __syncthreads();
    for (int o = 128; o > 0; o >>= 1) {
        if (threadIdx.x < o) rs[threadIdx.x] += rs[threadIdx.x + o];
        __syncthreads();
    }
    if (threadIdx.x == 0) g_gap[b*128 + c] = rs[0] * (1.f / (float)HW);
}

// ---------------- K8: SE MLP + radix softmax ----------------
__global__ void k8_se(const float* __restrict__ w1, const float* __restrict__ b1,
                      const float* __restrict__ w2, const float* __restrict__ b2) {
    __shared__ float gaps[128], a1s[64], a2s[256];
    int b = blockIdx.x, tid = threadIdx.x;
    if (tid < 128) gaps[tid] = g_gap[b*128 + tid];
    __syncthreads();
    if (tid < 64) {
        float s = __ldg(&b1[tid]);
        for (int c = 0; c < 128; c++) s += __ldg(&w1[tid*128 + c]) * gaps[c];
        a1s[tid] = fmaxf(s, 0.f);
    }
    __syncthreads();
    {
        float s = __ldg(&b2[tid]);
        for (int j = 0; j < 64; j++) s += __ldg(&w2[tid*64 + j]) * a1s[j];
        a2s[tid] = s;
    }
    __syncthreads();
    if (tid < 128) {
        float e0 = a2s[tid*2], e1 = a2s[tid*2 + 1];
        float m = fmaxf(e0, e1);
        float p0 = expf(e0 - m), p1 = expf(e1 - m);
        float d = p0 + p1;
        g_a[(b*128 + tid)*2]     = p0 / d;
        g_a[(b*128 + tid)*2 + 1] = p1 / d;
    }
}

// ---------------- K9: final mix ----------------
__global__ void k9_out(float* __restrict__ out, const float* __restrict__ bn_g,
                       const float* __restrict__ bn_b) {
    int idx = blockIdx.x * 256 + threadIdx.x;
    int bc = idx / 2304;
    int c = bc & 127;
    float mean = g_bn[c*2], rstd = g_bn[c*2 + 1];
    float gg = __ldg(&bn_g[c]), bb = __ldg(&bn_b[c]);
    float a0 = g_a[bc*2], a1 = g_a[bc*2 + 1];
    const float4 yp = ((const float4*)g_ypre)[idx];
    const float4 kv = ((const float4*)g_k)[idx];
    float t0 = (yp.x - mean) * rstd * gg + bb;
    float t1 = (yp.y - mean) * rstd * gg + bb;
    float t2 = (yp.z - mean) * rstd * gg + bb;
    float t3 = (yp.w - mean) * rstd * gg + bb;
    float y0 = t0 * __frcp_rn(1.f + __expf(-t0));
    float y1 = t1 * __frcp_rn(1.f + __expf(-t1));
    float y2 = t2 * __frcp_rn(1.f + __expf(-t2));
    float y3 = t3 * __frcp_rn(1.f + __expf(-t3));
    ((float4*)out)[idx] = make_float4(y0*a0 + kv.x*a1, y1*a0 + kv.y*a1,
                                      y2*a0 + kv.z*a1, y3*a0 + kv.w*a1);
}

// ---------------- launch ----------------
extern "C" void kernel_launch(void* const* d_in, const int* in_sizes, int n_in,
                              void* d_out, int out_size) {
    const float* x     = (const float*)d_in[0];
    const float* key_w = (const float*)d_in[1];
    const float* e_w1  = (const float*)d_in[2];
    const float* e_w2  = (const float*)d_in[3];
    const float* e_b2  = (const float*)d_in[4];
    const float* gn_g  = (const float*)d_in[5];
    const float* gn_b  = (const float*)d_in[6];
    const float* c1_w  = (const float*)d_in[7];
    const float* bn_g  = (const float*)d_in[8];
    const float* bn_b  = (const float*)d_in[9];
    const float* se_w1 = (const float*)d_in[10];
    const float* se_b1 = (const float*)d_in[11];
    const float* se_w2 = (const float*)d_in[12];
    const float* se_b2 = (const float*)d_in[13];
    float* out = (float*)d_out;

    cudaFuncSetAttribute(k2_mma,   cudaFuncAttributeMaxDynamicSharedMemorySize, K2_SMEM);
    cudaFuncSetAttribute(k5_local, cudaFuncAttributeMaxDynamicSharedMemorySize, K5_SMEM);

    k0_prep <<<72, 256>>>(e_w1, c1_w, e_w2, key_w);
    k1_mma  <<<dim3(96, 4, 8), 384>>>(x);
    kdummy  <<<1, 32>>>();                        // keeps k2 at ncu capture slot 4
    k2_mma  <<<PTOT/128, 256, K2_SMEM>>>(x, e_b2);
    k4_gn2  <<<128, 256>>>();
    k5_local<<<dim3(12, 16, 8), 384, K5_SMEM>>>(gn_g, gn_b);
    k6_bn   <<<128, 128>>>();
    k7_gap  <<<dim3(128, 8), 256>>>(bn_g, bn_b);
    k8_se   <<<8, 256>>>(se_w1, se_b1, se_w2, se_b2);
    k9_out  <<<PTOT*128/(256*4), 256>>>(out, bn_g, bn_b);
}